// round 2
// baseline (speedup 1.0000x reference)
#include <cuda_runtime.h>
#include <math.h>

// ---------------------------------------------------------------------------
// Problem constants
// ---------------------------------------------------------------------------
#define NN   32768          // nodes
#define IN_C 256            // in channels
#define DD   128            // per-head dim
#define HH   4              // heads
#define HD   512            // H*D
#define MM   4              // seeds per partition
#define KPP  128            // partitions
#define SSZ  256            // partition size
#define RR   (KPP*MM)       // 512 reps
#define INV_SCALE 0.088388347648318447f   // 1/sqrt(128)

// ---------------------------------------------------------------------------
// Scratch (static device globals; no allocation allowed)
// ---------------------------------------------------------------------------
__device__ float g_Q[(size_t)NN*HD];
__device__ float g_K[(size_t)NN*HD];
__device__ float g_V[(size_t)NN*HD];
__device__ float g_outL[(size_t)NN*HD];
__device__ float g_outG[(size_t)NN*HD];
__device__ float g_repK[(size_t)RR*HD];
__device__ float g_repV[(size_t)RR*HD];

// ---------------------------------------------------------------------------
// Kernel 1: fused QKV GEMM  C = x @ W + b   (M=32768, K=256, N=512), z picks Q/K/V
// Classic 128x128x8 SGEMM with 8x8 register tiles.
// ---------------------------------------------------------------------------
#define BM 128
#define BN 128
#define BK 8
#define TM 8
#define TN 8

__global__ __launch_bounds__(256) void qkv_gemm(
    const float* __restrict__ x,
    const float* __restrict__ Wq, const float* __restrict__ bq,
    const float* __restrict__ Wk, const float* __restrict__ bk,
    const float* __restrict__ Wv, const float* __restrict__ bv)
{
    const float* W; const float* bias; float* C;
    if (blockIdx.z == 0)      { W = Wq; bias = bq; C = g_Q; }
    else if (blockIdx.z == 1) { W = Wk; bias = bk; C = g_K; }
    else                      { W = Wv; bias = bv; C = g_V; }

    __shared__ float As[BK][BM];
    __shared__ float Bs[BK][BN];

    const int tid  = threadIdx.x;
    const int row0 = blockIdx.y * BM;
    const int col0 = blockIdx.x * BN;
    const int tx = tid & 15;        // 16 col groups
    const int ty = tid >> 4;        // 16 row groups
    const int aRow = tid >> 1, aCol = (tid & 1) * 4;
    const int bRow = tid >> 5, bCol = (tid & 31) * 4;

    float acc[TM][TN];
#pragma unroll
    for (int i = 0; i < TM; i++)
#pragma unroll
        for (int j = 0; j < TN; j++) acc[i][j] = 0.f;

    for (int kk = 0; kk < IN_C; kk += BK) {
        float4 a = *(const float4*)&x[(size_t)(row0 + aRow) * IN_C + kk + aCol];
        As[aCol + 0][aRow] = a.x;
        As[aCol + 1][aRow] = a.y;
        As[aCol + 2][aRow] = a.z;
        As[aCol + 3][aRow] = a.w;
        *(float4*)&Bs[bRow][bCol] =
            *(const float4*)&W[(size_t)(kk + bRow) * HD + col0 + bCol];
        __syncthreads();
#pragma unroll
        for (int k = 0; k < BK; k++) {
            float ar[TM], br[TN];
            *(float4*)&ar[0] = *(float4*)&As[k][ty * TM];
            *(float4*)&ar[4] = *(float4*)&As[k][ty * TM + 4];
            *(float4*)&br[0] = *(float4*)&Bs[k][tx * TN];
            *(float4*)&br[4] = *(float4*)&Bs[k][tx * TN + 4];
#pragma unroll
            for (int i = 0; i < TM; i++)
#pragma unroll
                for (int j = 0; j < TN; j++)
                    acc[i][j] += ar[i] * br[j];
        }
        __syncthreads();
    }

#pragma unroll
    for (int i = 0; i < TM; i++) {
        const int r = row0 + ty * TM + i;
#pragma unroll
        for (int j0 = 0; j0 < TN; j0 += 4) {
            const int c = col0 + tx * TN + j0;
            float4 o;
            o.x = acc[i][j0 + 0] + bias[c + 0];
            o.y = acc[i][j0 + 1] + bias[c + 1];
            o.z = acc[i][j0 + 2] + bias[c + 2];
            o.w = acc[i][j0 + 3] + bias[c + 3];
            *(float4*)&C[(size_t)r * HD + c] = o;
        }
    }
}

// ---------------------------------------------------------------------------
// Kernel 2: fine attention within each partition (flash-style online softmax)
// block = (partition, head, 64-row q chunk); 8 warps x 8 rows; key tiles of 32
// ---------------------------------------------------------------------------
#define TSK 32
#define QPB 64
#define RPW 8

__device__ __forceinline__ float warp_sum(float s) {
    s += __shfl_xor_sync(0xffffffffu, s, 16);
    s += __shfl_xor_sync(0xffffffffu, s, 8);
    s += __shfl_xor_sync(0xffffffffu, s, 4);
    s += __shfl_xor_sync(0xffffffffu, s, 2);
    s += __shfl_xor_sync(0xffffffffu, s, 1);
    return s;
}

__global__ __launch_bounds__(256) void fine_attn(const int* __restrict__ pidx)
{
    const int kpart = blockIdx.x;
    const int h     = blockIdx.y;
    const int qc    = blockIdx.z;
    const int tid = threadIdx.x, warp = tid >> 5, lane = tid & 31;

    __shared__ float Ks[TSK][DD];
    __shared__ float Vs[TSK][DD];
    __shared__ float Sx[QPB][TSK];

    const int* pi = pidx + kpart * SSZ;
    const int qbase = qc * QPB + warp * RPW;

    float q[RPW][4], acc[RPW][4], mr[RPW], lr[RPW];
#pragma unroll
    for (int i = 0; i < RPW; i++) {
        const int node = pi[qbase + i];
        float4 qq = *(const float4*)&g_Q[(size_t)node * HD + h * DD + lane * 4];
        q[i][0] = qq.x * INV_SCALE; q[i][1] = qq.y * INV_SCALE;
        q[i][2] = qq.z * INV_SCALE; q[i][3] = qq.w * INV_SCALE;
        acc[i][0] = acc[i][1] = acc[i][2] = acc[i][3] = 0.f;
        mr[i] = -INFINITY; lr[i] = 0.f;
    }

    for (int t = 0; t < SSZ; t += TSK) {
        {   // cooperative gather of K,V tile: 256 threads x 16 floats each
            const int j = tid >> 3, d0 = (tid & 7) * 16;
            const int node = pi[t + j];
            const float* kp = &g_K[(size_t)node * HD + h * DD + d0];
            const float* vp = &g_V[(size_t)node * HD + h * DD + d0];
#pragma unroll
            for (int c = 0; c < 4; c++) {
                *(float4*)&Ks[j][d0 + 4 * c] = *(const float4*)(kp + 4 * c);
                *(float4*)&Vs[j][d0 + 4 * c] = *(const float4*)(vp + 4 * c);
            }
        }
        __syncthreads();

#pragma unroll
        for (int i = 0; i < RPW; i++) {
            float tmax = -INFINITY;
#pragma unroll
            for (int jj = 0; jj < TSK; jj++) {
                float4 kk = *(float4*)&Ks[jj][lane * 4];
                float s = q[i][0] * kk.x + q[i][1] * kk.y +
                          q[i][2] * kk.z + q[i][3] * kk.w;
                s = warp_sum(s);
                if (lane == 0) Sx[warp * RPW + i][jj] = s;
                tmax = fmaxf(tmax, s);
            }
            __syncwarp();
            const float mnew = fmaxf(mr[i], tmax);
            const float corr = __expf(mr[i] - mnew);
            mr[i] = mnew;
            lr[i] *= corr;
            acc[i][0] *= corr; acc[i][1] *= corr;
            acc[i][2] *= corr; acc[i][3] *= corr;
            float ls = 0.f;
#pragma unroll
            for (int jj = 0; jj < TSK; jj++) {
                const float p = __expf(Sx[warp * RPW + i][jj] - mnew);
                float4 vv = *(float4*)&Vs[jj][lane * 4];
                acc[i][0] += p * vv.x; acc[i][1] += p * vv.y;
                acc[i][2] += p * vv.z; acc[i][3] += p * vv.w;
                ls += p;
            }
            lr[i] += ls;
        }
        __syncthreads();
    }

#pragma unroll
    for (int i = 0; i < RPW; i++) {
        const int node = pi[qbase + i];
        const float inv = 1.f / lr[i];
        float4 o;
        o.x = acc[i][0] * inv; o.y = acc[i][1] * inv;
        o.z = acc[i][2] * inv; o.w = acc[i][3] * inv;
        *(float4*)&g_outL[(size_t)node * HD + h * DD + lane * 4] = o;
    }
}

// ---------------------------------------------------------------------------
// Kernel 3: coarse pooling — seeds attend over each partition's K; produce
// reps_k / reps_v. block = (partition, head), warp per seed (M=4 -> 128 thr).
// ---------------------------------------------------------------------------
__global__ __launch_bounds__(128) void coarse_pool(const int* __restrict__ pidx,
                                                   const float* __restrict__ seeds)
{
    const int kpart = blockIdx.x;
    const int h     = blockIdx.y;
    const int tid = threadIdx.x, m = tid >> 5, lane = tid & 31;

    __shared__ float Ks[TSK][DD];
    __shared__ float Vs[TSK][DD];
    __shared__ float Sx[MM][SSZ];

    const int* pi = pidx + kpart * SSZ;

    float4 sq = *(const float4*)&seeds[(size_t)m * HD + h * DD + lane * 4];
    const float q0 = sq.x * INV_SCALE, q1 = sq.y * INV_SCALE;
    const float q2 = sq.z * INV_SCALE, q3 = sq.w * INV_SCALE;

    float tmax = -INFINITY;
    // pass 1: scores
    for (int t = 0; t < SSZ; t += TSK) {
        {   // 128 threads x 32 floats each (K only)
            const int j = tid >> 2, d0 = (tid & 3) * 32;
            const int node = pi[t + j];
            const float* kp = &g_K[(size_t)node * HD + h * DD + d0];
#pragma unroll
            for (int c = 0; c < 8; c++)
                *(float4*)&Ks[j][d0 + 4 * c] = *(const float4*)(kp + 4 * c);
        }
        __syncthreads();
#pragma unroll
        for (int jj = 0; jj < TSK; jj++) {
            float4 kk = *(float4*)&Ks[jj][lane * 4];
            float s = q0 * kk.x + q1 * kk.y + q2 * kk.z + q3 * kk.w;
            s = warp_sum(s);
            if (lane == 0) Sx[m][t + jj] = s;
            tmax = fmaxf(tmax, s);
        }
        __syncthreads();
    }
    __syncwarp();

    // softmax weights
    float lsum = 0.f;
    for (int jj = lane; jj < SSZ; jj += 32) {
        const float p = __expf(Sx[m][jj] - tmax);
        Sx[m][jj] = p;
        lsum += p;
    }
    lsum = warp_sum(lsum);
    __syncwarp();

    // pass 2: weighted sums of K and V
    float rk[4] = {0.f, 0.f, 0.f, 0.f};
    float rv[4] = {0.f, 0.f, 0.f, 0.f};
    for (int t = 0; t < SSZ; t += TSK) {
        {
            const int j = tid >> 2, d0 = (tid & 3) * 32;
            const int node = pi[t + j];
            const float* kp = &g_K[(size_t)node * HD + h * DD + d0];
            const float* vp = &g_V[(size_t)node * HD + h * DD + d0];
#pragma unroll
            for (int c = 0; c < 8; c++) {
                *(float4*)&Ks[j][d0 + 4 * c] = *(const float4*)(kp + 4 * c);
                *(float4*)&Vs[j][d0 + 4 * c] = *(const float4*)(vp + 4 * c);
            }
        }
        __syncthreads();
#pragma unroll
        for (int jj = 0; jj < TSK; jj++) {
            const float p = Sx[m][t + jj];
            float4 kk = *(float4*)&Ks[jj][lane * 4];
            float4 vv = *(float4*)&Vs[jj][lane * 4];
            rk[0] += p * kk.x; rk[1] += p * kk.y; rk[2] += p * kk.z; rk[3] += p * kk.w;
            rv[0] += p * vv.x; rv[1] += p * vv.y; rv[2] += p * vv.z; rv[3] += p * vv.w;
        }
        __syncthreads();
    }

    const float inv = 1.f / lsum;
    const int r = kpart * MM + m;
    float4 ok, ov;
    ok.x = rk[0] * inv; ok.y = rk[1] * inv; ok.z = rk[2] * inv; ok.w = rk[3] * inv;
    ov.x = rv[0] * inv; ov.y = rv[1] * inv; ov.z = rv[2] * inv; ov.w = rv[3] * inv;
    *(float4*)&g_repK[(size_t)r * HD + h * DD + lane * 4] = ok;
    *(float4*)&g_repV[(size_t)r * HD + h * DD + lane * 4] = ov;
}

// ---------------------------------------------------------------------------
// Kernel 4: global cross-attention — every node attends to all 512 reps.
// Same flash structure as fine_attn; reps fit in L2 so reloads are cheap.
// ---------------------------------------------------------------------------
__global__ __launch_bounds__(256) void global_attn()
{
    const int nc = blockIdx.x;     // 512 node chunks of 64
    const int h  = blockIdx.y;
    const int tid = threadIdx.x, warp = tid >> 5, lane = tid & 31;

    __shared__ float Ks[TSK][DD];
    __shared__ float Vs[TSK][DD];
    __shared__ float Sx[QPB][TSK];

    const int nbase = nc * QPB + warp * RPW;

    float q[RPW][4], acc[RPW][4], mr[RPW], lr[RPW];
#pragma unroll
    for (int i = 0; i < RPW; i++) {
        float4 qq = *(const float4*)&g_Q[(size_t)(nbase + i) * HD + h * DD + lane * 4];
        q[i][0] = qq.x * INV_SCALE; q[i][1] = qq.y * INV_SCALE;
        q[i][2] = qq.z * INV_SCALE; q[i][3] = qq.w * INV_SCALE;
        acc[i][0] = acc[i][1] = acc[i][2] = acc[i][3] = 0.f;
        mr[i] = -INFINITY; lr[i] = 0.f;
    }

    for (int t = 0; t < RR; t += TSK) {
        {
            const int j = tid >> 3, d0 = (tid & 7) * 16;
            const float* kp = &g_repK[(size_t)(t + j) * HD + h * DD + d0];
            const float* vp = &g_repV[(size_t)(t + j) * HD + h * DD + d0];
#pragma unroll
            for (int c = 0; c < 4; c++) {
                *(float4*)&Ks[j][d0 + 4 * c] = *(const float4*)(kp + 4 * c);
                *(float4*)&Vs[j][d0 + 4 * c] = *(const float4*)(vp + 4 * c);
            }
        }
        __syncthreads();

#pragma unroll
        for (int i = 0; i < RPW; i++) {
            float tmax = -INFINITY;
#pragma unroll
            for (int jj = 0; jj < TSK; jj++) {
                float4 kk = *(float4*)&Ks[jj][lane * 4];
                float s = q[i][0] * kk.x + q[i][1] * kk.y +
                          q[i][2] * kk.z + q[i][3] * kk.w;
                s = warp_sum(s);
                if (lane == 0) Sx[warp * RPW + i][jj] = s;
                tmax = fmaxf(tmax, s);
            }
            __syncwarp();
            const float mnew = fmaxf(mr[i], tmax);
            const float corr = __expf(mr[i] - mnew);
            mr[i] = mnew;
            lr[i] *= corr;
            acc[i][0] *= corr; acc[i][1] *= corr;
            acc[i][2] *= corr; acc[i][3] *= corr;
            float ls = 0.f;
#pragma unroll
            for (int jj = 0; jj < TSK; jj++) {
                const float p = __expf(Sx[warp * RPW + i][jj] - mnew);
                float4 vv = *(float4*)&Vs[jj][lane * 4];
                acc[i][0] += p * vv.x; acc[i][1] += p * vv.y;
                acc[i][2] += p * vv.z; acc[i][3] += p * vv.w;
                ls += p;
            }
            lr[i] += ls;
        }
        __syncthreads();
    }

#pragma unroll
    for (int i = 0; i < RPW; i++) {
        const float inv = 1.f / lr[i];
        float4 o;
        o.x = acc[i][0] * inv; o.y = acc[i][1] * inv;
        o.z = acc[i][2] * inv; o.w = acc[i][3] * inv;
        *(float4*)&g_outG[(size_t)(nbase + i) * HD + h * DD + lane * 4] = o;
    }
}

// ---------------------------------------------------------------------------
// Kernel 5: combine — out = alpha*mean_h(outL) + (1-alpha)*mean_h(outG)
//                         + beta*mean_h(V)
// ---------------------------------------------------------------------------
__global__ __launch_bounds__(256) void combine(const float* __restrict__ alpha_logit,
                                               const float* __restrict__ beta_p,
                                               float* __restrict__ out)
{
    const int idx = blockIdx.x * blockDim.x + threadIdx.x;   // over N*D/4
    const int n  = idx / (DD / 4);
    const int d4 = (idx % (DD / 4)) * 4;

    const float alpha = 1.f / (1.f + __expf(-alpha_logit[0]));
    const float beta  = beta_p[0];
    const float ca = alpha * 0.25f;
    const float cg = (1.f - alpha) * 0.25f;
    const float cb = beta * 0.25f;

    float sl0 = 0, sl1 = 0, sl2 = 0, sl3 = 0;
    float sg0 = 0, sg1 = 0, sg2 = 0, sg3 = 0;
    float sv0 = 0, sv1 = 0, sv2 = 0, sv3 = 0;
#pragma unroll
    for (int h = 0; h < HH; h++) {
        const size_t base = (size_t)n * HD + h * DD + d4;
        float4 a = *(const float4*)&g_outL[base];
        float4 b = *(const float4*)&g_outG[base];
        float4 c = *(const float4*)&g_V[base];
        sl0 += a.x; sl1 += a.y; sl2 += a.z; sl3 += a.w;
        sg0 += b.x; sg1 += b.y; sg2 += b.z; sg3 += b.w;
        sv0 += c.x; sv1 += c.y; sv2 += c.z; sv3 += c.w;
    }
    float4 o;
    o.x = ca * sl0 + cg * sg0 + cb * sv0;
    o.y = ca * sl1 + cg * sg1 + cb * sv1;
    o.z = ca * sl2 + cg * sg2 + cb * sv2;
    o.w = ca * sl3 + cg * sg3 + cb * sv3;
    *(float4*)&out[(size_t)n * DD + d4] = o;
}

// ---------------------------------------------------------------------------
// Launcher
// ---------------------------------------------------------------------------
extern "C" void kernel_launch(void* const* d_in, const int* in_sizes, int n_in,
                              void* d_out, int out_size)
{
    (void)in_sizes; (void)n_in; (void)out_size;
    const float* x     = (const float*)d_in[0];
    const int*   pidx  = (const int*)  d_in[1];
    const float* Wq    = (const float*)d_in[2];
    const float* bq    = (const float*)d_in[3];
    const float* Wk    = (const float*)d_in[4];
    const float* bk    = (const float*)d_in[5];
    const float* Wv    = (const float*)d_in[6];
    const float* bv    = (const float*)d_in[7];
    const float* seeds = (const float*)d_in[8];
    const float* alog  = (const float*)d_in[9];
    const float* beta  = (const float*)d_in[10];
    float* out = (float*)d_out;

    dim3 g1(HD / BN, NN / BM, 3);              // 4 x 256 x 3
    qkv_gemm<<<g1, 256>>>(x, Wq, bq, Wk, bk, Wv, bv);

    dim3 g2(KPP, HH, SSZ / QPB);               // 128 x 4 x 4
    fine_attn<<<g2, 256>>>(pidx);

    dim3 g3(KPP, HH);                          // 128 x 4
    coarse_pool<<<g3, 128>>>(pidx, seeds);

    dim3 g4(NN / QPB, HH);                     // 512 x 4
    global_attn<<<g4, 256>>>();

    combine<<<(NN * DD / 4) / 256, 256>>>(alog, beta, out);
}

// round 3
// speedup vs baseline: 1.5679x; 1.5679x over previous
#include <cuda_runtime.h>
#include <math.h>

// ---------------------------------------------------------------------------
// Problem constants
// ---------------------------------------------------------------------------
#define NN   32768          // nodes
#define IN_C 256            // in channels
#define DD   128            // per-head dim
#define HH   4              // heads
#define HD   512            // H*D
#define MM   4              // seeds per partition
#define KPP  128            // partitions
#define SSZ  256            // partition size
#define RR   (KPP*MM)       // 512 reps
#define INV_SCALE 0.088388347648318447f   // 1/sqrt(128)

// ---------------------------------------------------------------------------
// Scratch (static device globals; no allocation allowed)
// ---------------------------------------------------------------------------
__device__ float g_Q[(size_t)NN*HD];
__device__ float g_K[(size_t)NN*HD];
__device__ float g_V[(size_t)NN*HD];
__device__ float g_outL[(size_t)NN*HD];
__device__ float g_outG[(size_t)NN*HD];
__device__ float g_repK[(size_t)RR*HD];
__device__ float g_repV[(size_t)RR*HD];

// ---------------------------------------------------------------------------
// Kernel 1: fused QKV GEMM  C = x @ W + b   (M=32768, K=256, N=512)
// ---------------------------------------------------------------------------
#define BM 128
#define BN 128
#define BK 8
#define TM 8
#define TN 8

__global__ __launch_bounds__(256) void qkv_gemm(
    const float* __restrict__ x,
    const float* __restrict__ Wq, const float* __restrict__ bq,
    const float* __restrict__ Wk, const float* __restrict__ bk,
    const float* __restrict__ Wv, const float* __restrict__ bv)
{
    const float* W; const float* bias; float* C;
    if (blockIdx.z == 0)      { W = Wq; bias = bq; C = g_Q; }
    else if (blockIdx.z == 1) { W = Wk; bias = bk; C = g_K; }
    else                      { W = Wv; bias = bv; C = g_V; }

    __shared__ float As[BK][BM];
    __shared__ float Bs[BK][BN];

    const int tid  = threadIdx.x;
    const int row0 = blockIdx.y * BM;
    const int col0 = blockIdx.x * BN;
    const int tx = tid & 15;
    const int ty = tid >> 4;
    const int aRow = tid >> 1, aCol = (tid & 1) * 4;
    const int bRow = tid >> 5, bCol = (tid & 31) * 4;

    float acc[TM][TN];
#pragma unroll
    for (int i = 0; i < TM; i++)
#pragma unroll
        for (int j = 0; j < TN; j++) acc[i][j] = 0.f;

    for (int kk = 0; kk < IN_C; kk += BK) {
        float4 a = *(const float4*)&x[(size_t)(row0 + aRow) * IN_C + kk + aCol];
        As[aCol + 0][aRow] = a.x;
        As[aCol + 1][aRow] = a.y;
        As[aCol + 2][aRow] = a.z;
        As[aCol + 3][aRow] = a.w;
        *(float4*)&Bs[bRow][bCol] =
            *(const float4*)&W[(size_t)(kk + bRow) * HD + col0 + bCol];
        __syncthreads();
#pragma unroll
        for (int k = 0; k < BK; k++) {
            float ar[TM], br[TN];
            *(float4*)&ar[0] = *(float4*)&As[k][ty * TM];
            *(float4*)&ar[4] = *(float4*)&As[k][ty * TM + 4];
            *(float4*)&br[0] = *(float4*)&Bs[k][tx * TN];
            *(float4*)&br[4] = *(float4*)&Bs[k][tx * TN + 4];
#pragma unroll
            for (int i = 0; i < TM; i++)
#pragma unroll
                for (int j = 0; j < TN; j++)
                    acc[i][j] += ar[i] * br[j];
        }
        __syncthreads();
    }

#pragma unroll
    for (int i = 0; i < TM; i++) {
        const int r = row0 + ty * TM + i;
#pragma unroll
        for (int j0 = 0; j0 < TN; j0 += 4) {
            const int c = col0 + tx * TN + j0;
            float4 o;
            o.x = acc[i][j0 + 0] + bias[c + 0];
            o.y = acc[i][j0 + 1] + bias[c + 1];
            o.z = acc[i][j0 + 2] + bias[c + 2];
            o.w = acc[i][j0 + 3] + bias[c + 3];
            *(float4*)&C[(size_t)r * HD + c] = o;
        }
    }
}

// ---------------------------------------------------------------------------
// Unified flash attention worker — NO per-score shuffles.
// Block: 256 threads (8 warps), 64 q rows x 1 head, keys tiled by 32.
// Score phase: lane owns one key (swizzled K in smem, Q broadcast from smem).
// PV phase:    lane owns a 4-float d-slice (P staged in smem, broadcast).
// Dynamic smem: Qs 64x128 | Ks 32x128 (xor-swizzled f4) | Vs 32x128 | Ps 8x8x32
// ---------------------------------------------------------------------------
#define ATTN_SMEM_BYTES ((8192 + 4096 + 4096 + 2048) * 4)

__device__ __forceinline__ float warp_sum(float s) {
    s += __shfl_xor_sync(0xffffffffu, s, 16);
    s += __shfl_xor_sync(0xffffffffu, s, 8);
    s += __shfl_xor_sync(0xffffffffu, s, 4);
    s += __shfl_xor_sync(0xffffffffu, s, 2);
    s += __shfl_xor_sync(0xffffffffu, s, 1);
    return s;
}
__device__ __forceinline__ float warp_max(float s) {
    s = fmaxf(s, __shfl_xor_sync(0xffffffffu, s, 16));
    s = fmaxf(s, __shfl_xor_sync(0xffffffffu, s, 8));
    s = fmaxf(s, __shfl_xor_sync(0xffffffffu, s, 4));
    s = fmaxf(s, __shfl_xor_sync(0xffffffffu, s, 2));
    s = fmaxf(s, __shfl_xor_sync(0xffffffffu, s, 1));
    return s;
}

template<int LKEYS, bool GATHER>
__global__ __launch_bounds__(256) void attn_kern(const int* __restrict__ pidx)
{
    extern __shared__ float sm[];
    float*  Qs  = sm;                           // [64][128]
    float4* Ks4 = (float4*)(sm + 8192);         // [32][32] f4, xor-swizzled
    float4* Vs4 = (float4*)(sm + 8192 + 4096);  // [32][32] f4, plain
    float*  Ps  = sm + 8192 + 8192;             // [8 warps][8 rows][32 keys]

    const int tid = threadIdx.x, warp = tid >> 5, lane = tid & 31;
    const int h = blockIdx.y;

    const float* Kg = GATHER ? g_K    : g_repK;
    const float* Vg = GATHER ? g_V    : g_repV;
    float*       Og = GATHER ? g_outL : g_outG;
    const int*   pi = GATHER ? (pidx + blockIdx.x * SSZ) : (const int*)0;
    const int    q0 = GATHER ? (int)blockIdx.z * 64 : (int)blockIdx.x * 64;

    // ---- stage Q tile (pre-scaled by 1/sqrt(D)) ----
    {
        const int r  = tid >> 2;
        const int c0 = (tid & 3) * 32;
        const int node = GATHER ? pi[q0 + r] : (q0 + r);
        const float* src = g_Q + (size_t)node * HD + h * DD + c0;
        float* dst = Qs + r * DD + c0;
#pragma unroll
        for (int c = 0; c < 8; c++) {
            float4 v = *(const float4*)(src + 4 * c);
            v.x *= INV_SCALE; v.y *= INV_SCALE; v.z *= INV_SCALE; v.w *= INV_SCALE;
            *(float4*)(dst + 4 * c) = v;
        }
    }

    float4 acc[8];
    float  m[8], l[8];
#pragma unroll
    for (int i = 0; i < 8; i++) {
        acc[i] = make_float4(0.f, 0.f, 0.f, 0.f);
        m[i] = -INFINITY; l[i] = 0.f;
    }

    float*       PsW = Ps + warp * 256;
    const float* QsW = Qs + (warp * 8) * DD;
    const int    lsw = lane & 7;

    for (int t = 0; t < LKEYS; t += 32) {
        __syncthreads();   // protects previous tile reads (and Q staging first iter)
        {   // ---- stage K (swizzled) + V tile ----
            const int r  = tid >> 3;
            const int c0 = (tid & 7) * 4;   // f4 column
            const int knode = GATHER ? pi[t + r] : (t + r);
            const float4* ksrc = (const float4*)(Kg + (size_t)knode * HD + h * DD) + c0;
            const float4* vsrc = (const float4*)(Vg + (size_t)knode * HD + h * DD) + c0;
#pragma unroll
            for (int c = 0; c < 4; c++) {
                Ks4[r * 32 + ((c0 + c) ^ (r & 7))] = ksrc[c];
                Vs4[r * 32 + c0 + c]               = vsrc[c];
            }
        }
        __syncthreads();

        // ---- scores: lane owns key 'lane'; 8 q rows; pure FMA ----
        float s[8];
#pragma unroll
        for (int i = 0; i < 8; i++) s[i] = 0.f;
#pragma unroll
        for (int d4 = 0; d4 < 32; d4++) {
            float4 k = Ks4[lane * 32 + (d4 ^ lsw)];
#pragma unroll
            for (int i = 0; i < 8; i++) {
                float4 q = *(const float4*)(QsW + i * DD + d4 * 4);
                s[i] += q.x * k.x + q.y * k.y + q.z * k.z + q.w * k.w;
            }
        }

        // ---- online softmax per row (only place with shuffles) ----
#pragma unroll
        for (int i = 0; i < 8; i++) {
            const float tm   = warp_max(s[i]);
            const float mnew = fmaxf(m[i], tm);
            const float corr = __expf(m[i] - mnew);
            m[i] = mnew;
            const float p = __expf(s[i] - mnew);
            PsW[i * 32 + lane] = p;
            const float rs = warp_sum(p);
            l[i] = l[i] * corr + rs;
            acc[i].x *= corr; acc[i].y *= corr; acc[i].z *= corr; acc[i].w *= corr;
        }
        __syncwarp();

        // ---- PV: lane owns d-slice lane*4; P broadcast from smem ----
#pragma unroll
        for (int jq = 0; jq < 8; jq++) {
            const float4 v0 = Vs4[(jq * 4 + 0) * 32 + lane];
            const float4 v1 = Vs4[(jq * 4 + 1) * 32 + lane];
            const float4 v2 = Vs4[(jq * 4 + 2) * 32 + lane];
            const float4 v3 = Vs4[(jq * 4 + 3) * 32 + lane];
#pragma unroll
            for (int i = 0; i < 8; i++) {
                const float4 p = *(const float4*)(PsW + i * 32 + jq * 4);
                acc[i].x += p.x * v0.x + p.y * v1.x + p.z * v2.x + p.w * v3.x;
                acc[i].y += p.x * v0.y + p.y * v1.y + p.z * v2.y + p.w * v3.y;
                acc[i].z += p.x * v0.z + p.y * v1.z + p.z * v2.z + p.w * v3.z;
                acc[i].w += p.x * v0.w + p.y * v1.w + p.z * v2.w + p.w * v3.w;
            }
        }
        __syncwarp();
    }

    // ---- normalize + write out ----
#pragma unroll
    for (int i = 0; i < 8; i++) {
        const int r = warp * 8 + i;
        const int node = GATHER ? pi[q0 + r] : (q0 + r);
        const float inv = 1.f / l[i];
        float4 o;
        o.x = acc[i].x * inv; o.y = acc[i].y * inv;
        o.z = acc[i].z * inv; o.w = acc[i].w * inv;
        *(float4*)(Og + (size_t)node * HD + h * DD + lane * 4) = o;
    }
}

// ---------------------------------------------------------------------------
// Kernel 3: coarse pooling — seeds attend over each partition's K.
// ---------------------------------------------------------------------------
#define TSK 32

__global__ __launch_bounds__(128) void coarse_pool(const int* __restrict__ pidx,
                                                   const float* __restrict__ seeds)
{
    const int kpart = blockIdx.x;
    const int h     = blockIdx.y;
    const int tid = threadIdx.x, m = tid >> 5, lane = tid & 31;

    __shared__ float Ks[TSK][DD];
    __shared__ float Vs[TSK][DD];
    __shared__ float Sx[MM][SSZ];

    const int* pi = pidx + kpart * SSZ;

    float4 sq = *(const float4*)&seeds[(size_t)m * HD + h * DD + lane * 4];
    const float q0 = sq.x * INV_SCALE, q1 = sq.y * INV_SCALE;
    const float q2 = sq.z * INV_SCALE, q3 = sq.w * INV_SCALE;

    float tmax = -INFINITY;
    for (int t = 0; t < SSZ; t += TSK) {
        {
            const int j = tid >> 2, d0 = (tid & 3) * 32;
            const int node = pi[t + j];
            const float* kp = &g_K[(size_t)node * HD + h * DD + d0];
#pragma unroll
            for (int c = 0; c < 8; c++)
                *(float4*)&Ks[j][d0 + 4 * c] = *(const float4*)(kp + 4 * c);
        }
        __syncthreads();
#pragma unroll
        for (int jj = 0; jj < TSK; jj++) {
            float4 kk = *(float4*)&Ks[jj][lane * 4];
            float s = q0 * kk.x + q1 * kk.y + q2 * kk.z + q3 * kk.w;
            s = warp_sum(s);
            if (lane == 0) Sx[m][t + jj] = s;
            tmax = fmaxf(tmax, s);
        }
        __syncthreads();
    }
    __syncwarp();

    float lsum = 0.f;
    for (int jj = lane; jj < SSZ; jj += 32) {
        const float p = __expf(Sx[m][jj] - tmax);
        Sx[m][jj] = p;
        lsum += p;
    }
    lsum = warp_sum(lsum);
    __syncwarp();

    float rk[4] = {0.f, 0.f, 0.f, 0.f};
    float rv[4] = {0.f, 0.f, 0.f, 0.f};
    for (int t = 0; t < SSZ; t += TSK) {
        {
            const int j = tid >> 2, d0 = (tid & 3) * 32;
            const int node = pi[t + j];
            const float* kp = &g_K[(size_t)node * HD + h * DD + d0];
            const float* vp = &g_V[(size_t)node * HD + h * DD + d0];
#pragma unroll
            for (int c = 0; c < 8; c++) {
                *(float4*)&Ks[j][d0 + 4 * c] = *(const float4*)(kp + 4 * c);
                *(float4*)&Vs[j][d0 + 4 * c] = *(const float4*)(vp + 4 * c);
            }
        }
        __syncthreads();
#pragma unroll
        for (int jj = 0; jj < TSK; jj++) {
            const float p = Sx[m][t + jj];
            float4 kk = *(float4*)&Ks[jj][lane * 4];
            float4 vv = *(float4*)&Vs[jj][lane * 4];
            rk[0] += p * kk.x; rk[1] += p * kk.y; rk[2] += p * kk.z; rk[3] += p * kk.w;
            rv[0] += p * vv.x; rv[1] += p * vv.y; rv[2] += p * vv.z; rv[3] += p * vv.w;
        }
        __syncthreads();
    }

    const float inv = 1.f / lsum;
    const int r = kpart * MM + m;
    float4 ok, ov;
    ok.x = rk[0] * inv; ok.y = rk[1] * inv; ok.z = rk[2] * inv; ok.w = rk[3] * inv;
    ov.x = rv[0] * inv; ov.y = rv[1] * inv; ov.z = rv[2] * inv; ov.w = rv[3] * inv;
    *(float4*)&g_repK[(size_t)r * HD + h * DD + lane * 4] = ok;
    *(float4*)&g_repV[(size_t)r * HD + h * DD + lane * 4] = ov;
}

// ---------------------------------------------------------------------------
// Kernel 5: combine — out = a*mean_h(outL) + (1-a)*mean_h(outG) + b*mean_h(V)
// ---------------------------------------------------------------------------
__global__ __launch_bounds__(256) void combine(const float* __restrict__ alpha_logit,
                                               const float* __restrict__ beta_p,
                                               float* __restrict__ out)
{
    const int idx = blockIdx.x * blockDim.x + threadIdx.x;
    const int n  = idx / (DD / 4);
    const int d4 = (idx % (DD / 4)) * 4;

    const float alpha = 1.f / (1.f + __expf(-alpha_logit[0]));
    const float beta  = beta_p[0];
    const float ca = alpha * 0.25f;
    const float cg = (1.f - alpha) * 0.25f;
    const float cb = beta * 0.25f;

    float sl0 = 0, sl1 = 0, sl2 = 0, sl3 = 0;
    float sg0 = 0, sg1 = 0, sg2 = 0, sg3 = 0;
    float sv0 = 0, sv1 = 0, sv2 = 0, sv3 = 0;
#pragma unroll
    for (int h = 0; h < HH; h++) {
        const size_t base = (size_t)n * HD + h * DD + d4;
        float4 a = *(const float4*)&g_outL[base];
        float4 b = *(const float4*)&g_outG[base];
        float4 c = *(const float4*)&g_V[base];
        sl0 += a.x; sl1 += a.y; sl2 += a.z; sl3 += a.w;
        sg0 += b.x; sg1 += b.y; sg2 += b.z; sg3 += b.w;
        sv0 += c.x; sv1 += c.y; sv2 += c.z; sv3 += c.w;
    }
    float4 o;
    o.x = ca * sl0 + cg * sg0 + cb * sv0;
    o.y = ca * sl1 + cg * sg1 + cb * sv1;
    o.z = ca * sl2 + cg * sg2 + cb * sv2;
    o.w = ca * sl3 + cg * sg3 + cb * sv3;
    *(float4*)&out[(size_t)n * DD + d4] = o;
}

// ---------------------------------------------------------------------------
// Launcher
// ---------------------------------------------------------------------------
extern "C" void kernel_launch(void* const* d_in, const int* in_sizes, int n_in,
                              void* d_out, int out_size)
{
    (void)in_sizes; (void)n_in; (void)out_size;
    const float* x     = (const float*)d_in[0];
    const int*   pidx  = (const int*)  d_in[1];
    const float* Wq    = (const float*)d_in[2];
    const float* bq    = (const float*)d_in[3];
    const float* Wk    = (const float*)d_in[4];
    const float* bk    = (const float*)d_in[5];
    const float* Wv    = (const float*)d_in[6];
    const float* bv    = (const float*)d_in[7];
    const float* seeds = (const float*)d_in[8];
    const float* alog  = (const float*)d_in[9];
    const float* beta  = (const float*)d_in[10];
    float* out = (float*)d_out;

    // raise dynamic smem limit (idempotent host-state calls; capture-legal)
    cudaFuncSetAttribute((const void*)attn_kern<SSZ, true>,
                         cudaFuncAttributeMaxDynamicSharedMemorySize, ATTN_SMEM_BYTES);
    cudaFuncSetAttribute((const void*)attn_kern<RR, false>,
                         cudaFuncAttributeMaxDynamicSharedMemorySize, ATTN_SMEM_BYTES);

    dim3 g1(HD / BN, NN / BM, 3);
    qkv_gemm<<<g1, 256>>>(x, Wq, bq, Wk, bk, Wv, bv);

    dim3 g2(KPP, HH, SSZ / 64);                 // fine attention: 128 x 4 x 4
    attn_kern<SSZ, true><<<g2, 256, ATTN_SMEM_BYTES>>>(pidx);

    dim3 g3(KPP, HH);                           // coarse pooling
    coarse_pool<<<g3, 128>>>(pidx, seeds);

    dim3 g4(NN / 64, HH);                       // global cross-attention: 512 x 4
    attn_kern<RR, false><<<g4, 256, ATTN_SMEM_BYTES>>>(nullptr);

    combine<<<(NN * DD / 4) / 256, 256>>>(alog, beta, out);
}

// round 4
// speedup vs baseline: 2.5274x; 1.6119x over previous
#include <cuda_runtime.h>
#include <math.h>

// ---------------------------------------------------------------------------
// Problem constants
// ---------------------------------------------------------------------------
#define NN   32768          // nodes
#define IN_C 256            // in channels
#define DD   128            // per-head dim
#define HH   4              // heads
#define HD   512            // H*D
#define MM   4              // seeds per partition
#define KPP  128            // partitions
#define SSZ  256            // partition size
#define RR   (KPP*MM)       // 512 reps
#define INV_SCALE 0.088388347648318447f   // 1/sqrt(128)

// ---------------------------------------------------------------------------
// Scratch (static device globals; no allocation allowed)
// ---------------------------------------------------------------------------
__device__ float g_Q[(size_t)NN*HD];
__device__ float g_K[(size_t)NN*HD];
__device__ float g_V[(size_t)NN*HD];
__device__ float g_outL[(size_t)NN*HD];
__device__ float g_outG[(size_t)NN*HD];
__device__ float g_repK[(size_t)RR*HD];
__device__ float g_repV[(size_t)RR*HD];

// ---------------------------------------------------------------------------
// Kernel 1: fused QKV GEMM  C = x @ W + b   (M=32768, K=256, N=512)
// ---------------------------------------------------------------------------
#define BM 128
#define BN 128
#define BK 8
#define TM 8
#define TN 8

__global__ __launch_bounds__(256) void qkv_gemm(
    const float* __restrict__ x,
    const float* __restrict__ Wq, const float* __restrict__ bq,
    const float* __restrict__ Wk, const float* __restrict__ bk,
    const float* __restrict__ Wv, const float* __restrict__ bv)
{
    const float* W; const float* bias; float* C;
    if (blockIdx.z == 0)      { W = Wq; bias = bq; C = g_Q; }
    else if (blockIdx.z == 1) { W = Wk; bias = bk; C = g_K; }
    else                      { W = Wv; bias = bv; C = g_V; }

    __shared__ float As[BK][BM];
    __shared__ float Bs[BK][BN];

    const int tid  = threadIdx.x;
    const int row0 = blockIdx.y * BM;
    const int col0 = blockIdx.x * BN;
    const int tx = tid & 15;
    const int ty = tid >> 4;
    const int aRow = tid >> 1, aCol = (tid & 1) * 4;
    const int bRow = tid >> 5, bCol = (tid & 31) * 4;

    float acc[TM][TN];
#pragma unroll
    for (int i = 0; i < TM; i++)
#pragma unroll
        for (int j = 0; j < TN; j++) acc[i][j] = 0.f;

    for (int kk = 0; kk < IN_C; kk += BK) {
        float4 a = *(const float4*)&x[(size_t)(row0 + aRow) * IN_C + kk + aCol];
        As[aCol + 0][aRow] = a.x;
        As[aCol + 1][aRow] = a.y;
        As[aCol + 2][aRow] = a.z;
        As[aCol + 3][aRow] = a.w;
        *(float4*)&Bs[bRow][bCol] =
            *(const float4*)&W[(size_t)(kk + bRow) * HD + col0 + bCol];
        __syncthreads();
#pragma unroll
        for (int k = 0; k < BK; k++) {
            float ar[TM], br[TN];
            *(float4*)&ar[0] = *(float4*)&As[k][ty * TM];
            *(float4*)&ar[4] = *(float4*)&As[k][ty * TM + 4];
            *(float4*)&br[0] = *(float4*)&Bs[k][tx * TN];
            *(float4*)&br[4] = *(float4*)&Bs[k][tx * TN + 4];
#pragma unroll
            for (int i = 0; i < TM; i++)
#pragma unroll
                for (int j = 0; j < TN; j++)
                    acc[i][j] += ar[i] * br[j];
        }
        __syncthreads();
    }

#pragma unroll
    for (int i = 0; i < TM; i++) {
        const int r = row0 + ty * TM + i;
#pragma unroll
        for (int j0 = 0; j0 < TN; j0 += 4) {
            const int c = col0 + tx * TN + j0;
            float4 o;
            o.x = acc[i][j0 + 0] + bias[c + 0];
            o.y = acc[i][j0 + 1] + bias[c + 1];
            o.z = acc[i][j0 + 2] + bias[c + 2];
            o.w = acc[i][j0 + 3] + bias[c + 3];
            *(float4*)&C[(size_t)r * HD + c] = o;
        }
    }
}

// ---------------------------------------------------------------------------
// Unified flash attention worker — NO per-score shuffles.
// Block: 256 threads (8 warps), 64 q rows x 1 head, keys tiled by 32.
// Score phase: lane owns one key (swizzled K in smem, Q broadcast from smem).
// PV phase:    lane owns a 4-float d-slice (P staged in smem, broadcast).
// Dynamic smem: Qs 64x128 | Ks 32x128 (xor-swizzled f4) | Vs 32x128 | Ps 8x8x32
// ---------------------------------------------------------------------------
#define ATTN_SMEM_BYTES ((8192 + 4096 + 4096 + 2048) * 4)

__device__ __forceinline__ float warp_sum(float s) {
    s += __shfl_xor_sync(0xffffffffu, s, 16);
    s += __shfl_xor_sync(0xffffffffu, s, 8);
    s += __shfl_xor_sync(0xffffffffu, s, 4);
    s += __shfl_xor_sync(0xffffffffu, s, 2);
    s += __shfl_xor_sync(0xffffffffu, s, 1);
    return s;
}
__device__ __forceinline__ float warp_max(float s) {
    s = fmaxf(s, __shfl_xor_sync(0xffffffffu, s, 16));
    s = fmaxf(s, __shfl_xor_sync(0xffffffffu, s, 8));
    s = fmaxf(s, __shfl_xor_sync(0xffffffffu, s, 4));
    s = fmaxf(s, __shfl_xor_sync(0xffffffffu, s, 2));
    s = fmaxf(s, __shfl_xor_sync(0xffffffffu, s, 1));
    return s;
}

template<int LKEYS, bool GATHER>
__global__ __launch_bounds__(256) void attn_kern(const int* __restrict__ pidx)
{
    extern __shared__ float sm[];
    float*  Qs  = sm;                           // [64][128]
    float4* Ks4 = (float4*)(sm + 8192);         // [32][32] f4, xor-swizzled
    float4* Vs4 = (float4*)(sm + 8192 + 4096);  // [32][32] f4, plain
    float*  Ps  = sm + 8192 + 8192;             // [8 warps][8 rows][32 keys]

    const int tid = threadIdx.x, warp = tid >> 5, lane = tid & 31;
    const int h = blockIdx.y;

    const float* Kg = GATHER ? g_K    : g_repK;
    const float* Vg = GATHER ? g_V    : g_repV;
    float*       Og = GATHER ? g_outL : g_outG;
    const int*   pi = GATHER ? (pidx + blockIdx.x * SSZ) : (const int*)0;
    const int    q0 = GATHER ? (int)blockIdx.z * 64 : (int)blockIdx.x * 64;

    // ---- stage Q tile (pre-scaled by 1/sqrt(D)) ----
    {
        const int r  = tid >> 2;
        const int c0 = (tid & 3) * 32;
        const int node = GATHER ? pi[q0 + r] : (q0 + r);
        const float* src = g_Q + (size_t)node * HD + h * DD + c0;
        float* dst = Qs + r * DD + c0;
#pragma unroll
        for (int c = 0; c < 8; c++) {
            float4 v = *(const float4*)(src + 4 * c);
            v.x *= INV_SCALE; v.y *= INV_SCALE; v.z *= INV_SCALE; v.w *= INV_SCALE;
            *(float4*)(dst + 4 * c) = v;
        }
    }

    float4 acc[8];
    float  m[8], l[8];
#pragma unroll
    for (int i = 0; i < 8; i++) {
        acc[i] = make_float4(0.f, 0.f, 0.f, 0.f);
        m[i] = -INFINITY; l[i] = 0.f;
    }

    float*       PsW = Ps + warp * 256;
    const float* QsW = Qs + (warp * 8) * DD;
    const int    lsw = lane & 7;

    for (int t = 0; t < LKEYS; t += 32) {
        __syncthreads();   // protects previous tile reads (and Q staging first iter)
        {   // ---- stage K (swizzled) + V tile ----
            const int r  = tid >> 3;
            const int c0 = (tid & 7) * 4;   // f4 column
            const int knode = GATHER ? pi[t + r] : (t + r);
            const float4* ksrc = (const float4*)(Kg + (size_t)knode * HD + h * DD) + c0;
            const float4* vsrc = (const float4*)(Vg + (size_t)knode * HD + h * DD) + c0;
#pragma unroll
            for (int c = 0; c < 4; c++) {
                Ks4[r * 32 + ((c0 + c) ^ (r & 7))] = ksrc[c];
                Vs4[r * 32 + c0 + c]               = vsrc[c];
            }
        }
        __syncthreads();

        // ---- scores: lane owns key 'lane'; 8 q rows; pure FMA ----
        float s[8];
#pragma unroll
        for (int i = 0; i < 8; i++) s[i] = 0.f;
#pragma unroll
        for (int d4 = 0; d4 < 32; d4++) {
            float4 k = Ks4[lane * 32 + (d4 ^ lsw)];
#pragma unroll
            for (int i = 0; i < 8; i++) {
                float4 q = *(const float4*)(QsW + i * DD + d4 * 4);
                s[i] += q.x * k.x + q.y * k.y + q.z * k.z + q.w * k.w;
            }
        }

        // ---- online softmax per row (only place with shuffles) ----
#pragma unroll
        for (int i = 0; i < 8; i++) {
            const float tm   = warp_max(s[i]);
            const float mnew = fmaxf(m[i], tm);
            const float corr = __expf(m[i] - mnew);
            m[i] = mnew;
            const float p = __expf(s[i] - mnew);
            PsW[i * 32 + lane] = p;
            const float rs = warp_sum(p);
            l[i] = l[i] * corr + rs;
            acc[i].x *= corr; acc[i].y *= corr; acc[i].z *= corr; acc[i].w *= corr;
        }
        __syncwarp();

        // ---- PV: lane owns d-slice lane*4; P broadcast from smem ----
#pragma unroll
        for (int jq = 0; jq < 8; jq++) {
            const float4 v0 = Vs4[(jq * 4 + 0) * 32 + lane];
            const float4 v1 = Vs4[(jq * 4 + 1) * 32 + lane];
            const float4 v2 = Vs4[(jq * 4 + 2) * 32 + lane];
            const float4 v3 = Vs4[(jq * 4 + 3) * 32 + lane];
#pragma unroll
            for (int i = 0; i < 8; i++) {
                const float4 p = *(const float4*)(PsW + i * 32 + jq * 4);
                acc[i].x += p.x * v0.x + p.y * v1.x + p.z * v2.x + p.w * v3.x;
                acc[i].y += p.x * v0.y + p.y * v1.y + p.z * v2.y + p.w * v3.y;
                acc[i].z += p.x * v0.z + p.y * v1.z + p.z * v2.z + p.w * v3.z;
                acc[i].w += p.x * v0.w + p.y * v1.w + p.z * v2.w + p.w * v3.w;
            }
        }
        __syncwarp();
    }

    // ---- normalize + write out ----
#pragma unroll
    for (int i = 0; i < 8; i++) {
        const int r = warp * 8 + i;
        const int node = GATHER ? pi[q0 + r] : (q0 + r);
        const float inv = 1.f / l[i];
        float4 o;
        o.x = acc[i].x * inv; o.y = acc[i].y * inv;
        o.z = acc[i].z * inv; o.w = acc[i].w * inv;
        *(float4*)(Og + (size_t)node * HD + h * DD + lane * 4) = o;
    }
}

// ---------------------------------------------------------------------------
// Kernel 3: coarse pooling — seeds attend over each partition's K.
// ---------------------------------------------------------------------------
#define TSK 32

__global__ __launch_bounds__(128) void coarse_pool(const int* __restrict__ pidx,
                                                   const float* __restrict__ seeds)
{
    const int kpart = blockIdx.x;
    const int h     = blockIdx.y;
    const int tid = threadIdx.x, m = tid >> 5, lane = tid & 31;

    __shared__ float Ks[TSK][DD];
    __shared__ float Vs[TSK][DD];
    __shared__ float Sx[MM][SSZ];

    const int* pi = pidx + kpart * SSZ;

    float4 sq = *(const float4*)&seeds[(size_t)m * HD + h * DD + lane * 4];
    const float q0 = sq.x * INV_SCALE, q1 = sq.y * INV_SCALE;
    const float q2 = sq.z * INV_SCALE, q3 = sq.w * INV_SCALE;

    float tmax = -INFINITY;
    for (int t = 0; t < SSZ; t += TSK) {
        {
            const int j = tid >> 2, d0 = (tid & 3) * 32;
            const int node = pi[t + j];
            const float* kp = &g_K[(size_t)node * HD + h * DD + d0];
#pragma unroll
            for (int c = 0; c < 8; c++)
                *(float4*)&Ks[j][d0 + 4 * c] = *(const float4*)(kp + 4 * c);
        }
        __syncthreads();
#pragma unroll
        for (int jj = 0; jj < TSK; jj++) {
            float4 kk = *(float4*)&Ks[jj][lane * 4];
            float s = q0 * kk.x + q1 * kk.y + q2 * kk.z + q3 * kk.w;
            s = warp_sum(s);
            if (lane == 0) Sx[m][t + jj] = s;
            tmax = fmaxf(tmax, s);
        }
        __syncthreads();
    }
    __syncwarp();

    float lsum = 0.f;
    for (int jj = lane; jj < SSZ; jj += 32) {
        const float p = __expf(Sx[m][jj] - tmax);
        Sx[m][jj] = p;
        lsum += p;
    }
    lsum = warp_sum(lsum);
    __syncwarp();

    float rk[4] = {0.f, 0.f, 0.f, 0.f};
    float rv[4] = {0.f, 0.f, 0.f, 0.f};
    for (int t = 0; t < SSZ; t += TSK) {
        {
            const int j = tid >> 2, d0 = (tid & 3) * 32;
            const int node = pi[t + j];
            const float* kp = &g_K[(size_t)node * HD + h * DD + d0];
            const float* vp = &g_V[(size_t)node * HD + h * DD + d0];
#pragma unroll
            for (int c = 0; c < 8; c++) {
                *(float4*)&Ks[j][d0 + 4 * c] = *(const float4*)(kp + 4 * c);
                *(float4*)&Vs[j][d0 + 4 * c] = *(const float4*)(vp + 4 * c);
            }
        }
        __syncthreads();
#pragma unroll
        for (int jj = 0; jj < TSK; jj++) {
            const float p = Sx[m][t + jj];
            float4 kk = *(float4*)&Ks[jj][lane * 4];
            float4 vv = *(float4*)&Vs[jj][lane * 4];
            rk[0] += p * kk.x; rk[1] += p * kk.y; rk[2] += p * kk.z; rk[3] += p * kk.w;
            rv[0] += p * vv.x; rv[1] += p * vv.y; rv[2] += p * vv.z; rv[3] += p * vv.w;
        }
        __syncthreads();
    }

    const float inv = 1.f / lsum;
    const int r = kpart * MM + m;
    float4 ok, ov;
    ok.x = rk[0] * inv; ok.y = rk[1] * inv; ok.z = rk[2] * inv; ok.w = rk[3] * inv;
    ov.x = rv[0] * inv; ov.y = rv[1] * inv; ov.z = rv[2] * inv; ov.w = rv[3] * inv;
    *(float4*)&g_repK[(size_t)r * HD + h * DD + lane * 4] = ok;
    *(float4*)&g_repV[(size_t)r * HD + h * DD + lane * 4] = ov;
}

// ---------------------------------------------------------------------------
// Kernel 5: combine — out = a*mean_h(outL) + (1-a)*mean_h(outG) + b*mean_h(V)
// ---------------------------------------------------------------------------
__global__ __launch_bounds__(256) void combine(const float* __restrict__ alpha_logit,
                                               const float* __restrict__ beta_p,
                                               float* __restrict__ out)
{
    const int idx = blockIdx.x * blockDim.x + threadIdx.x;
    const int n  = idx / (DD / 4);
    const int d4 = (idx % (DD / 4)) * 4;

    const float alpha = 1.f / (1.f + __expf(-alpha_logit[0]));
    const float beta  = beta_p[0];
    const float ca = alpha * 0.25f;
    const float cg = (1.f - alpha) * 0.25f;
    const float cb = beta * 0.25f;

    float sl0 = 0, sl1 = 0, sl2 = 0, sl3 = 0;
    float sg0 = 0, sg1 = 0, sg2 = 0, sg3 = 0;
    float sv0 = 0, sv1 = 0, sv2 = 0, sv3 = 0;
#pragma unroll
    for (int h = 0; h < HH; h++) {
        const size_t base = (size_t)n * HD + h * DD + d4;
        float4 a = *(const float4*)&g_outL[base];
        float4 b = *(const float4*)&g_outG[base];
        float4 c = *(const float4*)&g_V[base];
        sl0 += a.x; sl1 += a.y; sl2 += a.z; sl3 += a.w;
        sg0 += b.x; sg1 += b.y; sg2 += b.z; sg3 += b.w;
        sv0 += c.x; sv1 += c.y; sv2 += c.z; sv3 += c.w;
    }
    float4 o;
    o.x = ca * sl0 + cg * sg0 + cb * sv0;
    o.y = ca * sl1 + cg * sg1 + cb * sv1;
    o.z = ca * sl2 + cg * sg2 + cb * sv2;
    o.w = ca * sl3 + cg * sg3 + cb * sv3;
    *(float4*)&out[(size_t)n * DD + d4] = o;
}

// ---------------------------------------------------------------------------
// Launcher
// ---------------------------------------------------------------------------
extern "C" void kernel_launch(void* const* d_in, const int* in_sizes, int n_in,
                              void* d_out, int out_size)
{
    (void)in_sizes; (void)n_in; (void)out_size;
    const float* x     = (const float*)d_in[0];
    const int*   pidx  = (const int*)  d_in[1];
    const float* Wq    = (const float*)d_in[2];
    const float* bq    = (const float*)d_in[3];
    const float* Wk    = (const float*)d_in[4];
    const float* bk    = (const float*)d_in[5];
    const float* Wv    = (const float*)d_in[6];
    const float* bv    = (const float*)d_in[7];
    const float* seeds = (const float*)d_in[8];
    const float* alog  = (const float*)d_in[9];
    const float* beta  = (const float*)d_in[10];
    float* out = (float*)d_out;

    // raise dynamic smem limit (idempotent host-state calls; capture-legal)
    cudaFuncSetAttribute((const void*)attn_kern<SSZ, true>,
                         cudaFuncAttributeMaxDynamicSharedMemorySize, ATTN_SMEM_BYTES);
    cudaFuncSetAttribute((const void*)attn_kern<RR, false>,
                         cudaFuncAttributeMaxDynamicSharedMemorySize, ATTN_SMEM_BYTES);

    dim3 g1(HD / BN, NN / BM, 3);
    qkv_gemm<<<g1, 256>>>(x, Wq, bq, Wk, bk, Wv, bv);

    dim3 g2(KPP, HH, SSZ / 64);                 // fine attention: 128 x 4 x 4
    attn_kern<SSZ, true><<<g2, 256, ATTN_SMEM_BYTES>>>(pidx);

    dim3 g3(KPP, HH);                           // coarse pooling
    coarse_pool<<<g3, 128>>>(pidx, seeds);

    dim3 g4(NN / 64, HH);                       // global cross-attention: 512 x 4
    attn_kern<RR, false><<<g4, 256, ATTN_SMEM_BYTES>>>(nullptr);

    combine<<<(NN * DD / 4) / 256, 256>>>(alog, beta, out);
}

// round 5
// speedup vs baseline: 2.5284x; 1.0004x over previous
#include <cuda_runtime.h>
#include <math.h>

// ---------------------------------------------------------------------------
// Problem constants
// ---------------------------------------------------------------------------
#define NN   32768          // nodes
#define IN_C 256            // in channels
#define DD   128            // per-head dim
#define HH   4              // heads
#define HD   512            // H*D
#define MM   4              // seeds per partition
#define KPP  128            // partitions
#define SSZ  256            // partition size
#define RR   (KPP*MM)       // 512 reps
#define INV_SCALE 0.088388347648318447f   // 1/sqrt(128)

// ---------------------------------------------------------------------------
// Scratch (static device globals; no allocation allowed)
// ---------------------------------------------------------------------------
__device__ float g_Q[(size_t)NN*HD];
__device__ float g_K[(size_t)NN*HD];
__device__ float g_V[(size_t)NN*HD];
__device__ float g_outL[(size_t)NN*HD];
__device__ float g_outG[(size_t)NN*HD];
__device__ float g_repK[(size_t)RR*HD];
__device__ float g_repV[(size_t)RR*HD];

// ---------------------------------------------------------------------------
// Kernel 1: fused QKV GEMM  C = x @ W + b   (M=32768, K=256, N=512)
// ---------------------------------------------------------------------------
#define BM 128
#define BN 128
#define BK 8
#define TM 8
#define TN 8

__global__ __launch_bounds__(256) void qkv_gemm(
    const float* __restrict__ x,
    const float* __restrict__ Wq, const float* __restrict__ bq,
    const float* __restrict__ Wk, const float* __restrict__ bk,
    const float* __restrict__ Wv, const float* __restrict__ bv)
{
    const float* W; const float* bias; float* C;
    if (blockIdx.z == 0)      { W = Wq; bias = bq; C = g_Q; }
    else if (blockIdx.z == 1) { W = Wk; bias = bk; C = g_K; }
    else                      { W = Wv; bias = bv; C = g_V; }

    __shared__ float As[BK][BM];
    __shared__ float Bs[BK][BN];

    const int tid  = threadIdx.x;
    const int row0 = blockIdx.y * BM;
    const int col0 = blockIdx.x * BN;
    const int tx = tid & 15;
    const int ty = tid >> 4;
    const int aRow = tid >> 1, aCol = (tid & 1) * 4;
    const int bRow = tid >> 5, bCol = (tid & 31) * 4;

    float acc[TM][TN];
#pragma unroll
    for (int i = 0; i < TM; i++)
#pragma unroll
        for (int j = 0; j < TN; j++) acc[i][j] = 0.f;

    for (int kk = 0; kk < IN_C; kk += BK) {
        float4 a = *(const float4*)&x[(size_t)(row0 + aRow) * IN_C + kk + aCol];
        As[aCol + 0][aRow] = a.x;
        As[aCol + 1][aRow] = a.y;
        As[aCol + 2][aRow] = a.z;
        As[aCol + 3][aRow] = a.w;
        *(float4*)&Bs[bRow][bCol] =
            *(const float4*)&W[(size_t)(kk + bRow) * HD + col0 + bCol];
        __syncthreads();
#pragma unroll
        for (int k = 0; k < BK; k++) {
            float ar[TM], br[TN];
            *(float4*)&ar[0] = *(float4*)&As[k][ty * TM];
            *(float4*)&ar[4] = *(float4*)&As[k][ty * TM + 4];
            *(float4*)&br[0] = *(float4*)&Bs[k][tx * TN];
            *(float4*)&br[4] = *(float4*)&Bs[k][tx * TN + 4];
#pragma unroll
            for (int i = 0; i < TM; i++)
#pragma unroll
                for (int j = 0; j < TN; j++)
                    acc[i][j] += ar[i] * br[j];
        }
        __syncthreads();
    }

#pragma unroll
    for (int i = 0; i < TM; i++) {
        const int r = row0 + ty * TM + i;
#pragma unroll
        for (int j0 = 0; j0 < TN; j0 += 4) {
            const int c = col0 + tx * TN + j0;
            float4 o;
            o.x = acc[i][j0 + 0] + bias[c + 0];
            o.y = acc[i][j0 + 1] + bias[c + 1];
            o.z = acc[i][j0 + 2] + bias[c + 2];
            o.w = acc[i][j0 + 3] + bias[c + 3];
            *(float4*)&C[(size_t)r * HD + c] = o;
        }
    }
}

// ---------------------------------------------------------------------------
// Unified flash attention worker — NO per-score shuffles.
// Block: 256 threads (8 warps), 64 q rows x 1 head, keys tiled by 32.
// Score phase: lane owns one key (swizzled K in smem, Q broadcast from smem).
// PV phase:    lane owns a 4-float d-slice (P staged in smem, broadcast).
// Dynamic smem: Qs 64x128 | Ks 32x128 (xor-swizzled f4) | Vs 32x128 | Ps 8x8x32
// ---------------------------------------------------------------------------
#define ATTN_SMEM_BYTES ((8192 + 4096 + 4096 + 2048) * 4)

__device__ __forceinline__ float warp_sum(float s) {
    s += __shfl_xor_sync(0xffffffffu, s, 16);
    s += __shfl_xor_sync(0xffffffffu, s, 8);
    s += __shfl_xor_sync(0xffffffffu, s, 4);
    s += __shfl_xor_sync(0xffffffffu, s, 2);
    s += __shfl_xor_sync(0xffffffffu, s, 1);
    return s;
}
__device__ __forceinline__ float warp_max(float s) {
    s = fmaxf(s, __shfl_xor_sync(0xffffffffu, s, 16));
    s = fmaxf(s, __shfl_xor_sync(0xffffffffu, s, 8));
    s = fmaxf(s, __shfl_xor_sync(0xffffffffu, s, 4));
    s = fmaxf(s, __shfl_xor_sync(0xffffffffu, s, 2));
    s = fmaxf(s, __shfl_xor_sync(0xffffffffu, s, 1));
    return s;
}

template<int LKEYS, bool GATHER>
__global__ __launch_bounds__(256) void attn_kern(const int* __restrict__ pidx)
{
    extern __shared__ float sm[];
    float*  Qs  = sm;                           // [64][128]
    float4* Ks4 = (float4*)(sm + 8192);         // [32][32] f4, xor-swizzled
    float4* Vs4 = (float4*)(sm + 8192 + 4096);  // [32][32] f4, plain
    float*  Ps  = sm + 8192 + 8192;             // [8 warps][8 rows][32 keys]

    const int tid = threadIdx.x, warp = tid >> 5, lane = tid & 31;
    const int h = blockIdx.y;

    const float* Kg = GATHER ? g_K    : g_repK;
    const float* Vg = GATHER ? g_V    : g_repV;
    float*       Og = GATHER ? g_outL : g_outG;
    const int*   pi = GATHER ? (pidx + blockIdx.x * SSZ) : (const int*)0;
    const int    q0 = GATHER ? (int)blockIdx.z * 64 : (int)blockIdx.x * 64;

    // ---- stage Q tile (pre-scaled by 1/sqrt(D)) ----
    {
        const int r  = tid >> 2;
        const int c0 = (tid & 3) * 32;
        const int node = GATHER ? pi[q0 + r] : (q0 + r);
        const float* src = g_Q + (size_t)node * HD + h * DD + c0;
        float* dst = Qs + r * DD + c0;
#pragma unroll
        for (int c = 0; c < 8; c++) {
            float4 v = *(const float4*)(src + 4 * c);
            v.x *= INV_SCALE; v.y *= INV_SCALE; v.z *= INV_SCALE; v.w *= INV_SCALE;
            *(float4*)(dst + 4 * c) = v;
        }
    }

    float4 acc[8];
    float  m[8], l[8];
#pragma unroll
    for (int i = 0; i < 8; i++) {
        acc[i] = make_float4(0.f, 0.f, 0.f, 0.f);
        m[i] = -INFINITY; l[i] = 0.f;
    }

    float*       PsW = Ps + warp * 256;
    const float* QsW = Qs + (warp * 8) * DD;
    const int    lsw = lane & 7;

    for (int t = 0; t < LKEYS; t += 32) {
        __syncthreads();   // protects previous tile reads (and Q staging first iter)
        {   // ---- stage K (swizzled) + V tile ----
            const int r  = tid >> 3;
            const int c0 = (tid & 7) * 4;   // f4 column
            const int knode = GATHER ? pi[t + r] : (t + r);
            const float4* ksrc = (const float4*)(Kg + (size_t)knode * HD + h * DD) + c0;
            const float4* vsrc = (const float4*)(Vg + (size_t)knode * HD + h * DD) + c0;
#pragma unroll
            for (int c = 0; c < 4; c++) {
                Ks4[r * 32 + ((c0 + c) ^ (r & 7))] = ksrc[c];
                Vs4[r * 32 + c0 + c]               = vsrc[c];
            }
        }
        __syncthreads();

        // ---- scores: lane owns key 'lane'; 8 q rows; pure FMA ----
        float s[8];
#pragma unroll
        for (int i = 0; i < 8; i++) s[i] = 0.f;
#pragma unroll
        for (int d4 = 0; d4 < 32; d4++) {
            float4 k = Ks4[lane * 32 + (d4 ^ lsw)];
#pragma unroll
            for (int i = 0; i < 8; i++) {
                float4 q = *(const float4*)(QsW + i * DD + d4 * 4);
                s[i] += q.x * k.x + q.y * k.y + q.z * k.z + q.w * k.w;
            }
        }

        // ---- online softmax per row (only place with shuffles) ----
#pragma unroll
        for (int i = 0; i < 8; i++) {
            const float tm   = warp_max(s[i]);
            const float mnew = fmaxf(m[i], tm);
            const float corr = __expf(m[i] - mnew);
            m[i] = mnew;
            const float p = __expf(s[i] - mnew);
            PsW[i * 32 + lane] = p;
            const float rs = warp_sum(p);
            l[i] = l[i] * corr + rs;
            acc[i].x *= corr; acc[i].y *= corr; acc[i].z *= corr; acc[i].w *= corr;
        }
        __syncwarp();

        // ---- PV: lane owns d-slice lane*4; P broadcast from smem ----
#pragma unroll
        for (int jq = 0; jq < 8; jq++) {
            const float4 v0 = Vs4[(jq * 4 + 0) * 32 + lane];
            const float4 v1 = Vs4[(jq * 4 + 1) * 32 + lane];
            const float4 v2 = Vs4[(jq * 4 + 2) * 32 + lane];
            const float4 v3 = Vs4[(jq * 4 + 3) * 32 + lane];
#pragma unroll
            for (int i = 0; i < 8; i++) {
                const float4 p = *(const float4*)(PsW + i * 32 + jq * 4);
                acc[i].x += p.x * v0.x + p.y * v1.x + p.z * v2.x + p.w * v3.x;
                acc[i].y += p.x * v0.y + p.y * v1.y + p.z * v2.y + p.w * v3.y;
                acc[i].z += p.x * v0.z + p.y * v1.z + p.z * v2.z + p.w * v3.z;
                acc[i].w += p.x * v0.w + p.y * v1.w + p.z * v2.w + p.w * v3.w;
            }
        }
        __syncwarp();
    }

    // ---- normalize + write out ----
#pragma unroll
    for (int i = 0; i < 8; i++) {
        const int r = warp * 8 + i;
        const int node = GATHER ? pi[q0 + r] : (q0 + r);
        const float inv = 1.f / l[i];
        float4 o;
        o.x = acc[i].x * inv; o.y = acc[i].y * inv;
        o.z = acc[i].z * inv; o.w = acc[i].w * inv;
        *(float4*)(Og + (size_t)node * HD + h * DD + lane * 4) = o;
    }
}

// ---------------------------------------------------------------------------
// Kernel 3: coarse pooling — seeds attend over each partition's K.
// ---------------------------------------------------------------------------
#define TSK 32

__global__ __launch_bounds__(128) void coarse_pool(const int* __restrict__ pidx,
                                                   const float* __restrict__ seeds)
{
    const int kpart = blockIdx.x;
    const int h     = blockIdx.y;
    const int tid = threadIdx.x, m = tid >> 5, lane = tid & 31;

    __shared__ float Ks[TSK][DD];
    __shared__ float Vs[TSK][DD];
    __shared__ float Sx[MM][SSZ];

    const int* pi = pidx + kpart * SSZ;

    float4 sq = *(const float4*)&seeds[(size_t)m * HD + h * DD + lane * 4];
    const float q0 = sq.x * INV_SCALE, q1 = sq.y * INV_SCALE;
    const float q2 = sq.z * INV_SCALE, q3 = sq.w * INV_SCALE;

    float tmax = -INFINITY;
    for (int t = 0; t < SSZ; t += TSK) {
        {
            const int j = tid >> 2, d0 = (tid & 3) * 32;
            const int node = pi[t + j];
            const float* kp = &g_K[(size_t)node * HD + h * DD + d0];
#pragma unroll
            for (int c = 0; c < 8; c++)
                *(float4*)&Ks[j][d0 + 4 * c] = *(const float4*)(kp + 4 * c);
        }
        __syncthreads();
#pragma unroll
        for (int jj = 0; jj < TSK; jj++) {
            float4 kk = *(float4*)&Ks[jj][lane * 4];
            float s = q0 * kk.x + q1 * kk.y + q2 * kk.z + q3 * kk.w;
            s = warp_sum(s);
            if (lane == 0) Sx[m][t + jj] = s;
            tmax = fmaxf(tmax, s);
        }
        __syncthreads();
    }
    __syncwarp();

    float lsum = 0.f;
    for (int jj = lane; jj < SSZ; jj += 32) {
        const float p = __expf(Sx[m][jj] - tmax);
        Sx[m][jj] = p;
        lsum += p;
    }
    lsum = warp_sum(lsum);
    __syncwarp();

    float rk[4] = {0.f, 0.f, 0.f, 0.f};
    float rv[4] = {0.f, 0.f, 0.f, 0.f};
    for (int t = 0; t < SSZ; t += TSK) {
        {
            const int j = tid >> 2, d0 = (tid & 3) * 32;
            const int node = pi[t + j];
            const float* kp = &g_K[(size_t)node * HD + h * DD + d0];
            const float* vp = &g_V[(size_t)node * HD + h * DD + d0];
#pragma unroll
            for (int c = 0; c < 8; c++) {
                *(float4*)&Ks[j][d0 + 4 * c] = *(const float4*)(kp + 4 * c);
                *(float4*)&Vs[j][d0 + 4 * c] = *(const float4*)(vp + 4 * c);
            }
        }
        __syncthreads();
#pragma unroll
        for (int jj = 0; jj < TSK; jj++) {
            const float p = Sx[m][t + jj];
            float4 kk = *(float4*)&Ks[jj][lane * 4];
            float4 vv = *(float4*)&Vs[jj][lane * 4];
            rk[0] += p * kk.x; rk[1] += p * kk.y; rk[2] += p * kk.z; rk[3] += p * kk.w;
            rv[0] += p * vv.x; rv[1] += p * vv.y; rv[2] += p * vv.z; rv[3] += p * vv.w;
        }
        __syncthreads();
    }

    const float inv = 1.f / lsum;
    const int r = kpart * MM + m;
    float4 ok, ov;
    ok.x = rk[0] * inv; ok.y = rk[1] * inv; ok.z = rk[2] * inv; ok.w = rk[3] * inv;
    ov.x = rv[0] * inv; ov.y = rv[1] * inv; ov.z = rv[2] * inv; ov.w = rv[3] * inv;
    *(float4*)&g_repK[(size_t)r * HD + h * DD + lane * 4] = ok;
    *(float4*)&g_repV[(size_t)r * HD + h * DD + lane * 4] = ov;
}

// ---------------------------------------------------------------------------
// Kernel 5: combine — out = a*mean_h(outL) + (1-a)*mean_h(outG) + b*mean_h(V)
// ---------------------------------------------------------------------------
__global__ __launch_bounds__(256) void combine(const float* __restrict__ alpha_logit,
                                               const float* __restrict__ beta_p,
                                               float* __restrict__ out)
{
    const int idx = blockIdx.x * blockDim.x + threadIdx.x;
    const int n  = idx / (DD / 4);
    const int d4 = (idx % (DD / 4)) * 4;

    const float alpha = 1.f / (1.f + __expf(-alpha_logit[0]));
    const float beta  = beta_p[0];
    const float ca = alpha * 0.25f;
    const float cg = (1.f - alpha) * 0.25f;
    const float cb = beta * 0.25f;

    float sl0 = 0, sl1 = 0, sl2 = 0, sl3 = 0;
    float sg0 = 0, sg1 = 0, sg2 = 0, sg3 = 0;
    float sv0 = 0, sv1 = 0, sv2 = 0, sv3 = 0;
#pragma unroll
    for (int h = 0; h < HH; h++) {
        const size_t base = (size_t)n * HD + h * DD + d4;
        float4 a = *(const float4*)&g_outL[base];
        float4 b = *(const float4*)&g_outG[base];
        float4 c = *(const float4*)&g_V[base];
        sl0 += a.x; sl1 += a.y; sl2 += a.z; sl3 += a.w;
        sg0 += b.x; sg1 += b.y; sg2 += b.z; sg3 += b.w;
        sv0 += c.x; sv1 += c.y; sv2 += c.z; sv3 += c.w;
    }
    float4 o;
    o.x = ca * sl0 + cg * sg0 + cb * sv0;
    o.y = ca * sl1 + cg * sg1 + cb * sv1;
    o.z = ca * sl2 + cg * sg2 + cb * sv2;
    o.w = ca * sl3 + cg * sg3 + cb * sv3;
    *(float4*)&out[(size_t)n * DD + d4] = o;
}

// ---------------------------------------------------------------------------
// Launcher
// ---------------------------------------------------------------------------
extern "C" void kernel_launch(void* const* d_in, const int* in_sizes, int n_in,
                              void* d_out, int out_size)
{
    (void)in_sizes; (void)n_in; (void)out_size;
    const float* x     = (const float*)d_in[0];
    const int*   pidx  = (const int*)  d_in[1];
    const float* Wq    = (const float*)d_in[2];
    const float* bq    = (const float*)d_in[3];
    const float* Wk    = (const float*)d_in[4];
    const float* bk    = (const float*)d_in[5];
    const float* Wv    = (const float*)d_in[6];
    const float* bv    = (const float*)d_in[7];
    const float* seeds = (const float*)d_in[8];
    const float* alog  = (const float*)d_in[9];
    const float* beta  = (const float*)d_in[10];
    float* out = (float*)d_out;

    // raise dynamic smem limit (idempotent host-state calls; capture-legal)
    cudaFuncSetAttribute((const void*)attn_kern<SSZ, true>,
                         cudaFuncAttributeMaxDynamicSharedMemorySize, ATTN_SMEM_BYTES);
    cudaFuncSetAttribute((const void*)attn_kern<RR, false>,
                         cudaFuncAttributeMaxDynamicSharedMemorySize, ATTN_SMEM_BYTES);

    dim3 g1(HD / BN, NN / BM, 3);
    qkv_gemm<<<g1, 256>>>(x, Wq, bq, Wk, bk, Wv, bv);

    dim3 g2(KPP, HH, SSZ / 64);                 // fine attention: 128 x 4 x 4
    attn_kern<SSZ, true><<<g2, 256, ATTN_SMEM_BYTES>>>(pidx);

    dim3 g3(KPP, HH);                           // coarse pooling
    coarse_pool<<<g3, 128>>>(pidx, seeds);

    dim3 g4(NN / 64, HH);                       // global cross-attention: 512 x 4
    attn_kern<RR, false><<<g4, 256, ATTN_SMEM_BYTES>>>(nullptr);

    combine<<<(NN * DD / 4) / 256, 256>>>(alog, beta, out);
}

// round 6
// speedup vs baseline: 5.2997x; 2.0960x over previous
#include <cuda_runtime.h>
#include <math.h>
#include <stdint.h>

// ---------------------------------------------------------------------------
// Problem constants
// ---------------------------------------------------------------------------
#define NN   32768
#define IN_C 256
#define DD   128
#define HH   4
#define HD   512
#define MM   4
#define KPP  128
#define SSZ  256
#define RR   (KPP*MM)
#define INV_SCALE 0.088388347648318447f   // 1/sqrt(128)

// ---------------------------------------------------------------------------
// Scratch (static device globals; no allocation allowed)
// ---------------------------------------------------------------------------
__device__ float g_Q[(size_t)NN*HD];
__device__ float g_K[(size_t)NN*HD];
__device__ float g_V[(size_t)NN*HD];
__device__ float g_outL[(size_t)NN*HD];
__device__ float g_outG[(size_t)NN*HD];
__device__ float g_repK[(size_t)RR*HD];
__device__ float g_repV[(size_t)RR*HD];

// ---------------------------------------------------------------------------
// TF32 helpers
// ---------------------------------------------------------------------------
__device__ __forceinline__ float tf32_rna(float f) {
    uint32_t u;
    asm("cvt.rna.tf32.f32 %0, %1;" : "=r"(u) : "f"(f));
    return __uint_as_float(u);
}

__device__ __forceinline__ void mma_tf32(float4& d, const uint32_t a[4],
                                         const uint32_t b0, const uint32_t b1) {
    asm volatile(
        "mma.sync.aligned.m16n8k8.row.col.f32.tf32.tf32.f32 "
        "{%0,%1,%2,%3}, {%4,%5,%6,%7}, {%8,%9}, {%0,%1,%2,%3};"
        : "+f"(d.x), "+f"(d.y), "+f"(d.z), "+f"(d.w)
        : "r"(a[0]), "r"(a[1]), "r"(a[2]), "r"(a[3]), "r"(b0), "r"(b1));
}

// ---------------------------------------------------------------------------
// Kernel 1: QKV GEMM on tensor cores, 3xTF32 split (fp32-grade accuracy).
// Block 128x128, K-tile 32, 8 warps (4M x 2N), warp tile 32x64.
// Smem: Ah/Al [32k][136m], Bh/Bl [32k][136n] -> conflict-free frag loads.
// ---------------------------------------------------------------------------
#define GEMM_SMEM_BYTES (4 * 32 * 136 * 4)

__global__ __launch_bounds__(256) void qkv_gemm_tc(
    const float* __restrict__ x,
    const float* __restrict__ Wq, const float* __restrict__ bq,
    const float* __restrict__ Wk, const float* __restrict__ bk,
    const float* __restrict__ Wv, const float* __restrict__ bv)
{
    const float* W; const float* bias; float* C;
    if (blockIdx.z == 0)      { W = Wq; bias = bq; C = g_Q; }
    else if (blockIdx.z == 1) { W = Wk; bias = bk; C = g_K; }
    else                      { W = Wv; bias = bv; C = g_V; }

    extern __shared__ float smg[];
    float* Ah = smg;                 // [32][136]  (k-major: [k][m])
    float* Al = Ah + 32 * 136;
    float* Bh = Al + 32 * 136;       // [32][136]  ([k][n])
    float* Bl = Bh + 32 * 136;

    const int tid  = threadIdx.x;
    const int warp = tid >> 5, lane = tid & 31;
    const int lr = lane >> 2, lc = lane & 3;
    const int wm = warp & 3, wn = warp >> 2;
    const int row0 = blockIdx.y * 128;
    const int col0 = blockIdx.x * 128;

    float4 acc[2][8];
#pragma unroll
    for (int mi = 0; mi < 2; mi++)
#pragma unroll
        for (int ni = 0; ni < 8; ni++)
            acc[mi][ni] = make_float4(0.f, 0.f, 0.f, 0.f);

    for (int k0 = 0; k0 < IN_C; k0 += 32) {
        __syncthreads();
        {   // stage A tile (128 rows x 32 k), transposed + hi/lo split
            const int r = tid & 127;
            const int c4b = (tid >> 7) * 4;
            const float* src = x + (size_t)(row0 + r) * IN_C + k0;
#pragma unroll
            for (int j = 0; j < 4; j++) {
                float4 v = *(const float4*)(src + (c4b + j) * 4);
                const int k = (c4b + j) * 4;
                float h0 = tf32_rna(v.x), h1 = tf32_rna(v.y);
                float h2 = tf32_rna(v.z), h3 = tf32_rna(v.w);
                Ah[(k + 0) * 136 + r] = h0;  Al[(k + 0) * 136 + r] = tf32_rna(v.x - h0);
                Ah[(k + 1) * 136 + r] = h1;  Al[(k + 1) * 136 + r] = tf32_rna(v.y - h1);
                Ah[(k + 2) * 136 + r] = h2;  Al[(k + 2) * 136 + r] = tf32_rna(v.z - h2);
                Ah[(k + 3) * 136 + r] = h3;  Al[(k + 3) * 136 + r] = tf32_rna(v.w - h3);
            }
        }
        {   // stage B tile (32 k x 128 n), hi/lo split
#pragma unroll
            for (int j = 0; j < 4; j++) {
                const int p  = tid * 4 + j;       // 0..1023 f4 index
                const int kr = p >> 5, c4 = p & 31;
                float4 v = *(const float4*)(W + (size_t)(k0 + kr) * HD + col0 + c4 * 4);
                float4 h, l;
                h.x = tf32_rna(v.x); l.x = tf32_rna(v.x - h.x);
                h.y = tf32_rna(v.y); l.y = tf32_rna(v.y - h.y);
                h.z = tf32_rna(v.z); l.z = tf32_rna(v.z - h.z);
                h.w = tf32_rna(v.w); l.w = tf32_rna(v.w - h.w);
                *(float4*)&Bh[kr * 136 + c4 * 4] = h;
                *(float4*)&Bl[kr * 136 + c4 * 4] = l;
            }
        }
        __syncthreads();

#pragma unroll
        for (int kf = 0; kf < 4; kf++) {
            const int kr = kf * 8 + lc;
            uint32_t ah[2][4], al[2][4];
#pragma unroll
            for (int mi = 0; mi < 2; mi++) {
                const int m0 = wm * 32 + mi * 16 + lr;
                ah[mi][0] = __float_as_uint(Ah[kr * 136 + m0]);
                ah[mi][1] = __float_as_uint(Ah[kr * 136 + m0 + 8]);
                ah[mi][2] = __float_as_uint(Ah[(kr + 4) * 136 + m0]);
                ah[mi][3] = __float_as_uint(Ah[(kr + 4) * 136 + m0 + 8]);
                al[mi][0] = __float_as_uint(Al[kr * 136 + m0]);
                al[mi][1] = __float_as_uint(Al[kr * 136 + m0 + 8]);
                al[mi][2] = __float_as_uint(Al[(kr + 4) * 136 + m0]);
                al[mi][3] = __float_as_uint(Al[(kr + 4) * 136 + m0 + 8]);
            }
#pragma unroll
            for (int ni = 0; ni < 8; ni++) {
                const int n0 = wn * 64 + ni * 8 + lr;
                const uint32_t bh0 = __float_as_uint(Bh[kr * 136 + n0]);
                const uint32_t bh1 = __float_as_uint(Bh[(kr + 4) * 136 + n0]);
                const uint32_t bl0 = __float_as_uint(Bl[kr * 136 + n0]);
                const uint32_t bl1 = __float_as_uint(Bl[(kr + 4) * 136 + n0]);
#pragma unroll
                for (int mi = 0; mi < 2; mi++) {
                    mma_tf32(acc[mi][ni], ah[mi], bh0, bh1);
                    mma_tf32(acc[mi][ni], ah[mi], bl0, bl1);
                    mma_tf32(acc[mi][ni], al[mi], bh0, bh1);
                }
            }
        }
    }

    // epilogue: bias + store (c-frag: rows lr, lr+8; cols 2*lc, 2*lc+1)
#pragma unroll
    for (int mi = 0; mi < 2; mi++) {
        const int r = row0 + wm * 32 + mi * 16 + lr;
#pragma unroll
        for (int ni = 0; ni < 8; ni++) {
            const int c = col0 + wn * 64 + ni * 8 + 2 * lc;
            const float2 b2 = *(const float2*)&bias[c];
            *(float2*)&C[(size_t)r * HD + c] =
                make_float2(acc[mi][ni].x + b2.x, acc[mi][ni].y + b2.y);
            *(float2*)&C[(size_t)(r + 8) * HD + c] =
                make_float2(acc[mi][ni].z + b2.x, acc[mi][ni].w + b2.y);
        }
    }
}

// ---------------------------------------------------------------------------
// Flash attention on tensor cores (single tf32, rna-rounded operands).
// Block 256 thr / 8 warps; 128 q-rows per block, warp owns 16 rows; key
// tiles of 64; d=128. Q frags in regs; K d-major smem; V key-major smem;
// P round-trips through smem (c-frag -> a-frag relayout).
// ---------------------------------------------------------------------------
#define KT 64
#define ATTN_SMEM_BYTES ((128*72 + 64*136 + 128*68) * 4)

template<int LKEYS, bool GATHER>
__global__ __launch_bounds__(256) void attn_tc(const int* __restrict__ pidx)
{
    extern __shared__ float sma[];
    float* Ks = sma;                  // [128 d][72]   (stride 72: frag-LDS conflict-free)
    float* Vs = Ks + 128 * 72;        // [64 key][136]
    float* Ps = Vs + 64 * 136;        // [128 q][68]

    const int tid = threadIdx.x, warp = tid >> 5, lane = tid & 31;
    const int lr = lane >> 2, lc = lane & 3;
    const int h = blockIdx.y;

    const float* Kg = GATHER ? g_K    : g_repK;
    const float* Vg = GATHER ? g_V    : g_repV;
    float*       Og = GATHER ? g_outL : g_outG;
    const int*   pi = GATHER ? (pidx + blockIdx.x * SSZ) : (const int*)0;
    const int    q0 = GATHER ? (int)blockIdx.z * 128 : (int)blockIdx.x * 128;

    const int wq = warp * 16;
    const int n0 = GATHER ? pi[q0 + wq + lr]     : q0 + wq + lr;
    const int n1 = GATHER ? pi[q0 + wq + lr + 8] : q0 + wq + lr + 8;

    // Q a-frags (pre-scaled, tf32): 16 k-frags x 4 regs
    uint32_t qa[16][4];
    {
        const float* q0p = g_Q + (size_t)n0 * HD + h * DD;
        const float* q1p = g_Q + (size_t)n1 * HD + h * DD;
#pragma unroll
        for (int kf = 0; kf < 16; kf++) {
            const int c = kf * 8 + lc;
            qa[kf][0] = __float_as_uint(tf32_rna(q0p[c]     * INV_SCALE));
            qa[kf][1] = __float_as_uint(tf32_rna(q1p[c]     * INV_SCALE));
            qa[kf][2] = __float_as_uint(tf32_rna(q0p[c + 4] * INV_SCALE));
            qa[kf][3] = __float_as_uint(tf32_rna(q1p[c + 4] * INV_SCALE));
        }
    }

    float4 acc[16];
#pragma unroll
    for (int ni = 0; ni < 16; ni++) acc[ni] = make_float4(0.f, 0.f, 0.f, 0.f);
    float m0 = -INFINITY, m1 = -INFINITY, l0 = 0.f, l1 = 0.f;

    for (int t = 0; t < LKEYS; t += KT) {
        __syncthreads();
        {   // ---- stage K (d-major, tf32) + V (key-major, tf32) ----
            const int key = tid & 63;
            const int d0  = (tid >> 6) * 32;
            const int kn  = GATHER ? pi[t + key] : t + key;
            const float* kp = Kg + (size_t)kn * HD + h * DD + d0;
            const float* vp = Vg + (size_t)kn * HD + h * DD + d0;
#pragma unroll
            for (int c = 0; c < 8; c++) {
                float4 kv = *(const float4*)(kp + 4 * c);
                Ks[(d0 + 4*c + 0) * 72 + key] = tf32_rna(kv.x);
                Ks[(d0 + 4*c + 1) * 72 + key] = tf32_rna(kv.y);
                Ks[(d0 + 4*c + 2) * 72 + key] = tf32_rna(kv.z);
                Ks[(d0 + 4*c + 3) * 72 + key] = tf32_rna(kv.w);
                float4 vv = *(const float4*)(vp + 4 * c);
                vv.x = tf32_rna(vv.x); vv.y = tf32_rna(vv.y);
                vv.z = tf32_rna(vv.z); vv.w = tf32_rna(vv.w);
                *(float4*)&Vs[key * 136 + d0 + 4 * c] = vv;
            }
        }
        __syncthreads();

        // ---- S = Q K^T : 8 n-frags (64 keys) ----
        float4 s[8];
#pragma unroll
        for (int ni = 0; ni < 8; ni++) s[ni] = make_float4(0.f, 0.f, 0.f, 0.f);
#pragma unroll
        for (int kf = 0; kf < 16; kf++) {
            const float* kr0 = Ks + (kf * 8 + lc) * 72;
            const float* kr1 = kr0 + 4 * 72;
#pragma unroll
            for (int ni = 0; ni < 8; ni++) {
                mma_tf32(s[ni], qa[kf],
                         __float_as_uint(kr0[ni * 8 + lr]),
                         __float_as_uint(kr1[ni * 8 + lr]));
            }
        }

        // ---- online softmax (rows lr -> x,y ; lr+8 -> z,w) ----
        float tm0 = -INFINITY, tm1 = -INFINITY;
#pragma unroll
        for (int ni = 0; ni < 8; ni++) {
            tm0 = fmaxf(tm0, fmaxf(s[ni].x, s[ni].y));
            tm1 = fmaxf(tm1, fmaxf(s[ni].z, s[ni].w));
        }
        tm0 = fmaxf(tm0, __shfl_xor_sync(0xffffffffu, tm0, 1));
        tm0 = fmaxf(tm0, __shfl_xor_sync(0xffffffffu, tm0, 2));
        tm1 = fmaxf(tm1, __shfl_xor_sync(0xffffffffu, tm1, 1));
        tm1 = fmaxf(tm1, __shfl_xor_sync(0xffffffffu, tm1, 2));

        const float mn0 = fmaxf(m0, tm0), mn1 = fmaxf(m1, tm1);
        const float corr0 = __expf(m0 - mn0), corr1 = __expf(m1 - mn1);
        m0 = mn0; m1 = mn1;

        float rs0 = 0.f, rs1 = 0.f;
        float* pw0 = Ps + (wq + lr) * 68;
        float* pw1 = Ps + (wq + lr + 8) * 68;
#pragma unroll
        for (int ni = 0; ni < 8; ni++) {
            const float p0 = __expf(s[ni].x - mn0);
            const float p1 = __expf(s[ni].y - mn0);
            const float p2 = __expf(s[ni].z - mn1);
            const float p3 = __expf(s[ni].w - mn1);
            rs0 += p0 + p1; rs1 += p2 + p3;
            const int col = ni * 8 + 2 * lc;
            *(float2*)&pw0[col] = make_float2(tf32_rna(p0), tf32_rna(p1));
            *(float2*)&pw1[col] = make_float2(tf32_rna(p2), tf32_rna(p3));
        }
        rs0 += __shfl_xor_sync(0xffffffffu, rs0, 1);
        rs0 += __shfl_xor_sync(0xffffffffu, rs0, 2);
        rs1 += __shfl_xor_sync(0xffffffffu, rs1, 1);
        rs1 += __shfl_xor_sync(0xffffffffu, rs1, 2);
        l0 = l0 * corr0 + rs0;
        l1 = l1 * corr1 + rs1;
#pragma unroll
        for (int ni = 0; ni < 16; ni++) {
            acc[ni].x *= corr0; acc[ni].y *= corr0;
            acc[ni].z *= corr1; acc[ni].w *= corr1;
        }
        __syncwarp();

        // ---- O += P V : 8 k-frags (keys) x 16 n-frags (d) ----
#pragma unroll
        for (int kf = 0; kf < 8; kf++) {
            uint32_t pa[4];
            pa[0] = __float_as_uint(Ps[(wq + lr)     * 68 + kf * 8 + lc]);
            pa[1] = __float_as_uint(Ps[(wq + lr + 8) * 68 + kf * 8 + lc]);
            pa[2] = __float_as_uint(Ps[(wq + lr)     * 68 + kf * 8 + lc + 4]);
            pa[3] = __float_as_uint(Ps[(wq + lr + 8) * 68 + kf * 8 + lc + 4]);
            const float* vr0 = Vs + (kf * 8 + lc) * 136;
            const float* vr1 = vr0 + 4 * 136;
#pragma unroll
            for (int ni = 0; ni < 16; ni++) {
                mma_tf32(acc[ni], pa,
                         __float_as_uint(vr0[ni * 8 + lr]),
                         __float_as_uint(vr1[ni * 8 + lr]));
            }
        }
    }

    // ---- normalize + write ----
    const float inv0 = 1.f / l0, inv1 = 1.f / l1;
    float* o0 = Og + (size_t)n0 * HD + h * DD;
    float* o1 = Og + (size_t)n1 * HD + h * DD;
#pragma unroll
    for (int ni = 0; ni < 16; ni++) {
        const int col = ni * 8 + 2 * lc;
        *(float2*)&o0[col] = make_float2(acc[ni].x * inv0, acc[ni].y * inv0);
        *(float2*)&o1[col] = make_float2(acc[ni].z * inv1, acc[ni].w * inv1);
    }
}

// ---------------------------------------------------------------------------
// Kernel 3: coarse pooling (unchanged — small)
// ---------------------------------------------------------------------------
#define TSK 32

__device__ __forceinline__ float warp_sum(float s) {
    s += __shfl_xor_sync(0xffffffffu, s, 16);
    s += __shfl_xor_sync(0xffffffffu, s, 8);
    s += __shfl_xor_sync(0xffffffffu, s, 4);
    s += __shfl_xor_sync(0xffffffffu, s, 2);
    s += __shfl_xor_sync(0xffffffffu, s, 1);
    return s;
}

__global__ __launch_bounds__(128) void coarse_pool(const int* __restrict__ pidx,
                                                   const float* __restrict__ seeds)
{
    const int kpart = blockIdx.x;
    const int h     = blockIdx.y;
    const int tid = threadIdx.x, m = tid >> 5, lane = tid & 31;

    __shared__ float Ksm[TSK][DD];
    __shared__ float Vsm[TSK][DD];
    __shared__ float Sx[MM][SSZ];

    const int* pi = pidx + kpart * SSZ;

    float4 sq = *(const float4*)&seeds[(size_t)m * HD + h * DD + lane * 4];
    const float q0 = sq.x * INV_SCALE, q1 = sq.y * INV_SCALE;
    const float q2 = sq.z * INV_SCALE, q3 = sq.w * INV_SCALE;

    float tmax = -INFINITY;
    for (int t = 0; t < SSZ; t += TSK) {
        {
            const int j = tid >> 2, d0 = (tid & 3) * 32;
            const int node = pi[t + j];
            const float* kp = &g_K[(size_t)node * HD + h * DD + d0];
#pragma unroll
            for (int c = 0; c < 8; c++)
                *(float4*)&Ksm[j][d0 + 4 * c] = *(const float4*)(kp + 4 * c);
        }
        __syncthreads();
#pragma unroll
        for (int jj = 0; jj < TSK; jj++) {
            float4 kk = *(float4*)&Ksm[jj][lane * 4];
            float s = q0 * kk.x + q1 * kk.y + q2 * kk.z + q3 * kk.w;
            s = warp_sum(s);
            if (lane == 0) Sx[m][t + jj] = s;
            tmax = fmaxf(tmax, s);
        }
        __syncthreads();
    }
    __syncwarp();

    float lsum = 0.f;
    for (int jj = lane; jj < SSZ; jj += 32) {
        const float p = __expf(Sx[m][jj] - tmax);
        Sx[m][jj] = p;
        lsum += p;
    }
    lsum = warp_sum(lsum);
    __syncwarp();

    float rk[4] = {0.f, 0.f, 0.f, 0.f};
    float rv[4] = {0.f, 0.f, 0.f, 0.f};
    for (int t = 0; t < SSZ; t += TSK) {
        {
            const int j = tid >> 2, d0 = (tid & 3) * 32;
            const int node = pi[t + j];
            const float* kp = &g_K[(size_t)node * HD + h * DD + d0];
            const float* vp = &g_V[(size_t)node * HD + h * DD + d0];
#pragma unroll
            for (int c = 0; c < 8; c++) {
                *(float4*)&Ksm[j][d0 + 4 * c] = *(const float4*)(kp + 4 * c);
                *(float4*)&Vsm[j][d0 + 4 * c] = *(const float4*)(vp + 4 * c);
            }
        }
        __syncthreads();
#pragma unroll
        for (int jj = 0; jj < TSK; jj++) {
            const float p = Sx[m][t + jj];
            float4 kk = *(float4*)&Ksm[jj][lane * 4];
            float4 vv = *(float4*)&Vsm[jj][lane * 4];
            rk[0] += p * kk.x; rk[1] += p * kk.y; rk[2] += p * kk.z; rk[3] += p * kk.w;
            rv[0] += p * vv.x; rv[1] += p * vv.y; rv[2] += p * vv.z; rv[3] += p * vv.w;
        }
        __syncthreads();
    }

    const float inv = 1.f / lsum;
    const int r = kpart * MM + m;
    float4 ok, ov;
    ok.x = rk[0] * inv; ok.y = rk[1] * inv; ok.z = rk[2] * inv; ok.w = rk[3] * inv;
    ov.x = rv[0] * inv; ov.y = rv[1] * inv; ov.z = rv[2] * inv; ov.w = rv[3] * inv;
    *(float4*)&g_repK[(size_t)r * HD + h * DD + lane * 4] = ok;
    *(float4*)&g_repV[(size_t)r * HD + h * DD + lane * 4] = ov;
}

// ---------------------------------------------------------------------------
// Kernel 5: combine
// ---------------------------------------------------------------------------
__global__ __launch_bounds__(256) void combine(const float* __restrict__ alpha_logit,
                                               const float* __restrict__ beta_p,
                                               float* __restrict__ out)
{
    const int idx = blockIdx.x * blockDim.x + threadIdx.x;
    const int n  = idx / (DD / 4);
    const int d4 = (idx % (DD / 4)) * 4;

    const float alpha = 1.f / (1.f + __expf(-alpha_logit[0]));
    const float beta  = beta_p[0];
    const float ca = alpha * 0.25f;
    const float cg = (1.f - alpha) * 0.25f;
    const float cb = beta * 0.25f;

    float sl0 = 0, sl1 = 0, sl2 = 0, sl3 = 0;
    float sg0 = 0, sg1 = 0, sg2 = 0, sg3 = 0;
    float sv0 = 0, sv1 = 0, sv2 = 0, sv3 = 0;
#pragma unroll
    for (int h = 0; h < HH; h++) {
        const size_t base = (size_t)n * HD + h * DD + d4;
        float4 a = *(const float4*)&g_outL[base];
        float4 b = *(const float4*)&g_outG[base];
        float4 c = *(const float4*)&g_V[base];
        sl0 += a.x; sl1 += a.y; sl2 += a.z; sl3 += a.w;
        sg0 += b.x; sg1 += b.y; sg2 += b.z; sg3 += b.w;
        sv0 += c.x; sv1 += c.y; sv2 += c.z; sv3 += c.w;
    }
    float4 o;
    o.x = ca * sl0 + cg * sg0 + cb * sv0;
    o.y = ca * sl1 + cg * sg1 + cb * sv1;
    o.z = ca * sl2 + cg * sg2 + cb * sv2;
    o.w = ca * sl3 + cg * sg3 + cb * sv3;
    *(float4*)&out[(size_t)n * DD + d4] = o;
}

// ---------------------------------------------------------------------------
// Launcher
// ---------------------------------------------------------------------------
extern "C" void kernel_launch(void* const* d_in, const int* in_sizes, int n_in,
                              void* d_out, int out_size)
{
    (void)in_sizes; (void)n_in; (void)out_size;
    const float* x     = (const float*)d_in[0];
    const int*   pidx  = (const int*)  d_in[1];
    const float* Wq    = (const float*)d_in[2];
    const float* bq    = (const float*)d_in[3];
    const float* Wk    = (const float*)d_in[4];
    const float* bk    = (const float*)d_in[5];
    const float* Wv    = (const float*)d_in[6];
    const float* bv    = (const float*)d_in[7];
    const float* seeds = (const float*)d_in[8];
    const float* alog  = (const float*)d_in[9];
    const float* beta  = (const float*)d_in[10];
    float* out = (float*)d_out;

    // idempotent host-state calls; capture-legal
    cudaFuncSetAttribute((const void*)qkv_gemm_tc,
                         cudaFuncAttributeMaxDynamicSharedMemorySize, GEMM_SMEM_BYTES);
    cudaFuncSetAttribute((const void*)attn_tc<SSZ, true>,
                         cudaFuncAttributeMaxDynamicSharedMemorySize, ATTN_SMEM_BYTES);
    cudaFuncSetAttribute((const void*)attn_tc<RR, false>,
                         cudaFuncAttributeMaxDynamicSharedMemorySize, ATTN_SMEM_BYTES);

    dim3 g1(HD / 128, NN / 128, 3);            // 4 x 256 x 3
    qkv_gemm_tc<<<g1, 256, GEMM_SMEM_BYTES>>>(x, Wq, bq, Wk, bk, Wv, bv);

    dim3 g2(KPP, HH, SSZ / 128);               // fine: 128 x 4 x 2
    attn_tc<SSZ, true><<<g2, 256, ATTN_SMEM_BYTES>>>(pidx);

    dim3 g3(KPP, HH);                          // coarse pooling
    coarse_pool<<<g3, 128>>>(pidx, seeds);

    dim3 g4(NN / 128, HH);                     // global: 256 x 4
    attn_tc<RR, false><<<g4, 256, ATTN_SMEM_BYTES>>>(nullptr);

    combine<<<(NN * DD / 4) / 256, 256>>>(alog, beta, out);
}

// round 7
// speedup vs baseline: 7.5028x; 1.4157x over previous
#include <cuda_runtime.h>
#include <cuda_bf16.h>
#include <math.h>
#include <stdint.h>

// ---------------------------------------------------------------------------
// Problem constants
// ---------------------------------------------------------------------------
#define NN   32768
#define IN_C 256
#define DD   128
#define HH   4
#define HD   512
#define MM   4
#define KPP  128
#define SSZ  256
#define RR   (KPP*MM)
#define INV_SCALE 0.088388347648318447f   // 1/sqrt(128)

// ---------------------------------------------------------------------------
// Scratch (static device globals; no allocation allowed)
// ---------------------------------------------------------------------------
__device__ float g_Q[(size_t)NN*HD];
__device__ float g_K[(size_t)NN*HD];
__device__ float g_V[(size_t)NN*HD];
__device__ float g_outL[(size_t)NN*HD];
__device__ float g_outG[(size_t)NN*HD];
__device__ float g_repK[(size_t)RR*HD];
__device__ float g_repV[(size_t)RR*HD];

// packed bf16x2 hi/lo splits (precomputed each invocation)
__device__ uint32_t g_xh[(size_t)NN*(IN_C/2)];   // [m][kp]
__device__ uint32_t g_xl[(size_t)NN*(IN_C/2)];
__device__ uint32_t g_Wh[3][(IN_C/2)*HD];        // [kp][n]
__device__ uint32_t g_Wl[3][(IN_C/2)*HD];

// ---------------------------------------------------------------------------
// bf16 helpers
// ---------------------------------------------------------------------------
__device__ __forceinline__ float bfr(float v) {            // round f32 -> bf16 -> f32
    return __bfloat162float(__float2bfloat16(v));
}
__device__ __forceinline__ uint32_t bf2(float lo, float hi) {  // pack {lo,hi}
    uint32_t r;
    asm("cvt.rn.bf16x2.f32 %0, %1, %2;" : "=r"(r) : "f"(hi), "f"(lo));
    return r;
}
__device__ __forceinline__ void mma_bf16(float4& d, const uint32_t a[4],
                                         uint32_t b0, uint32_t b1) {
    asm volatile(
        "mma.sync.aligned.m16n8k16.row.col.f32.bf16.bf16.f32 "
        "{%0,%1,%2,%3}, {%4,%5,%6,%7}, {%8,%9}, {%0,%1,%2,%3};"
        : "+f"(d.x), "+f"(d.y), "+f"(d.z), "+f"(d.w)
        : "r"(a[0]), "r"(a[1]), "r"(a[2]), "r"(a[3]), "r"(b0), "r"(b1));
}

// ---------------------------------------------------------------------------
// Precompute: hi/lo bf16x2 splits of x and the three W matrices
// ---------------------------------------------------------------------------
__global__ __launch_bounds__(256) void split_x(const float* __restrict__ x)
{
    const int idx = blockIdx.x * 256 + threadIdx.x;      // over NN*128
    const int m = idx >> 7, kp = idx & 127;
    const float2 v = *(const float2*)&x[(size_t)m * IN_C + 2 * kp];
    const float h0 = bfr(v.x), h1 = bfr(v.y);
    g_xh[idx] = bf2(v.x, v.y);
    g_xl[idx] = bf2(v.x - h0, v.y - h1);
}

__global__ __launch_bounds__(256) void split_w(
    const float* __restrict__ Wq, const float* __restrict__ Wk,
    const float* __restrict__ Wv)
{
    const float* W = (blockIdx.y == 0) ? Wq : (blockIdx.y == 1) ? Wk : Wv;
    const int idx = blockIdx.x * 256 + threadIdx.x;      // over 128*512
    const int kp = idx >> 9, n = idx & 511;
    const float v0 = W[(size_t)(2 * kp) * HD + n];
    const float v1 = W[(size_t)(2 * kp + 1) * HD + n];
    const float h0 = bfr(v0), h1 = bfr(v1);
    g_Wh[blockIdx.y][idx] = bf2(v0, v1);
    g_Wl[blockIdx.y][idx] = bf2(v0 - h0, v1 - h1);
}

// ---------------------------------------------------------------------------
// Kernel 1: QKV GEMM, bf16 split (hi*hi + hi*lo + lo*hi), m16n8k16.
// Block 128x128, k-tile 32 (16 kpairs), 8 warps (4M x 2N).
// Smem u32: Ah/Al [16 kp][136 m], Bh/Bl [16 kp][136 n] — conflict-free frags.
// ---------------------------------------------------------------------------
#define GEMM_SMEM_BYTES (4 * 16 * 136 * 4)

__global__ __launch_bounds__(256) void qkv_gemm_tc(
    const float* __restrict__ bq, const float* __restrict__ bk,
    const float* __restrict__ bv)
{
    const uint32_t* WH = g_Wh[blockIdx.z];
    const uint32_t* WL = g_Wl[blockIdx.z];
    const float* bias; float* C;
    if (blockIdx.z == 0)      { bias = bq; C = g_Q; }
    else if (blockIdx.z == 1) { bias = bk; C = g_K; }
    else                      { bias = bv; C = g_V; }

    extern __shared__ uint32_t smg[];
    uint32_t* Ah = smg;                 // [16][136]
    uint32_t* Al = Ah + 16 * 136;
    uint32_t* Bh = Al + 16 * 136;
    uint32_t* Bl = Bh + 16 * 136;

    const int tid  = threadIdx.x;
    const int warp = tid >> 5, lane = tid & 31;
    const int lr = lane >> 2, lc = lane & 3;
    const int wm = warp & 3, wn = warp >> 2;
    const int row0 = blockIdx.y * 128;
    const int col0 = blockIdx.x * 128;

    float4 acc[2][8];
#pragma unroll
    for (int mi = 0; mi < 2; mi++)
#pragma unroll
        for (int ni = 0; ni < 8; ni++)
            acc[mi][ni] = make_float4(0.f, 0.f, 0.f, 0.f);

    for (int it = 0; it < 8; it++) {            // 8 x (k=32) = 256
        const int kp0 = it * 16;
        __syncthreads();
        {   // stage A (transpose [m][kp] -> [kp][m])
            const int r = tid >> 1, half = tid & 1;
            const size_t src = (size_t)(row0 + r) * 128 + kp0 + half * 8;
            uint4 h0 = *(const uint4*)&g_xh[src];
            uint4 h1 = *(const uint4*)&g_xh[src + 4];
            uint4 l0 = *(const uint4*)&g_xl[src];
            uint4 l1 = *(const uint4*)&g_xl[src + 4];
            const int c = half * 8;
            Ah[(c+0)*136+r] = h0.x; Ah[(c+1)*136+r] = h0.y;
            Ah[(c+2)*136+r] = h0.z; Ah[(c+3)*136+r] = h0.w;
            Ah[(c+4)*136+r] = h1.x; Ah[(c+5)*136+r] = h1.y;
            Ah[(c+6)*136+r] = h1.z; Ah[(c+7)*136+r] = h1.w;
            Al[(c+0)*136+r] = l0.x; Al[(c+1)*136+r] = l0.y;
            Al[(c+2)*136+r] = l0.z; Al[(c+3)*136+r] = l0.w;
            Al[(c+4)*136+r] = l1.x; Al[(c+5)*136+r] = l1.y;
            Al[(c+6)*136+r] = l1.z; Al[(c+7)*136+r] = l1.w;
        }
        {   // stage B ([kp][n] direct)
#pragma unroll
            for (int j = 0; j < 2; j++) {
                const int p = tid * 2 + j;
                const int kpr = p >> 5, c4 = (p & 31) * 4;
                const size_t src = (size_t)(kp0 + kpr) * HD + col0 + c4;
                *(uint4*)&Bh[kpr * 136 + c4] = *(const uint4*)&WH[src];
                *(uint4*)&Bl[kpr * 136 + c4] = *(const uint4*)&WL[src];
            }
        }
        __syncthreads();

#pragma unroll
        for (int kf = 0; kf < 2; kf++) {
            const int r0 = (kf * 8 + lc) * 136;
            const int r1 = (kf * 8 + lc + 4) * 136;
            uint32_t ah[2][4], al[2][4];
#pragma unroll
            for (int mi = 0; mi < 2; mi++) {
                const int m0 = wm * 32 + mi * 16 + lr;
                ah[mi][0] = Ah[r0 + m0]; ah[mi][1] = Ah[r0 + m0 + 8];
                ah[mi][2] = Ah[r1 + m0]; ah[mi][3] = Ah[r1 + m0 + 8];
                al[mi][0] = Al[r0 + m0]; al[mi][1] = Al[r0 + m0 + 8];
                al[mi][2] = Al[r1 + m0]; al[mi][3] = Al[r1 + m0 + 8];
            }
#pragma unroll
            for (int ni = 0; ni < 8; ni++) {
                const int n0 = wn * 64 + ni * 8 + lr;
                const uint32_t bh0 = Bh[r0 + n0], bh1 = Bh[r1 + n0];
                const uint32_t bl0 = Bl[r0 + n0], bl1 = Bl[r1 + n0];
#pragma unroll
                for (int mi = 0; mi < 2; mi++) {
                    mma_bf16(acc[mi][ni], ah[mi], bh0, bh1);
                    mma_bf16(acc[mi][ni], ah[mi], bl0, bl1);
                    mma_bf16(acc[mi][ni], al[mi], bh0, bh1);
                }
            }
        }
    }

#pragma unroll
    for (int mi = 0; mi < 2; mi++) {
        const int r = row0 + wm * 32 + mi * 16 + lr;
#pragma unroll
        for (int ni = 0; ni < 8; ni++) {
            const int c = col0 + wn * 64 + ni * 8 + 2 * lc;
            const float2 b2 = *(const float2*)&bias[c];
            *(float2*)&C[(size_t)r * HD + c] =
                make_float2(acc[mi][ni].x + b2.x, acc[mi][ni].y + b2.y);
            *(float2*)&C[(size_t)(r + 8) * HD + c] =
                make_float2(acc[mi][ni].z + b2.x, acc[mi][ni].w + b2.y);
        }
    }
}

// ---------------------------------------------------------------------------
// Flash attention, bf16 m16n8k16. 256 thr / 8 warps; 128 q rows; key tile 64.
// Smem u32 (conflict-free frag strides):
//   Kp [64 dpair][72]   (pairs along d;   b-frag banks: 8*lc + lr)
//   Vp [32 kpair][136]  (pairs along key; b-frag banks: 8*lc + lr)
//   Pp [128 q   ][36]   (pairs along key; a-frag banks: 4*lr + lc)
// ---------------------------------------------------------------------------
#define ATTN_SMEM_BYTES ((64*72 + 32*136 + 128*36) * 4)

template<int LKEYS, bool GATHER>
__global__ __launch_bounds__(256) void attn_tc(const int* __restrict__ pidx)
{
    extern __shared__ uint32_t smu[];
    uint32_t* Kp = smu;                   // [64][72]
    uint32_t* Vp = Kp + 64 * 72;          // [32][136]
    uint32_t* Pp = Vp + 32 * 136;         // [128][36]

    const int tid = threadIdx.x, warp = tid >> 5, lane = tid & 31;
    const int lr = lane >> 2, lc = lane & 3;
    const int h = blockIdx.y;

    const float* Kg = GATHER ? g_K    : g_repK;
    const float* Vg = GATHER ? g_V    : g_repV;
    float*       Og = GATHER ? g_outL : g_outG;
    const int*   pi = GATHER ? (pidx + blockIdx.x * SSZ) : (const int*)0;
    const int    q0 = GATHER ? (int)blockIdx.z * 128 : (int)blockIdx.x * 128;

    const int wq = warp * 16;
    const int n0g = GATHER ? pi[q0 + wq + lr]     : q0 + wq + lr;
    const int n1g = GATHER ? pi[q0 + wq + lr + 8] : q0 + wq + lr + 8;

    // Q a-frags: 8 k16-frags x 4 regs (packed bf16x2, pre-scaled)
    uint32_t qa[8][4];
    {
        const float* q0p = g_Q + (size_t)n0g * HD + h * DD;
        const float* q1p = g_Q + (size_t)n1g * HD + h * DD;
#pragma unroll
        for (int kf = 0; kf < 8; kf++) {
            float2 a = *(const float2*)&q0p[kf * 16 + 2 * lc];
            float2 b = *(const float2*)&q1p[kf * 16 + 2 * lc];
            float2 c = *(const float2*)&q0p[kf * 16 + 8 + 2 * lc];
            float2 d = *(const float2*)&q1p[kf * 16 + 8 + 2 * lc];
            qa[kf][0] = bf2(a.x * INV_SCALE, a.y * INV_SCALE);
            qa[kf][1] = bf2(b.x * INV_SCALE, b.y * INV_SCALE);
            qa[kf][2] = bf2(c.x * INV_SCALE, c.y * INV_SCALE);
            qa[kf][3] = bf2(d.x * INV_SCALE, d.y * INV_SCALE);
        }
    }

    float4 acc[16];
#pragma unroll
    for (int ni = 0; ni < 16; ni++) acc[ni] = make_float4(0.f, 0.f, 0.f, 0.f);
    float m0 = -INFINITY, m1 = -INFINITY, l0 = 0.f, l1 = 0.f;

    for (int t = 0; t < LKEYS; t += 64) {
        __syncthreads();
        {   // ---- stage K: pairs along d. thread: key = tid&63, d0 = (tid>>6)*32
            const int key = tid & 63;
            const int d0  = (tid >> 6) * 32;
            const int kn  = GATHER ? pi[t + key] : t + key;
            const float* kp = Kg + (size_t)kn * HD + h * DD + d0;
#pragma unroll
            for (int c = 0; c < 8; c++) {
                float4 kv = *(const float4*)(kp + 4 * c);
                Kp[((d0 >> 1) + 2 * c + 0) * 72 + key] = bf2(kv.x, kv.y);
                Kp[((d0 >> 1) + 2 * c + 1) * 72 + key] = bf2(kv.z, kv.w);
            }
        }
        {   // ---- stage V: pairs along key. thread: kp = tid>>3, d0 = (tid&7)*16
            const int kpi = tid >> 3;
            const int d0  = (tid & 7) * 16;
            const int ka  = GATHER ? pi[t + 2 * kpi]     : t + 2 * kpi;
            const int kb  = GATHER ? pi[t + 2 * kpi + 1] : t + 2 * kpi + 1;
            const float* va = Vg + (size_t)ka * HD + h * DD + d0;
            const float* vb = Vg + (size_t)kb * HD + h * DD + d0;
#pragma unroll
            for (int c = 0; c < 4; c++) {
                float4 x = *(const float4*)(va + 4 * c);
                float4 y = *(const float4*)(vb + 4 * c);
                uint32_t* dst = Vp + kpi * 136 + d0 + 4 * c;
                dst[0] = bf2(x.x, y.x); dst[1] = bf2(x.y, y.y);
                dst[2] = bf2(x.z, y.z); dst[3] = bf2(x.w, y.w);
            }
        }
        __syncthreads();

        // ---- S = Q K^T : 8 kf x 8 ni ----
        float4 s[8];
#pragma unroll
        for (int ni = 0; ni < 8; ni++) s[ni] = make_float4(0.f, 0.f, 0.f, 0.f);
#pragma unroll
        for (int kf = 0; kf < 8; kf++) {
            const uint32_t* kr0 = Kp + (kf * 8 + lc) * 72;
            const uint32_t* kr1 = Kp + (kf * 8 + lc + 4) * 72;
#pragma unroll
            for (int ni = 0; ni < 8; ni++)
                mma_bf16(s[ni], qa[kf], kr0[ni * 8 + lr], kr1[ni * 8 + lr]);
        }

        // ---- online softmax (rows lr -> x,y ; lr+8 -> z,w) ----
        float tm0 = -INFINITY, tm1 = -INFINITY;
#pragma unroll
        for (int ni = 0; ni < 8; ni++) {
            tm0 = fmaxf(tm0, fmaxf(s[ni].x, s[ni].y));
            tm1 = fmaxf(tm1, fmaxf(s[ni].z, s[ni].w));
        }
        tm0 = fmaxf(tm0, __shfl_xor_sync(0xffffffffu, tm0, 1));
        tm0 = fmaxf(tm0, __shfl_xor_sync(0xffffffffu, tm0, 2));
        tm1 = fmaxf(tm1, __shfl_xor_sync(0xffffffffu, tm1, 1));
        tm1 = fmaxf(tm1, __shfl_xor_sync(0xffffffffu, tm1, 2));

        const float mn0 = fmaxf(m0, tm0), mn1 = fmaxf(m1, tm1);
        const float corr0 = __expf(m0 - mn0), corr1 = __expf(m1 - mn1);
        m0 = mn0; m1 = mn1;

        float rs0 = 0.f, rs1 = 0.f;
        uint32_t* pw0 = Pp + (wq + lr) * 36;
        uint32_t* pw1 = Pp + (wq + lr + 8) * 36;
#pragma unroll
        for (int ni = 0; ni < 8; ni++) {
            const float p0 = __expf(s[ni].x - mn0);
            const float p1 = __expf(s[ni].y - mn0);
            const float p2 = __expf(s[ni].z - mn1);
            const float p3 = __expf(s[ni].w - mn1);
            rs0 += p0 + p1; rs1 += p2 + p3;
            pw0[ni * 4 + lc] = bf2(p0, p1);
            pw1[ni * 4 + lc] = bf2(p2, p3);
        }
        rs0 += __shfl_xor_sync(0xffffffffu, rs0, 1);
        rs0 += __shfl_xor_sync(0xffffffffu, rs0, 2);
        rs1 += __shfl_xor_sync(0xffffffffu, rs1, 1);
        rs1 += __shfl_xor_sync(0xffffffffu, rs1, 2);
        l0 = l0 * corr0 + rs0;
        l1 = l1 * corr1 + rs1;
#pragma unroll
        for (int ni = 0; ni < 16; ni++) {
            acc[ni].x *= corr0; acc[ni].y *= corr0;
            acc[ni].z *= corr1; acc[ni].w *= corr1;
        }
        __syncwarp();

        // ---- O += P V : 4 kf (k16 keys) x 16 ni (d) ----
#pragma unroll
        for (int kf = 0; kf < 4; kf++) {
            uint32_t pa[4];
            pa[0] = Pp[(wq + lr)     * 36 + kf * 8 + lc];
            pa[1] = Pp[(wq + lr + 8) * 36 + kf * 8 + lc];
            pa[2] = Pp[(wq + lr)     * 36 + kf * 8 + lc + 4];
            pa[3] = Pp[(wq + lr + 8) * 36 + kf * 8 + lc + 4];
            const uint32_t* vr0 = Vp + (kf * 8 + lc) * 136;
            const uint32_t* vr1 = Vp + (kf * 8 + lc + 4) * 136;
#pragma unroll
            for (int ni = 0; ni < 16; ni++)
                mma_bf16(acc[ni], pa, vr0[ni * 8 + lr], vr1[ni * 8 + lr]);
        }
    }

    // ---- normalize + write ----
    const float inv0 = 1.f / l0, inv1 = 1.f / l1;
    float* o0 = Og + (size_t)n0g * HD + h * DD;
    float* o1 = Og + (size_t)n1g * HD + h * DD;
#pragma unroll
    for (int ni = 0; ni < 16; ni++) {
        const int col = ni * 8 + 2 * lc;
        *(float2*)&o0[col] = make_float2(acc[ni].x * inv0, acc[ni].y * inv0);
        *(float2*)&o1[col] = make_float2(acc[ni].z * inv1, acc[ni].w * inv1);
    }
}

// ---------------------------------------------------------------------------
// Kernel 3: coarse pooling (unchanged — small)
// ---------------------------------------------------------------------------
#define TSK 32

__device__ __forceinline__ float warp_sum(float s) {
    s += __shfl_xor_sync(0xffffffffu, s, 16);
    s += __shfl_xor_sync(0xffffffffu, s, 8);
    s += __shfl_xor_sync(0xffffffffu, s, 4);
    s += __shfl_xor_sync(0xffffffffu, s, 2);
    s += __shfl_xor_sync(0xffffffffu, s, 1);
    return s;
}

__global__ __launch_bounds__(128) void coarse_pool(const int* __restrict__ pidx,
                                                   const float* __restrict__ seeds)
{
    const int kpart = blockIdx.x;
    const int h     = blockIdx.y;
    const int tid = threadIdx.x, m = tid >> 5, lane = tid & 31;

    __shared__ float Ksm[TSK][DD];
    __shared__ float Vsm[TSK][DD];
    __shared__ float Sx[MM][SSZ];

    const int* pi = pidx + kpart * SSZ;

    float4 sq = *(const float4*)&seeds[(size_t)m * HD + h * DD + lane * 4];
    const float q0 = sq.x * INV_SCALE, q1 = sq.y * INV_SCALE;
    const float q2 = sq.z * INV_SCALE, q3 = sq.w * INV_SCALE;

    float tmax = -INFINITY;
    for (int t = 0; t < SSZ; t += TSK) {
        {
            const int j = tid >> 2, d0 = (tid & 3) * 32;
            const int node = pi[t + j];
            const float* kp = &g_K[(size_t)node * HD + h * DD + d0];
#pragma unroll
            for (int c = 0; c < 8; c++)
                *(float4*)&Ksm[j][d0 + 4 * c] = *(const float4*)(kp + 4 * c);
        }
        __syncthreads();
#pragma unroll
        for (int jj = 0; jj < TSK; jj++) {
            float4 kk = *(float4*)&Ksm[jj][lane * 4];
            float s = q0 * kk.x + q1 * kk.y + q2 * kk.z + q3 * kk.w;
            s = warp_sum(s);
            if (lane == 0) Sx[m][t + jj] = s;
            tmax = fmaxf(tmax, s);
        }
        __syncthreads();
    }
    __syncwarp();

    float lsum = 0.f;
    for (int jj = lane; jj < SSZ; jj += 32) {
        const float p = __expf(Sx[m][jj] - tmax);
        Sx[m][jj] = p;
        lsum += p;
    }
    lsum = warp_sum(lsum);
    __syncwarp();

    float rk[4] = {0.f, 0.f, 0.f, 0.f};
    float rv[4] = {0.f, 0.f, 0.f, 0.f};
    for (int t = 0; t < SSZ; t += TSK) {
        {
            const int j = tid >> 2, d0 = (tid & 3) * 32;
            const int node = pi[t + j];
            const float* kp = &g_K[(size_t)node * HD + h * DD + d0];
            const float* vp = &g_V[(size_t)node * HD + h * DD + d0];
#pragma unroll
            for (int c = 0; c < 8; c++) {
                *(float4*)&Ksm[j][d0 + 4 * c] = *(const float4*)(kp + 4 * c);
                *(float4*)&Vsm[j][d0 + 4 * c] = *(const float4*)(vp + 4 * c);
            }
        }
        __syncthreads();
#pragma unroll
        for (int jj = 0; jj < TSK; jj++) {
            const float p = Sx[m][t + jj];
            float4 kk = *(float4*)&Ksm[jj][lane * 4];
            float4 vv = *(float4*)&Vsm[jj][lane * 4];
            rk[0] += p * kk.x; rk[1] += p * kk.y; rk[2] += p * kk.z; rk[3] += p * kk.w;
            rv[0] += p * vv.x; rv[1] += p * vv.y; rv[2] += p * vv.z; rv[3] += p * vv.w;
        }
        __syncthreads();
    }

    const float inv = 1.f / lsum;
    const int r = kpart * MM + m;
    float4 ok, ov;
    ok.x = rk[0] * inv; ok.y = rk[1] * inv; ok.z = rk[2] * inv; ok.w = rk[3] * inv;
    ov.x = rv[0] * inv; ov.y = rv[1] * inv; ov.z = rv[2] * inv; ov.w = rv[3] * inv;
    *(float4*)&g_repK[(size_t)r * HD + h * DD + lane * 4] = ok;
    *(float4*)&g_repV[(size_t)r * HD + h * DD + lane * 4] = ov;
}

// ---------------------------------------------------------------------------
// Kernel 5: combine
// ---------------------------------------------------------------------------
__global__ __launch_bounds__(256) void combine(const float* __restrict__ alpha_logit,
                                               const float* __restrict__ beta_p,
                                               float* __restrict__ out)
{
    const int idx = blockIdx.x * blockDim.x + threadIdx.x;
    const int n  = idx / (DD / 4);
    const int d4 = (idx % (DD / 4)) * 4;

    const float alpha = 1.f / (1.f + __expf(-alpha_logit[0]));
    const float beta  = beta_p[0];
    const float ca = alpha * 0.25f;
    const float cg = (1.f - alpha) * 0.25f;
    const float cb = beta * 0.25f;

    float sl0 = 0, sl1 = 0, sl2 = 0, sl3 = 0;
    float sg0 = 0, sg1 = 0, sg2 = 0, sg3 = 0;
    float sv0 = 0, sv1 = 0, sv2 = 0, sv3 = 0;
#pragma unroll
    for (int h = 0; h < HH; h++) {
        const size_t base = (size_t)n * HD + h * DD + d4;
        float4 a = *(const float4*)&g_outL[base];
        float4 b = *(const float4*)&g_outG[base];
        float4 c = *(const float4*)&g_V[base];
        sl0 += a.x; sl1 += a.y; sl2 += a.z; sl3 += a.w;
        sg0 += b.x; sg1 += b.y; sg2 += b.z; sg3 += b.w;
        sv0 += c.x; sv1 += c.y; sv2 += c.z; sv3 += c.w;
    }
    float4 o;
    o.x = ca * sl0 + cg * sg0 + cb * sv0;
    o.y = ca * sl1 + cg * sg1 + cb * sv1;
    o.z = ca * sl2 + cg * sg2 + cb * sv2;
    o.w = ca * sl3 + cg * sg3 + cb * sv3;
    *(float4*)&out[(size_t)n * DD + d4] = o;
}

// ---------------------------------------------------------------------------
// Launcher
// ---------------------------------------------------------------------------
extern "C" void kernel_launch(void* const* d_in, const int* in_sizes, int n_in,
                              void* d_out, int out_size)
{
    (void)in_sizes; (void)n_in; (void)out_size;
    const float* x     = (const float*)d_in[0];
    const int*   pidx  = (const int*)  d_in[1];
    const float* Wq    = (const float*)d_in[2];
    const float* bq    = (const float*)d_in[3];
    const float* Wk    = (const float*)d_in[4];
    const float* bk    = (const float*)d_in[5];
    const float* Wv    = (const float*)d_in[6];
    const float* bv    = (const float*)d_in[7];
    const float* seeds = (const float*)d_in[8];
    const float* alog  = (const float*)d_in[9];
    const float* beta  = (const float*)d_in[10];
    float* out = (float*)d_out;

    // idempotent host-state calls; capture-legal
    cudaFuncSetAttribute((const void*)qkv_gemm_tc,
                         cudaFuncAttributeMaxDynamicSharedMemorySize, GEMM_SMEM_BYTES);
    cudaFuncSetAttribute((const void*)attn_tc<SSZ, true>,
                         cudaFuncAttributeMaxDynamicSharedMemorySize, ATTN_SMEM_BYTES);
    cudaFuncSetAttribute((const void*)attn_tc<RR, false>,
                         cudaFuncAttributeMaxDynamicSharedMemorySize, ATTN_SMEM_BYTES);

    split_x<<<NN * 128 / 256, 256>>>(x);
    dim3 gw(128 * HD / 256, 3);
    split_w<<<gw, 256>>>(Wq, Wk, Wv);

    dim3 g1(HD / 128, NN / 128, 3);            // 4 x 256 x 3
    qkv_gemm_tc<<<g1, 256, GEMM_SMEM_BYTES>>>(bq, bk, bv);

    dim3 g2(KPP, HH, SSZ / 128);               // fine: 128 x 4 x 2
    attn_tc<SSZ, true><<<g2, 256, ATTN_SMEM_BYTES>>>(pidx);

    dim3 g3(KPP, HH);                          // coarse pooling
    coarse_pool<<<g3, 128>>>(pidx, seeds);

    dim3 g4(NN / 128, HH);                     // global: 256 x 4
    attn_tc<RR, false><<<g4, 256, ATTN_SMEM_BYTES>>>(nullptr);

    combine<<<(NN * DD / 4) / 256, 256>>>(alog, beta, out);
}

// round 8
// speedup vs baseline: 11.7210x; 1.5622x over previous
#include <cuda_runtime.h>
#include <cuda_bf16.h>
#include <math.h>
#include <stdint.h>

// ---------------------------------------------------------------------------
// Problem constants
// ---------------------------------------------------------------------------
#define NN   32768
#define IN_C 256
#define DD   128
#define HH   4
#define HD   512
#define MM   4
#define KPP  128
#define SSZ  256
#define RR   (KPP*MM)
#define INV_SCALE 0.088388347648318447f   // 1/sqrt(128)

// ---------------------------------------------------------------------------
// Scratch (static device globals; no allocation allowed)
// ---------------------------------------------------------------------------
__device__ float    g_V[(size_t)NN*HD];          // fp32 V (combine)
__device__ float    g_outL[(size_t)NN*HD];
__device__ float    g_outG[(size_t)NN*HD];
__device__ uint32_t g_Qb[(size_t)NN*256];        // packed bf16x2, pre-scaled
__device__ uint32_t g_Kb[(size_t)NN*256];
__device__ uint32_t g_Vb[(size_t)NN*256];
__device__ uint32_t g_repKb[(size_t)RR*256];
__device__ uint32_t g_repVb[(size_t)RR*256];
// GEMM operands: hi/lo bf16x2 splits
__device__ uint32_t g_xh_t[(size_t)128*NN];      // [kp][m] (transposed)
__device__ uint32_t g_xl_t[(size_t)128*NN];
__device__ uint32_t g_Wh[3][(IN_C/2)*HD];        // [kp][n]
__device__ uint32_t g_Wl[3][(IN_C/2)*HD];

// ---------------------------------------------------------------------------
// helpers
// ---------------------------------------------------------------------------
__device__ __forceinline__ float bfr(float v) {
    return __bfloat162float(__float2bfloat16(v));
}
__device__ __forceinline__ uint32_t bf2(float lo, float hi) {
    uint32_t r;
    asm("cvt.rn.bf16x2.f32 %0, %1, %2;" : "=r"(r) : "f"(hi), "f"(lo));
    return r;
}
__device__ __forceinline__ float bflo(uint32_t u) { return __uint_as_float(u << 16); }
__device__ __forceinline__ float bfhi(uint32_t u) { return __uint_as_float(u & 0xffff0000u); }
__device__ __forceinline__ uint32_t prmt(uint32_t a, uint32_t b, uint32_t sel) {
    uint32_t r;
    asm("prmt.b32 %0, %1, %2, %3;" : "=r"(r) : "r"(a), "r"(b), "r"(sel));
    return r;
}
__device__ __forceinline__ void mma_bf16(float4& d, const uint32_t a[4],
                                         uint32_t b0, uint32_t b1) {
    asm volatile(
        "mma.sync.aligned.m16n8k16.row.col.f32.bf16.bf16.f32 "
        "{%0,%1,%2,%3}, {%4,%5,%6,%7}, {%8,%9}, {%0,%1,%2,%3};"
        : "+f"(d.x), "+f"(d.y), "+f"(d.z), "+f"(d.w)
        : "r"(a[0]), "r"(a[1]), "r"(a[2]), "r"(a[3]), "r"(b0), "r"(b1));
}
#define CP_ASYNC16(dst, src) \
    asm volatile("cp.async.cg.shared.global [%0], [%1], 16;" :: "r"(dst), "l"(src))
#define CP_COMMIT() asm volatile("cp.async.commit_group;")
#define CP_WAIT(n)  asm volatile("cp.async.wait_group %0;" :: "n"(n))

__device__ __forceinline__ float warp_max2(float s) {
    s = fmaxf(s, __shfl_xor_sync(0xffffffffu, s, 1));
    s = fmaxf(s, __shfl_xor_sync(0xffffffffu, s, 2));
    return s;
}
__device__ __forceinline__ float warp_sum2(float s) {
    s += __shfl_xor_sync(0xffffffffu, s, 1);
    s += __shfl_xor_sync(0xffffffffu, s, 2);
    return s;
}
__device__ __forceinline__ float warp_max32(float s) {
#pragma unroll
    for (int o = 16; o > 0; o >>= 1) s = fmaxf(s, __shfl_xor_sync(0xffffffffu, s, o));
    return s;
}
__device__ __forceinline__ float warp_sum32(float s) {
#pragma unroll
    for (int o = 16; o > 0; o >>= 1) s += __shfl_xor_sync(0xffffffffu, s, o);
    return s;
}

// ---------------------------------------------------------------------------
// split_xt: x -> transposed hi/lo bf16x2 splits  g_x{h,l}_t [kp][m]
// ---------------------------------------------------------------------------
__global__ __launch_bounds__(256) void split_xt(const float* __restrict__ x)
{
    __shared__ uint32_t Th[32][132];
    __shared__ uint32_t Tl[32][132];
    const int m0 = blockIdx.x * 128;
    const int tid = threadIdx.x;
#pragma unroll
    for (int c = 0; c < 4; c++) {
        const int kpb = c * 32;
        {
            const int m = tid >> 1, half = tid & 1;
            const float* src = x + (size_t)(m0 + m) * IN_C + (kpb + half * 16) * 2;
#pragma unroll
            for (int j = 0; j < 16; j++) {
                float2 v = *(const float2*)(src + 2 * j);
                const float h0 = bfr(v.x), h1 = bfr(v.y);
                Th[half * 16 + j][m] = bf2(v.x, v.y);
                Tl[half * 16 + j][m] = bf2(v.x - h0, v.y - h1);
            }
        }
        __syncthreads();
        {
            const int kpr = tid >> 3, mo = (tid & 7) * 16;
            uint32_t* dh = g_xh_t + (size_t)(kpb + kpr) * NN + m0 + mo;
            uint32_t* dl = g_xl_t + (size_t)(kpb + kpr) * NN + m0 + mo;
#pragma unroll
            for (int j = 0; j < 4; j++) {
                *(uint4*)(dh + 4 * j) = *(uint4*)&Th[kpr][mo + 4 * j];
                *(uint4*)(dl + 4 * j) = *(uint4*)&Tl[kpr][mo + 4 * j];
            }
        }
        __syncthreads();
    }
}

// ---------------------------------------------------------------------------
// split_w: W -> hi/lo bf16x2 splits  g_W{h,l} [kp][n]
// ---------------------------------------------------------------------------
__global__ __launch_bounds__(256) void split_w(
    const float* __restrict__ Wq, const float* __restrict__ Wk,
    const float* __restrict__ Wv)
{
    const float* W = (blockIdx.y == 0) ? Wq : (blockIdx.y == 1) ? Wk : Wv;
    const int idx = blockIdx.x * 256 + threadIdx.x;
    const int kp = idx >> 9, n = idx & 511;
    const float v0 = W[(size_t)(2 * kp) * HD + n];
    const float v1 = W[(size_t)(2 * kp + 1) * HD + n];
    const float h0 = bfr(v0), h1 = bfr(v1);
    g_Wh[blockIdx.y][idx] = bf2(v0, v1);
    g_Wl[blockIdx.y][idx] = bf2(v0 - h0, v1 - h1);
}

// ---------------------------------------------------------------------------
// Kernel 1: QKV GEMM, bf16 split, cp.async double-buffered.
// Epilogue emits packed bf16x2 (Q pre-scaled) + fp32 V.
// ---------------------------------------------------------------------------
#define GSTG 2176                       // 16*136 u32 per array
#define GEMM_SMEM_BYTES (2 * 4 * GSTG * 4)

__global__ __launch_bounds__(256) void qkv_gemm_tc(
    const float* __restrict__ bq, const float* __restrict__ bk,
    const float* __restrict__ bv)
{
    const int z = blockIdx.z;
    const uint32_t* WH = g_Wh[z];
    const uint32_t* WL = g_Wl[z];
    const float* bias = (z == 0) ? bq : (z == 1) ? bk : bv;
    uint32_t* Cb = (z == 0) ? g_Qb : (z == 1) ? g_Kb : g_Vb;

    extern __shared__ uint32_t smg[];

    const int tid  = threadIdx.x;
    const int warp = tid >> 5, lane = tid & 31;
    const int lr = lane >> 2, lc = lane & 3;
    const int wm = warp & 3, wn = warp >> 2;
    const int row0 = blockIdx.y * 128;
    const int col0 = blockIdx.x * 128;

    // cp.async staging of one k-stage (16 kpairs) into buffer b
    auto issue = [&](int it, int b) {
        const int kp0 = it * 16;
        uint32_t* buf = smg + b * 4 * GSTG;
        uint32_t base;
        asm("{ .reg .u64 t; cvta.to.shared.u64 t, %1; cvt.u32.u64 %0, t; }"
            : "=r"(base) : "l"(buf));
#pragma unroll
        for (int j = 0; j < 2; j++) {
            const int slot = tid * 2 + j;
            const int kpr = slot >> 5, f = (slot & 31) * 4;
            const size_t asrc = (size_t)(kp0 + kpr) * NN + row0 + f;
            const size_t bsrc = (size_t)(kp0 + kpr) * HD + col0 + f;
            const uint32_t doff = (kpr * 136 + f) * 4;
            CP_ASYNC16(base + 0 * GSTG * 4 + doff, g_xh_t + asrc);
            CP_ASYNC16(base + 1 * GSTG * 4 + doff, g_xl_t + asrc);
            CP_ASYNC16(base + 2 * GSTG * 4 + doff, WH + bsrc);
            CP_ASYNC16(base + 3 * GSTG * 4 + doff, WL + bsrc);
        }
    };

    float4 acc[2][8];
#pragma unroll
    for (int mi = 0; mi < 2; mi++)
#pragma unroll
        for (int ni = 0; ni < 8; ni++)
            acc[mi][ni] = make_float4(0.f, 0.f, 0.f, 0.f);

    issue(0, 0); CP_COMMIT();

    for (int it = 0; it < 8; it++) {
        if (it < 7) { issue(it + 1, (it + 1) & 1); CP_COMMIT(); CP_WAIT(1); }
        else        { CP_WAIT(0); }
        __syncthreads();

        const uint32_t* buf = smg + (it & 1) * 4 * GSTG;
        const uint32_t* Ah = buf;
        const uint32_t* Al = buf + GSTG;
        const uint32_t* Bh = buf + 2 * GSTG;
        const uint32_t* Bl = buf + 3 * GSTG;

#pragma unroll
        for (int kf = 0; kf < 2; kf++) {
            const int r0 = (kf * 8 + lc) * 136;
            const int r1 = (kf * 8 + lc + 4) * 136;
            uint32_t ah[2][4], al[2][4];
#pragma unroll
            for (int mi = 0; mi < 2; mi++) {
                const int m0 = wm * 32 + mi * 16 + lr;
                ah[mi][0] = Ah[r0 + m0]; ah[mi][1] = Ah[r0 + m0 + 8];
                ah[mi][2] = Ah[r1 + m0]; ah[mi][3] = Ah[r1 + m0 + 8];
                al[mi][0] = Al[r0 + m0]; al[mi][1] = Al[r0 + m0 + 8];
                al[mi][2] = Al[r1 + m0]; al[mi][3] = Al[r1 + m0 + 8];
            }
#pragma unroll
            for (int ni = 0; ni < 8; ni++) {
                const int n0 = wn * 64 + ni * 8 + lr;
                const uint32_t bh0 = Bh[r0 + n0], bh1 = Bh[r1 + n0];
                const uint32_t bl0 = Bl[r0 + n0], bl1 = Bl[r1 + n0];
#pragma unroll
                for (int mi = 0; mi < 2; mi++) {
                    mma_bf16(acc[mi][ni], ah[mi], bh0, bh1);
                    mma_bf16(acc[mi][ni], ah[mi], bl0, bl1);
                    mma_bf16(acc[mi][ni], al[mi], bh0, bh1);
                }
            }
        }
        __syncthreads();
    }

    // epilogue
#pragma unroll
    for (int mi = 0; mi < 2; mi++) {
        const int r = row0 + wm * 32 + mi * 16 + lr;
#pragma unroll
        for (int ni = 0; ni < 8; ni++) {
            const int c = col0 + wn * 64 + ni * 8 + 2 * lc;
            const float2 b2 = *(const float2*)&bias[c];
            float x0 = acc[mi][ni].x + b2.x, y0 = acc[mi][ni].y + b2.y;
            float x1 = acc[mi][ni].z + b2.x, y1 = acc[mi][ni].w + b2.y;
            if (z == 0) { x0 *= INV_SCALE; y0 *= INV_SCALE;
                          x1 *= INV_SCALE; y1 *= INV_SCALE; }
            const int cp = c >> 1;
            Cb[(size_t)r * 256 + cp]       = bf2(x0, y0);
            Cb[(size_t)(r + 8) * 256 + cp] = bf2(x1, y1);
            if (z == 2) {
                *(float2*)&g_V[(size_t)r * HD + c]       = make_float2(x0, y0);
                *(float2*)&g_V[(size_t)(r + 8) * HD + c] = make_float2(x1, y1);
            }
        }
    }
}

// ---------------------------------------------------------------------------
// Kernel 2: fine attention + fused coarse pooling.
// Block = (partition, head); all 256 keys K/V resident in smem.
//   Kr [256 key][76]  packed bf16x2 pairs along d   (b-frag banks 12lr+lc: CF)
//   Vr [128 kpair][136] pairs along key             (b-frag banks 8lc+lr: CF)
//   Pp [128 q][36]                                  (a-frag CF)
// After attention: seeds-pooling on resident tiles -> packed reps.
// ---------------------------------------------------------------------------
#define FINE_SMEM_BYTES ((256*76 + 128*136 + 128*36) * 4)

__global__ __launch_bounds__(256) void fine_attn_pool(
    const int* __restrict__ pidx, const float* __restrict__ seeds)
{
    extern __shared__ uint32_t sf[];
    uint32_t* Kr = sf;                        // [256][76]
    uint32_t* Vr = sf + 256 * 76;             // [128][136]
    uint32_t* Pp = sf + 256 * 76 + 128 * 136; // [128][36]

    const int tid = threadIdx.x, warp = tid >> 5, lane = tid & 31;
    const int lr = lane >> 2, lc = lane & 3;
    const int kpart = blockIdx.x, h = blockIdx.y;
    const int* pi = pidx + kpart * SSZ;

    // ---- stage K (one key per thread, direct packed copy) ----
    {
        const int node = pi[tid];
        const uint32_t* src = g_Kb + (size_t)node * 256 + h * 64;
        uint32_t* dst = Kr + tid * 76;
#pragma unroll
        for (int j = 0; j < 16; j++)
            *(uint4*)(dst + 4 * j) = *(const uint4*)(src + 4 * j);
    }
    // ---- stage V (kpair per thread-pair, PRMT cross-pack) ----
    {
        const int kpi = tid >> 1, dh = (tid & 1) * 32;       // dp offset
        const int ka = pi[2 * kpi], kb = pi[2 * kpi + 1];
        const uint32_t* sa = g_Vb + (size_t)ka * 256 + h * 64 + dh;
        const uint32_t* sb = g_Vb + (size_t)kb * 256 + h * 64 + dh;
        uint32_t* dst = Vr + kpi * 136 + dh * 2;
#pragma unroll
        for (int j = 0; j < 8; j++) {
            uint4 a = *(const uint4*)(sa + 4 * j);
            uint4 b = *(const uint4*)(sb + 4 * j);
            uint4 o0, o1;
            o0.x = prmt(a.x, b.x, 0x5410); o0.y = prmt(a.x, b.x, 0x7632);
            o0.z = prmt(a.y, b.y, 0x5410); o0.w = prmt(a.y, b.y, 0x7632);
            o1.x = prmt(a.z, b.z, 0x5410); o1.y = prmt(a.z, b.z, 0x7632);
            o1.z = prmt(a.w, b.w, 0x5410); o1.w = prmt(a.w, b.w, 0x7632);
            *(uint4*)(dst + 8 * j)     = o0;
            *(uint4*)(dst + 8 * j + 4) = o1;
        }
    }
    __syncthreads();

    const int wq = warp * 16;

    // ---- attention: two q-sets of 128 rows ----
#pragma unroll 1
    for (int set = 0; set < 2; set++) {
        const int qb = set * 128;
        const int n0g = pi[qb + wq + lr];
        const int n1g = pi[qb + wq + lr + 8];

        uint32_t qa[8][4];
        {
            const uint32_t* q0p = g_Qb + (size_t)n0g * 256 + h * 64;
            const uint32_t* q1p = g_Qb + (size_t)n1g * 256 + h * 64;
#pragma unroll
            for (int kf = 0; kf < 8; kf++) {
                qa[kf][0] = q0p[kf * 8 + lc];
                qa[kf][1] = q1p[kf * 8 + lc];
                qa[kf][2] = q0p[kf * 8 + lc + 4];
                qa[kf][3] = q1p[kf * 8 + lc + 4];
            }
        }

        float4 acc[16];
#pragma unroll
        for (int ni = 0; ni < 16; ni++) acc[ni] = make_float4(0.f, 0.f, 0.f, 0.f);
        float m0 = -INFINITY, m1 = -INFINITY, l0 = 0.f, l1 = 0.f;

#pragma unroll 1
        for (int kt = 0; kt < 4; kt++) {
            float4 s[8];
#pragma unroll
            for (int ni = 0; ni < 8; ni++) s[ni] = make_float4(0.f, 0.f, 0.f, 0.f);
#pragma unroll
            for (int kf = 0; kf < 8; kf++) {
#pragma unroll
                for (int ni = 0; ni < 8; ni++) {
                    const uint32_t* kr = Kr + (kt * 64 + ni * 8 + lr) * 76 + kf * 8;
                    mma_bf16(s[ni], qa[kf], kr[lc], kr[lc + 4]);
                }
            }

            float tm0 = -INFINITY, tm1 = -INFINITY;
#pragma unroll
            for (int ni = 0; ni < 8; ni++) {
                tm0 = fmaxf(tm0, fmaxf(s[ni].x, s[ni].y));
                tm1 = fmaxf(tm1, fmaxf(s[ni].z, s[ni].w));
            }
            tm0 = warp_max2(tm0); tm1 = warp_max2(tm1);
            const float mn0 = fmaxf(m0, tm0), mn1 = fmaxf(m1, tm1);
            const float c0 = __expf(m0 - mn0), c1 = __expf(m1 - mn1);
            m0 = mn0; m1 = mn1;

            float rs0 = 0.f, rs1 = 0.f;
            uint32_t* pw0 = Pp + (wq + lr) * 36;
            uint32_t* pw1 = Pp + (wq + lr + 8) * 36;
#pragma unroll
            for (int ni = 0; ni < 8; ni++) {
                const float p0 = __expf(s[ni].x - mn0);
                const float p1 = __expf(s[ni].y - mn0);
                const float p2 = __expf(s[ni].z - mn1);
                const float p3 = __expf(s[ni].w - mn1);
                rs0 += p0 + p1; rs1 += p2 + p3;
                pw0[ni * 4 + lc] = bf2(p0, p1);
                pw1[ni * 4 + lc] = bf2(p2, p3);
            }
            rs0 = warp_sum2(rs0); rs1 = warp_sum2(rs1);
            l0 = l0 * c0 + rs0; l1 = l1 * c1 + rs1;
#pragma unroll
            for (int ni = 0; ni < 16; ni++) {
                acc[ni].x *= c0; acc[ni].y *= c0;
                acc[ni].z *= c1; acc[ni].w *= c1;
            }
            __syncwarp();

#pragma unroll
            for (int kf = 0; kf < 4; kf++) {
                uint32_t pa[4];
                pa[0] = Pp[(wq + lr)     * 36 + kf * 8 + lc];
                pa[1] = Pp[(wq + lr + 8) * 36 + kf * 8 + lc];
                pa[2] = Pp[(wq + lr)     * 36 + kf * 8 + lc + 4];
                pa[3] = Pp[(wq + lr + 8) * 36 + kf * 8 + lc + 4];
                const uint32_t* vr0 = Vr + (kt * 32 + kf * 8 + lc) * 136;
                const uint32_t* vr1 = Vr + (kt * 32 + kf * 8 + lc + 4) * 136;
#pragma unroll
                for (int ni = 0; ni < 16; ni++)
                    mma_bf16(acc[ni], pa, vr0[ni * 8 + lr], vr1[ni * 8 + lr]);
            }
            __syncwarp();
        }

        const float inv0 = 1.f / l0, inv1 = 1.f / l1;
        float* o0 = g_outL + (size_t)n0g * HD + h * DD;
        float* o1 = g_outL + (size_t)n1g * HD + h * DD;
#pragma unroll
        for (int ni = 0; ni < 16; ni++) {
            const int col = ni * 8 + 2 * lc;
            *(float2*)&o0[col] = make_float2(acc[ni].x * inv0, acc[ni].y * inv0);
            *(float2*)&o1[col] = make_float2(acc[ni].z * inv1, acc[ni].w * inv1);
        }
    }

    // ---- fused coarse pooling on resident K/V ----
    __syncthreads();
    float* ps  = (float*)Pp;                 // [4][260]
    float* qsm = ps + 4 * 260;               // [4][128]
    float* lsm = qsm + 4 * 128;              // [4]

    {   // seeds (scaled) -> smem
        const int i0 = tid, i1 = tid + 256;
        {
            const int m = i0 >> 7, d = i0 & 127;
            qsm[i0] = seeds[(size_t)m * HD + h * DD + d] * INV_SCALE;
        }
        {
            const int m = i1 >> 7, d = i1 & 127;
            qsm[i1] = seeds[(size_t)m * HD + h * DD + d] * INV_SCALE;
        }
    }
    __syncthreads();

    if (warp < 4) {      // scores for seed m = warp
        const int m = warp;
        float sc[8];
        float tmax = -INFINITY;
#pragma unroll
        for (int j = 0; j < 8; j++) {
            const int key = j * 32 + lane;
            float s = 0.f;
            const uint32_t* kr = Kr + key * 76;
#pragma unroll
            for (int dp = 0; dp < 64; dp++) {
                const uint32_t u = kr[dp];
                s += qsm[m * 128 + 2 * dp] * bflo(u)
                   + qsm[m * 128 + 2 * dp + 1] * bfhi(u);
            }
            sc[j] = s;
            tmax = fmaxf(tmax, s);
        }
        tmax = warp_max32(tmax);
        float lsum = 0.f;
#pragma unroll
        for (int j = 0; j < 8; j++) {
            const float p = __expf(sc[j] - tmax);
            ps[m * 260 + j * 32 + lane] = p;
            lsum += p;
        }
        lsum = warp_sum32(lsum);
        if (lane == 0) lsm[m] = lsum;
    }
    __syncthreads();

    {   // rep accumulation: thread = (m, dp)
        const int m = tid >> 6, dp = tid & 63;
        float rk0 = 0.f, rk1 = 0.f, rv0 = 0.f, rv1 = 0.f;
        const float* pm = ps + m * 260;
#pragma unroll 4
        for (int kp = 0; kp < 128; kp++) {
            const float p0 = pm[2 * kp], p1 = pm[2 * kp + 1];
            const uint32_t ka = Kr[(2 * kp) * 76 + dp];
            const uint32_t kb = Kr[(2 * kp + 1) * 76 + dp];
            rk0 += p0 * bflo(ka) + p1 * bflo(kb);
            rk1 += p0 * bfhi(ka) + p1 * bfhi(kb);
            const uint2 vv = *(const uint2*)&Vr[kp * 136 + 2 * dp];
            rv0 += p0 * bflo(vv.x) + p1 * bfhi(vv.x);
            rv1 += p0 * bflo(vv.y) + p1 * bfhi(vv.y);
        }
        const float inv = 1.f / lsm[m];
        const size_t r = (size_t)(kpart * MM + m) * 256 + h * 64 + dp;
        g_repKb[r] = bf2(rk0 * inv, rk1 * inv);
        g_repVb[r] = bf2(rv0 * inv, rv1 * inv);
    }
}

// ---------------------------------------------------------------------------
// Kernel 3: global cross-attention over 512 packed reps (streamed 64-key tiles)
// ---------------------------------------------------------------------------
#define GA_SMEM_BYTES ((64*76 + 32*136 + 128*36) * 4)

__global__ __launch_bounds__(256) void global_attn()
{
    extern __shared__ uint32_t sg[];
    uint32_t* Kr = sg;                        // [64][76]
    uint32_t* Vr = sg + 64 * 76;              // [32][136]
    uint32_t* Pp = sg + 64 * 76 + 32 * 136;   // [128][36]

    const int tid = threadIdx.x, warp = tid >> 5, lane = tid & 31;
    const int lr = lane >> 2, lc = lane & 3;
    const int h = blockIdx.y;
    const int q0 = blockIdx.x * 128;
    const int wq = warp * 16;
    const int n0g = q0 + wq + lr, n1g = q0 + wq + lr + 8;

    uint32_t qa[8][4];
    {
        const uint32_t* q0p = g_Qb + (size_t)n0g * 256 + h * 64;
        const uint32_t* q1p = g_Qb + (size_t)n1g * 256 + h * 64;
#pragma unroll
        for (int kf = 0; kf < 8; kf++) {
            qa[kf][0] = q0p[kf * 8 + lc];
            qa[kf][1] = q1p[kf * 8 + lc];
            qa[kf][2] = q0p[kf * 8 + lc + 4];
            qa[kf][3] = q1p[kf * 8 + lc + 4];
        }
    }

    float4 acc[16];
#pragma unroll
    for (int ni = 0; ni < 16; ni++) acc[ni] = make_float4(0.f, 0.f, 0.f, 0.f);
    float m0 = -INFINITY, m1 = -INFINITY, l0 = 0.f, l1 = 0.f;

    for (int t = 0; t < RR; t += 64) {
        __syncthreads();
        {   // K: direct packed copy
            const int key = tid >> 2, q4 = (tid & 3) * 16;
            const uint32_t* src = g_repKb + (size_t)(t + key) * 256 + h * 64 + q4;
            uint32_t* dst = Kr + key * 76 + q4;
#pragma unroll
            for (int j = 0; j < 4; j++)
                *(uint4*)(dst + 4 * j) = *(const uint4*)(src + 4 * j);
        }
        {   // V: PRMT cross-pack
            const int kpi = tid >> 3, d8 = (tid & 7) * 8;
            const uint32_t* sa = g_repVb + (size_t)(t + 2 * kpi) * 256 + h * 64 + d8;
            const uint32_t* sb = g_repVb + (size_t)(t + 2 * kpi + 1) * 256 + h * 64 + d8;
            uint32_t* dst = Vr + kpi * 136 + d8 * 2;
#pragma unroll
            for (int j = 0; j < 2; j++) {
                uint4 a = *(const uint4*)(sa + 4 * j);
                uint4 b = *(const uint4*)(sb + 4 * j);
                uint4 o0, o1;
                o0.x = prmt(a.x, b.x, 0x5410); o0.y = prmt(a.x, b.x, 0x7632);
                o0.z = prmt(a.y, b.y, 0x5410); o0.w = prmt(a.y, b.y, 0x7632);
                o1.x = prmt(a.z, b.z, 0x5410); o1.y = prmt(a.z, b.z, 0x7632);
                o1.z = prmt(a.w, b.w, 0x5410); o1.w = prmt(a.w, b.w, 0x7632);
                *(uint4*)(dst + 8 * j)     = o0;
                *(uint4*)(dst + 8 * j + 4) = o1;
            }
        }
        __syncthreads();

        float4 s[8];
#pragma unroll
        for (int ni = 0; ni < 8; ni++) s[ni] = make_float4(0.f, 0.f, 0.f, 0.f);
#pragma unroll
        for (int kf = 0; kf < 8; kf++) {
#pragma unroll
            for (int ni = 0; ni < 8; ni++) {
                const uint32_t* kr = Kr + (ni * 8 + lr) * 76 + kf * 8;
                mma_bf16(s[ni], qa[kf], kr[lc], kr[lc + 4]);
            }
        }

        float tm0 = -INFINITY, tm1 = -INFINITY;
#pragma unroll
        for (int ni = 0; ni < 8; ni++) {
            tm0 = fmaxf(tm0, fmaxf(s[ni].x, s[ni].y));
            tm1 = fmaxf(tm1, fmaxf(s[ni].z, s[ni].w));
        }
        tm0 = warp_max2(tm0); tm1 = warp_max2(tm1);
        const float mn0 = fmaxf(m0, tm0), mn1 = fmaxf(m1, tm1);
        const float c0 = __expf(m0 - mn0), c1 = __expf(m1 - mn1);
        m0 = mn0; m1 = mn1;

        float rs0 = 0.f, rs1 = 0.f;
        uint32_t* pw0 = Pp + (wq + lr) * 36;
        uint32_t* pw1 = Pp + (wq + lr + 8) * 36;
#pragma unroll
        for (int ni = 0; ni < 8; ni++) {
            const float p0 = __expf(s[ni].x - mn0);
            const float p1 = __expf(s[ni].y - mn0);
            const float p2 = __expf(s[ni].z - mn1);
            const float p3 = __expf(s[ni].w - mn1);
            rs0 += p0 + p1; rs1 += p2 + p3;
            pw0[ni * 4 + lc] = bf2(p0, p1);
            pw1[ni * 4 + lc] = bf2(p2, p3);
        }
        rs0 = warp_sum2(rs0); rs1 = warp_sum2(rs1);
        l0 = l0 * c0 + rs0; l1 = l1 * c1 + rs1;
#pragma unroll
        for (int ni = 0; ni < 16; ni++) {
            acc[ni].x *= c0; acc[ni].y *= c0;
            acc[ni].z *= c1; acc[ni].w *= c1;
        }
        __syncwarp();

#pragma unroll
        for (int kf = 0; kf < 4; kf++) {
            uint32_t pa[4];
            pa[0] = Pp[(wq + lr)     * 36 + kf * 8 + lc];
            pa[1] = Pp[(wq + lr + 8) * 36 + kf * 8 + lc];
            pa[2] = Pp[(wq + lr)     * 36 + kf * 8 + lc + 4];
            pa[3] = Pp[(wq + lr + 8) * 36 + kf * 8 + lc + 4];
            const uint32_t* vr0 = Vr + (kf * 8 + lc) * 136;
            const uint32_t* vr1 = Vr + (kf * 8 + lc + 4) * 136;
#pragma unroll
            for (int ni = 0; ni < 16; ni++)
                mma_bf16(acc[ni], pa, vr0[ni * 8 + lr], vr1[ni * 8 + lr]);
        }
    }

    const float inv0 = 1.f / l0, inv1 = 1.f / l1;
    float* o0 = g_outG + (size_t)n0g * HD + h * DD;
    float* o1 = g_outG + (size_t)n1g * HD + h * DD;
#pragma unroll
    for (int ni = 0; ni < 16; ni++) {
        const int col = ni * 8 + 2 * lc;
        *(float2*)&o0[col] = make_float2(acc[ni].x * inv0, acc[ni].y * inv0);
        *(float2*)&o1[col] = make_float2(acc[ni].z * inv1, acc[ni].w * inv1);
    }
}

// ---------------------------------------------------------------------------
// Kernel 4: combine
// ---------------------------------------------------------------------------
__global__ __launch_bounds__(256) void combine(const float* __restrict__ alpha_logit,
                                               const float* __restrict__ beta_p,
                                               float* __restrict__ out)
{
    const int idx = blockIdx.x * blockDim.x + threadIdx.x;
    const int n  = idx / (DD / 4);
    const int d4 = (idx % (DD / 4)) * 4;

    const float alpha = 1.f / (1.f + __expf(-alpha_logit[0]));
    const float beta  = beta_p[0];
    const float ca = alpha * 0.25f;
    const float cg = (1.f - alpha) * 0.25f;
    const float cb = beta * 0.25f;

    float sl0 = 0, sl1 = 0, sl2 = 0, sl3 = 0;
    float sg0 = 0, sg1 = 0, sg2 = 0, sg3 = 0;
    float sv0 = 0, sv1 = 0, sv2 = 0, sv3 = 0;
#pragma unroll
    for (int h = 0; h < HH; h++) {
        const size_t base = (size_t)n * HD + h * DD + d4;
        float4 a = *(const float4*)&g_outL[base];
        float4 b = *(const float4*)&g_outG[base];
        float4 c = *(const float4*)&g_V[base];
        sl0 += a.x; sl1 += a.y; sl2 += a.z; sl3 += a.w;
        sg0 += b.x; sg1 += b.y; sg2 += b.z; sg3 += b.w;
        sv0 += c.x; sv1 += c.y; sv2 += c.z; sv3 += c.w;
    }
    float4 o;
    o.x = ca * sl0 + cg * sg0 + cb * sv0;
    o.y = ca * sl1 + cg * sg1 + cb * sv1;
    o.z = ca * sl2 + cg * sg2 + cb * sv2;
    o.w = ca * sl3 + cg * sg3 + cb * sv3;
    *(float4*)&out[(size_t)n * DD + d4] = o;
}

// ---------------------------------------------------------------------------
// Launcher
// ---------------------------------------------------------------------------
extern "C" void kernel_launch(void* const* d_in, const int* in_sizes, int n_in,
                              void* d_out, int out_size)
{
    (void)in_sizes; (void)n_in; (void)out_size;
    const float* x     = (const float*)d_in[0];
    const int*   pidx  = (const int*)  d_in[1];
    const float* Wq    = (const float*)d_in[2];
    const float* bq    = (const float*)d_in[3];
    const float* Wk    = (const float*)d_in[4];
    const float* bk    = (const float*)d_in[5];
    const float* Wv    = (const float*)d_in[6];
    const float* bv    = (const float*)d_in[7];
    const float* seeds = (const float*)d_in[8];
    const float* alog  = (const float*)d_in[9];
    const float* beta  = (const float*)d_in[10];
    float* out = (float*)d_out;

    // idempotent host-state calls; capture-legal
    cudaFuncSetAttribute((const void*)qkv_gemm_tc,
                         cudaFuncAttributeMaxDynamicSharedMemorySize, GEMM_SMEM_BYTES);
    cudaFuncSetAttribute((const void*)fine_attn_pool,
                         cudaFuncAttributeMaxDynamicSharedMemorySize, FINE_SMEM_BYTES);
    cudaFuncSetAttribute((const void*)global_attn,
                         cudaFuncAttributeMaxDynamicSharedMemorySize, GA_SMEM_BYTES);

    split_xt<<<NN / 128, 256>>>(x);
    dim3 gw(128 * HD / 256, 3);
    split_w<<<gw, 256>>>(Wq, Wk, Wv);

    dim3 g1(HD / 128, NN / 128, 3);
    qkv_gemm_tc<<<g1, 256, GEMM_SMEM_BYTES>>>(bq, bk, bv);

    dim3 g2(KPP, HH);                          // fine + pooling: 128 x 4
    fine_attn_pool<<<g2, 256, FINE_SMEM_BYTES>>>(pidx, seeds);

    dim3 g4(NN / 128, HH);                     // global: 256 x 4
    global_attn<<<g4, 256, GA_SMEM_BYTES>>>();

    combine<<<(NN * DD / 4) / 256, 256>>>(alog, beta, out);
}

// round 9
// speedup vs baseline: 13.6260x; 1.1625x over previous
#include <cuda_runtime.h>
#include <cuda_bf16.h>
#include <math.h>
#include <stdint.h>

// ---------------------------------------------------------------------------
// Problem constants
// ---------------------------------------------------------------------------
#define NN   32768
#define IN_C 256
#define DD   128
#define HH   4
#define HD   512
#define MM   4
#define KPP  128
#define SSZ  256
#define RR   (KPP*MM)
#define INV_SCALE 0.088388347648318447f   // 1/sqrt(128)

// ---------------------------------------------------------------------------
// Scratch (static device globals; no allocation allowed)
// ---------------------------------------------------------------------------
__device__ float    g_V[(size_t)NN*HD];          // fp32 V (combine)
__device__ float    g_outL[(size_t)NN*HD];
__device__ float    g_outG[(size_t)NN*HD];
__device__ uint32_t g_Qb[(size_t)NN*256];        // packed bf16x2, pre-scaled
__device__ uint32_t g_Kb[(size_t)NN*256];
__device__ uint32_t g_Vb[(size_t)NN*256];
__device__ uint32_t g_repKb[(size_t)RR*256];
__device__ uint32_t g_repVb[(size_t)RR*256];
// GEMM operands: hi/lo bf16x2 splits
__device__ uint32_t g_xh_t[(size_t)128*NN];      // [kp][m] (transposed)
__device__ uint32_t g_xl_t[(size_t)128*NN];
__device__ uint32_t g_Wh[3][(IN_C/2)*HD];        // [kp][n]
__device__ uint32_t g_Wl[3][(IN_C/2)*HD];

// ---------------------------------------------------------------------------
// helpers
// ---------------------------------------------------------------------------
__device__ __forceinline__ float bfr(float v) {
    return __bfloat162float(__float2bfloat16(v));
}
__device__ __forceinline__ uint32_t bf2(float lo, float hi) {
    uint32_t r;
    asm("cvt.rn.bf16x2.f32 %0, %1, %2;" : "=r"(r) : "f"(hi), "f"(lo));
    return r;
}
__device__ __forceinline__ float bflo(uint32_t u) { return __uint_as_float(u << 16); }
__device__ __forceinline__ float bfhi(uint32_t u) { return __uint_as_float(u & 0xffff0000u); }
__device__ __forceinline__ uint32_t prmt(uint32_t a, uint32_t b, uint32_t sel) {
    uint32_t r;
    asm("prmt.b32 %0, %1, %2, %3;" : "=r"(r) : "r"(a), "r"(b), "r"(sel));
    return r;
}
__device__ __forceinline__ void mma_bf16(float4& d, const uint32_t a[4],
                                         uint32_t b0, uint32_t b1) {
    asm volatile(
        "mma.sync.aligned.m16n8k16.row.col.f32.bf16.bf16.f32 "
        "{%0,%1,%2,%3}, {%4,%5,%6,%7}, {%8,%9}, {%0,%1,%2,%3};"
        : "+f"(d.x), "+f"(d.y), "+f"(d.z), "+f"(d.w)
        : "r"(a[0]), "r"(a[1]), "r"(a[2]), "r"(a[3]), "r"(b0), "r"(b1));
}
#define CP_ASYNC16(dst, src) \
    asm volatile("cp.async.cg.shared.global [%0], [%1], 16;" :: "r"(dst), "l"(src))
#define CP_COMMIT() asm volatile("cp.async.commit_group;")
#define CP_WAIT(n)  asm volatile("cp.async.wait_group %0;" :: "n"(n))

__device__ __forceinline__ float warp_max2(float s) {
    s = fmaxf(s, __shfl_xor_sync(0xffffffffu, s, 1));
    s = fmaxf(s, __shfl_xor_sync(0xffffffffu, s, 2));
    return s;
}
__device__ __forceinline__ float warp_sum2(float s) {
    s += __shfl_xor_sync(0xffffffffu, s, 1);
    s += __shfl_xor_sync(0xffffffffu, s, 2);
    return s;
}
__device__ __forceinline__ float warp_max32(float s) {
#pragma unroll
    for (int o = 16; o > 0; o >>= 1) s = fmaxf(s, __shfl_xor_sync(0xffffffffu, s, o));
    return s;
}
__device__ __forceinline__ float warp_sum32(float s) {
#pragma unroll
    for (int o = 16; o > 0; o >>= 1) s += __shfl_xor_sync(0xffffffffu, s, o);
    return s;
}

// ---------------------------------------------------------------------------
// split_xt: x -> transposed hi/lo bf16x2 splits  g_x{h,l}_t [kp][m]
// ---------------------------------------------------------------------------
__global__ __launch_bounds__(256) void split_xt(const float* __restrict__ x)
{
    __shared__ uint32_t Th[32][132];
    __shared__ uint32_t Tl[32][132];
    const int m0 = blockIdx.x * 128;
    const int tid = threadIdx.x;
#pragma unroll
    for (int c = 0; c < 4; c++) {
        const int kpb = c * 32;
        {
            const int m = tid >> 1, half = tid & 1;
            const float* src = x + (size_t)(m0 + m) * IN_C + (kpb + half * 16) * 2;
#pragma unroll
            for (int j = 0; j < 16; j++) {
                float2 v = *(const float2*)(src + 2 * j);
                const float h0 = bfr(v.x), h1 = bfr(v.y);
                Th[half * 16 + j][m] = bf2(v.x, v.y);
                Tl[half * 16 + j][m] = bf2(v.x - h0, v.y - h1);
            }
        }
        __syncthreads();
        {
            const int kpr = tid >> 3, mo = (tid & 7) * 16;
            uint32_t* dh = g_xh_t + (size_t)(kpb + kpr) * NN + m0 + mo;
            uint32_t* dl = g_xl_t + (size_t)(kpb + kpr) * NN + m0 + mo;
#pragma unroll
            for (int j = 0; j < 4; j++) {
                *(uint4*)(dh + 4 * j) = *(uint4*)&Th[kpr][mo + 4 * j];
                *(uint4*)(dl + 4 * j) = *(uint4*)&Tl[kpr][mo + 4 * j];
            }
        }
        __syncthreads();
    }
}

// ---------------------------------------------------------------------------
// split_w: W -> hi/lo bf16x2 splits  g_W{h,l} [kp][n]
// ---------------------------------------------------------------------------
__global__ __launch_bounds__(256) void split_w(
    const float* __restrict__ Wq, const float* __restrict__ Wk,
    const float* __restrict__ Wv)
{
    const float* W = (blockIdx.y == 0) ? Wq : (blockIdx.y == 1) ? Wk : Wv;
    const int idx = blockIdx.x * 256 + threadIdx.x;
    const int kp = idx >> 9, n = idx & 511;
    const float v0 = W[(size_t)(2 * kp) * HD + n];
    const float v1 = W[(size_t)(2 * kp + 1) * HD + n];
    const float h0 = bfr(v0), h1 = bfr(v1);
    g_Wh[blockIdx.y][idx] = bf2(v0, v1);
    g_Wl[blockIdx.y][idx] = bf2(v0 - h0, v1 - h1);
}

// ---------------------------------------------------------------------------
// Kernel 1: QKV GEMM, cp.async double-buffered, m16n8k16.
// NT=1: single bf16 product (Q, K — stored bf16 anyway).
// NT=3: hi/lo split, 3 products (V — feeds fp32 x_self path).
// ---------------------------------------------------------------------------
#define GSTG 2176                       // 16*136 u32 per array

template<int NT>
__global__ __launch_bounds__(256) void qkv_gemm_tc(
    const float* __restrict__ bq, const float* __restrict__ bk,
    const float* __restrict__ bv, int zbase)
{
    const int z = zbase + blockIdx.z;
    const uint32_t* WH = g_Wh[z];
    const uint32_t* WL = g_Wl[z];
    const float* bias = (z == 0) ? bq : (z == 1) ? bk : bv;
    uint32_t* Cb = (z == 0) ? g_Qb : (z == 1) ? g_Kb : g_Vb;

    constexpr int NA = (NT == 3) ? 4 : 2;       // arrays per stage
    extern __shared__ uint32_t smg[];

    const int tid  = threadIdx.x;
    const int warp = tid >> 5, lane = tid & 31;
    const int lr = lane >> 2, lc = lane & 3;
    const int wm = warp & 3, wn = warp >> 2;
    const int row0 = blockIdx.y * 128;
    const int col0 = blockIdx.x * 128;

    auto issue = [&](int it, int b) {
        const int kp0 = it * 16;
        uint32_t* buf = smg + b * NA * GSTG;
        uint32_t base;
        asm("{ .reg .u64 t; cvta.to.shared.u64 t, %1; cvt.u32.u64 %0, t; }"
            : "=r"(base) : "l"(buf));
#pragma unroll
        for (int j = 0; j < 2; j++) {
            const int slot = tid * 2 + j;
            const int kpr = slot >> 5, f = (slot & 31) * 4;
            const size_t asrc = (size_t)(kp0 + kpr) * NN + row0 + f;
            const size_t bsrc = (size_t)(kp0 + kpr) * HD + col0 + f;
            const uint32_t doff = (kpr * 136 + f) * 4;
            if (NT == 3) {
                CP_ASYNC16(base + 0 * GSTG * 4 + doff, g_xh_t + asrc);
                CP_ASYNC16(base + 1 * GSTG * 4 + doff, g_xl_t + asrc);
                CP_ASYNC16(base + 2 * GSTG * 4 + doff, WH + bsrc);
                CP_ASYNC16(base + 3 * GSTG * 4 + doff, WL + bsrc);
            } else {
                CP_ASYNC16(base + 0 * GSTG * 4 + doff, g_xh_t + asrc);
                CP_ASYNC16(base + 1 * GSTG * 4 + doff, WH + bsrc);
            }
        }
    };

    float4 acc[2][8];
#pragma unroll
    for (int mi = 0; mi < 2; mi++)
#pragma unroll
        for (int ni = 0; ni < 8; ni++)
            acc[mi][ni] = make_float4(0.f, 0.f, 0.f, 0.f);

    issue(0, 0); CP_COMMIT();

    for (int it = 0; it < 8; it++) {
        if (it < 7) { issue(it + 1, (it + 1) & 1); CP_COMMIT(); CP_WAIT(1); }
        else        { CP_WAIT(0); }
        __syncthreads();

        const uint32_t* buf = smg + (it & 1) * NA * GSTG;
        const uint32_t* Ah = buf;
        const uint32_t* Al = buf + GSTG;                      // NT==3 only
        const uint32_t* Bh = buf + (NT == 3 ? 2 : 1) * GSTG;
        const uint32_t* Bl = buf + 3 * GSTG;                  // NT==3 only

#pragma unroll
        for (int kf = 0; kf < 2; kf++) {
            const int r0 = (kf * 8 + lc) * 136;
            const int r1 = (kf * 8 + lc + 4) * 136;
            uint32_t ah[2][4], al[2][4];
#pragma unroll
            for (int mi = 0; mi < 2; mi++) {
                const int m0 = wm * 32 + mi * 16 + lr;
                ah[mi][0] = Ah[r0 + m0]; ah[mi][1] = Ah[r0 + m0 + 8];
                ah[mi][2] = Ah[r1 + m0]; ah[mi][3] = Ah[r1 + m0 + 8];
                if (NT == 3) {
                    al[mi][0] = Al[r0 + m0]; al[mi][1] = Al[r0 + m0 + 8];
                    al[mi][2] = Al[r1 + m0]; al[mi][3] = Al[r1 + m0 + 8];
                }
            }
#pragma unroll
            for (int ni = 0; ni < 8; ni++) {
                const int n0 = wn * 64 + ni * 8 + lr;
                const uint32_t bh0 = Bh[r0 + n0], bh1 = Bh[r1 + n0];
#pragma unroll
                for (int mi = 0; mi < 2; mi++) {
                    mma_bf16(acc[mi][ni], ah[mi], bh0, bh1);
                    if (NT == 3) {
                        const uint32_t bl0 = Bl[r0 + n0], bl1 = Bl[r1 + n0];
                        mma_bf16(acc[mi][ni], ah[mi], bl0, bl1);
                        mma_bf16(acc[mi][ni], al[mi], bh0, bh1);
                    }
                }
            }
        }
        __syncthreads();
    }

    // epilogue
#pragma unroll
    for (int mi = 0; mi < 2; mi++) {
        const int r = row0 + wm * 32 + mi * 16 + lr;
#pragma unroll
        for (int ni = 0; ni < 8; ni++) {
            const int c = col0 + wn * 64 + ni * 8 + 2 * lc;
            const float2 b2 = *(const float2*)&bias[c];
            float x0 = acc[mi][ni].x + b2.x, y0 = acc[mi][ni].y + b2.y;
            float x1 = acc[mi][ni].z + b2.x, y1 = acc[mi][ni].w + b2.y;
            if (z == 0) { x0 *= INV_SCALE; y0 *= INV_SCALE;
                          x1 *= INV_SCALE; y1 *= INV_SCALE; }
            const int cp = c >> 1;
            Cb[(size_t)r * 256 + cp]       = bf2(x0, y0);
            Cb[(size_t)(r + 8) * 256 + cp] = bf2(x1, y1);
            if (z == 2) {
                *(float2*)&g_V[(size_t)r * HD + c]       = make_float2(x0, y0);
                *(float2*)&g_V[(size_t)(r + 8) * HD + c] = make_float2(x1, y1);
            }
        }
    }
}

// ---------------------------------------------------------------------------
// Kernel 2: fine attention + fused coarse pooling. Register-resident P
// (S c-frag packs directly into PV a-frag; no smem round-trip).
//   Kr [256 key][68]  packed bf16x2 pairs along d   (b-frag banks 4lr+lc: CF)
//   Vr [128 kpair][136] pairs along key             (b-frag banks 8lc+lr: CF)
// ---------------------------------------------------------------------------
#define FINE_SMEM_BYTES ((256*68 + 128*136) * 4 + 6240)

__global__ __launch_bounds__(256) void fine_attn_pool(
    const int* __restrict__ pidx, const float* __restrict__ seeds)
{
    extern __shared__ uint32_t sf[];
    uint32_t* Kr = sf;                        // [256][68]
    uint32_t* Vr = sf + 256 * 68;             // [128][136]
    float*    ps = (float*)(sf + 256 * 68 + 128 * 136);   // pooling scratch

    const int tid = threadIdx.x, warp = tid >> 5, lane = tid & 31;
    const int lr = lane >> 2, lc = lane & 3;
    const int kpart = blockIdx.x, h = blockIdx.y;
    const int* pi = pidx + kpart * SSZ;

    // ---- stage K (one key per thread, direct packed copy) ----
    {
        const int node = pi[tid];
        const uint32_t* src = g_Kb + (size_t)node * 256 + h * 64;
        uint32_t* dst = Kr + tid * 68;
#pragma unroll
        for (int j = 0; j < 16; j++)
            *(uint4*)(dst + 4 * j) = *(const uint4*)(src + 4 * j);
    }
    // ---- stage V (kpair per thread-pair, PRMT cross-pack) ----
    {
        const int kpi = tid >> 1, dh = (tid & 1) * 32;
        const int ka = pi[2 * kpi], kb = pi[2 * kpi + 1];
        const uint32_t* sa = g_Vb + (size_t)ka * 256 + h * 64 + dh;
        const uint32_t* sb = g_Vb + (size_t)kb * 256 + h * 64 + dh;
        uint32_t* dst = Vr + kpi * 136 + dh * 2;
#pragma unroll
        for (int j = 0; j < 8; j++) {
            uint4 a = *(const uint4*)(sa + 4 * j);
            uint4 b = *(const uint4*)(sb + 4 * j);
            uint4 o0, o1;
            o0.x = prmt(a.x, b.x, 0x5410); o0.y = prmt(a.x, b.x, 0x7632);
            o0.z = prmt(a.y, b.y, 0x5410); o0.w = prmt(a.y, b.y, 0x7632);
            o1.x = prmt(a.z, b.z, 0x5410); o1.y = prmt(a.z, b.z, 0x7632);
            o1.z = prmt(a.w, b.w, 0x5410); o1.w = prmt(a.w, b.w, 0x7632);
            *(uint4*)(dst + 8 * j)     = o0;
            *(uint4*)(dst + 8 * j + 4) = o1;
        }
    }
    __syncthreads();

    const int wq = warp * 16;

    // ---- attention: two q-sets of 128 rows ----
#pragma unroll 1
    for (int set = 0; set < 2; set++) {
        const int qb = set * 128;
        const int n0g = pi[qb + wq + lr];
        const int n1g = pi[qb + wq + lr + 8];

        uint32_t qa[8][4];
        {
            const uint32_t* q0p = g_Qb + (size_t)n0g * 256 + h * 64;
            const uint32_t* q1p = g_Qb + (size_t)n1g * 256 + h * 64;
#pragma unroll
            for (int kf = 0; kf < 8; kf++) {
                qa[kf][0] = q0p[kf * 8 + lc];
                qa[kf][1] = q1p[kf * 8 + lc];
                qa[kf][2] = q0p[kf * 8 + lc + 4];
                qa[kf][3] = q1p[kf * 8 + lc + 4];
            }
        }

        float4 acc[16];
#pragma unroll
        for (int ni = 0; ni < 16; ni++) acc[ni] = make_float4(0.f, 0.f, 0.f, 0.f);
        float m0 = -INFINITY, m1 = -INFINITY, l0 = 0.f, l1 = 0.f;

#pragma unroll 1
        for (int kt = 0; kt < 4; kt++) {
            float4 s[8];
#pragma unroll
            for (int ni = 0; ni < 8; ni++) s[ni] = make_float4(0.f, 0.f, 0.f, 0.f);
#pragma unroll
            for (int kf = 0; kf < 8; kf++) {
#pragma unroll
                for (int ni = 0; ni < 8; ni++) {
                    const uint32_t* kr = Kr + (kt * 64 + ni * 8 + lr) * 68 + kf * 8;
                    mma_bf16(s[ni], qa[kf], kr[lc], kr[lc + 4]);
                }
            }

            float tm0 = -INFINITY, tm1 = -INFINITY;
#pragma unroll
            for (int ni = 0; ni < 8; ni++) {
                tm0 = fmaxf(tm0, fmaxf(s[ni].x, s[ni].y));
                tm1 = fmaxf(tm1, fmaxf(s[ni].z, s[ni].w));
            }
            tm0 = warp_max2(tm0); tm1 = warp_max2(tm1);
            const float mn0 = fmaxf(m0, tm0), mn1 = fmaxf(m1, tm1);
            const float c0 = __expf(m0 - mn0), c1 = __expf(m1 - mn1);
            m0 = mn0; m1 = mn1;

            // exp in regs; pack P c-frags directly into PV a-frags
            float rs0 = 0.f, rs1 = 0.f;
            uint32_t pa[4][4];
#pragma unroll
            for (int ni = 0; ni < 8; ni++) {
                const float p0 = __expf(s[ni].x - mn0);
                const float p1 = __expf(s[ni].y - mn0);
                const float p2 = __expf(s[ni].z - mn1);
                const float p3 = __expf(s[ni].w - mn1);
                rs0 += p0 + p1; rs1 += p2 + p3;
                pa[ni >> 1][(ni & 1) * 2 + 0] = bf2(p0, p1);
                pa[ni >> 1][(ni & 1) * 2 + 1] = bf2(p2, p3);
            }
            rs0 = warp_sum2(rs0); rs1 = warp_sum2(rs1);
            l0 = l0 * c0 + rs0; l1 = l1 * c1 + rs1;
#pragma unroll
            for (int ni = 0; ni < 16; ni++) {
                acc[ni].x *= c0; acc[ni].y *= c0;
                acc[ni].z *= c1; acc[ni].w *= c1;
            }

#pragma unroll
            for (int kf = 0; kf < 4; kf++) {
                const uint32_t* vr0 = Vr + (kt * 32 + kf * 8 + lc) * 136;
                const uint32_t* vr1 = Vr + (kt * 32 + kf * 8 + lc + 4) * 136;
#pragma unroll
                for (int ni = 0; ni < 16; ni++)
                    mma_bf16(acc[ni], pa[kf], vr0[ni * 8 + lr], vr1[ni * 8 + lr]);
            }
        }

        const float inv0 = 1.f / l0, inv1 = 1.f / l1;
        float* o0 = g_outL + (size_t)n0g * HD + h * DD;
        float* o1 = g_outL + (size_t)n1g * HD + h * DD;
#pragma unroll
        for (int ni = 0; ni < 16; ni++) {
            const int col = ni * 8 + 2 * lc;
            *(float2*)&o0[col] = make_float2(acc[ni].x * inv0, acc[ni].y * inv0);
            *(float2*)&o1[col] = make_float2(acc[ni].z * inv1, acc[ni].w * inv1);
        }
    }

    // ---- fused coarse pooling on resident K/V ----
    float* qsm = ps + 4 * 260;               // [4][128]
    float* lsm = qsm + 4 * 128;              // [4]
    {
        const int i0 = tid, i1 = tid + 256;
        { const int m = i0 >> 7, d = i0 & 127;
          qsm[i0] = seeds[(size_t)m * HD + h * DD + d] * INV_SCALE; }
        { const int m = i1 >> 7, d = i1 & 127;
          qsm[i1] = seeds[(size_t)m * HD + h * DD + d] * INV_SCALE; }
    }
    __syncthreads();

    if (warp < 4) {
        const int m = warp;
        float sc[8];
        float tmax = -INFINITY;
#pragma unroll
        for (int j = 0; j < 8; j++) {
            const int key = j * 32 + lane;
            float s = 0.f;
            const uint32_t* kr = Kr + key * 68;
#pragma unroll
            for (int dp = 0; dp < 64; dp++) {
                const uint32_t u = kr[dp];
                s += qsm[m * 128 + 2 * dp] * bflo(u)
                   + qsm[m * 128 + 2 * dp + 1] * bfhi(u);
            }
            sc[j] = s;
            tmax = fmaxf(tmax, s);
        }
        tmax = warp_max32(tmax);
        float lsum = 0.f;
#pragma unroll
        for (int j = 0; j < 8; j++) {
            const float p = __expf(sc[j] - tmax);
            ps[m * 260 + j * 32 + lane] = p;
            lsum += p;
        }
        lsum = warp_sum32(lsum);
        if (lane == 0) lsm[m] = lsum;
    }
    __syncthreads();

    {
        const int m = tid >> 6, dp = tid & 63;
        float rk0 = 0.f, rk1 = 0.f, rv0 = 0.f, rv1 = 0.f;
        const float* pm = ps + m * 260;
#pragma unroll 4
        for (int kp = 0; kp < 128; kp++) {
            const float p0 = pm[2 * kp], p1 = pm[2 * kp + 1];
            const uint32_t ka = Kr[(2 * kp) * 68 + dp];
            const uint32_t kb = Kr[(2 * kp + 1) * 68 + dp];
            rk0 += p0 * bflo(ka) + p1 * bflo(kb);
            rk1 += p0 * bfhi(ka) + p1 * bfhi(kb);
            const uint2 vv = *(const uint2*)&Vr[kp * 136 + 2 * dp];
            rv0 += p0 * bflo(vv.x) + p1 * bfhi(vv.x);
            rv1 += p0 * bflo(vv.y) + p1 * bfhi(vv.y);
        }
        const float inv = 1.f / lsm[m];
        const size_t r = (size_t)(kpart * MM + m) * 256 + h * 64 + dp;
        g_repKb[r] = bf2(rk0 * inv, rk1 * inv);
        g_repVb[r] = bf2(rv0 * inv, rv1 * inv);
    }
}

// ---------------------------------------------------------------------------
// Kernel 3: global cross-attention over 512 packed reps. Register-P,
// small smem (35 KB -> 3 blocks/SM).
// ---------------------------------------------------------------------------
#define GA_SMEM_BYTES ((64*68 + 32*136) * 4)

__global__ __launch_bounds__(256) void global_attn()
{
    extern __shared__ uint32_t sg[];
    uint32_t* Kr = sg;                        // [64][68]
    uint32_t* Vr = sg + 64 * 68;              // [32][136]

    const int tid = threadIdx.x, warp = tid >> 5, lane = tid & 31;
    const int lr = lane >> 2, lc = lane & 3;
    const int h = blockIdx.y;
    const int q0 = blockIdx.x * 128;
    const int wq = warp * 16;
    const int n0g = q0 + wq + lr, n1g = q0 + wq + lr + 8;

    uint32_t qa[8][4];
    {
        const uint32_t* q0p = g_Qb + (size_t)n0g * 256 + h * 64;
        const uint32_t* q1p = g_Qb + (size_t)n1g * 256 + h * 64;
#pragma unroll
        for (int kf = 0; kf < 8; kf++) {
            qa[kf][0] = q0p[kf * 8 + lc];
            qa[kf][1] = q1p[kf * 8 + lc];
            qa[kf][2] = q0p[kf * 8 + lc + 4];
            qa[kf][3] = q1p[kf * 8 + lc + 4];
        }
    }

    float4 acc[16];
#pragma unroll
    for (int ni = 0; ni < 16; ni++) acc[ni] = make_float4(0.f, 0.f, 0.f, 0.f);
    float m0 = -INFINITY, m1 = -INFINITY, l0 = 0.f, l1 = 0.f;

    for (int t = 0; t < RR; t += 64) {
        __syncthreads();
        {   // K: direct packed copy
            const int key = tid >> 2, q4 = (tid & 3) * 16;
            const uint32_t* src = g_repKb + (size_t)(t + key) * 256 + h * 64 + q4;
            uint32_t* dst = Kr + key * 68 + q4;
#pragma unroll
            for (int j = 0; j < 4; j++)
                *(uint4*)(dst + 4 * j) = *(const uint4*)(src + 4 * j);
        }
        {   // V: PRMT cross-pack
            const int kpi = tid >> 3, d8 = (tid & 7) * 8;
            const uint32_t* sa = g_repVb + (size_t)(t + 2 * kpi) * 256 + h * 64 + d8;
            const uint32_t* sb = g_repVb + (size_t)(t + 2 * kpi + 1) * 256 + h * 64 + d8;
            uint32_t* dst = Vr + kpi * 136 + d8 * 2;
#pragma unroll
            for (int j = 0; j < 2; j++) {
                uint4 a = *(const uint4*)(sa + 4 * j);
                uint4 b = *(const uint4*)(sb + 4 * j);
                uint4 o0, o1;
                o0.x = prmt(a.x, b.x, 0x5410); o0.y = prmt(a.x, b.x, 0x7632);
                o0.z = prmt(a.y, b.y, 0x5410); o0.w = prmt(a.y, b.y, 0x7632);
                o1.x = prmt(a.z, b.z, 0x5410); o1.y = prmt(a.z, b.z, 0x7632);
                o1.z = prmt(a.w, b.w, 0x5410); o1.w = prmt(a.w, b.w, 0x7632);
                *(uint4*)(dst + 8 * j)     = o0;
                *(uint4*)(dst + 8 * j + 4) = o1;
            }
        }
        __syncthreads();

        float4 s[8];
#pragma unroll
        for (int ni = 0; ni < 8; ni++) s[ni] = make_float4(0.f, 0.f, 0.f, 0.f);
#pragma unroll
        for (int kf = 0; kf < 8; kf++) {
#pragma unroll
            for (int ni = 0; ni < 8; ni++) {
                const uint32_t* kr = Kr + (ni * 8 + lr) * 68 + kf * 8;
                mma_bf16(s[ni], qa[kf], kr[lc], kr[lc + 4]);
            }
        }

        float tm0 = -INFINITY, tm1 = -INFINITY;
#pragma unroll
        for (int ni = 0; ni < 8; ni++) {
            tm0 = fmaxf(tm0, fmaxf(s[ni].x, s[ni].y));
            tm1 = fmaxf(tm1, fmaxf(s[ni].z, s[ni].w));
        }
        tm0 = warp_max2(tm0); tm1 = warp_max2(tm1);
        const float mn0 = fmaxf(m0, tm0), mn1 = fmaxf(m1, tm1);
        const float c0 = __expf(m0 - mn0), c1 = __expf(m1 - mn1);
        m0 = mn0; m1 = mn1;

        float rs0 = 0.f, rs1 = 0.f;
        uint32_t pa[4][4];
#pragma unroll
        for (int ni = 0; ni < 8; ni++) {
            const float p0 = __expf(s[ni].x - mn0);
            const float p1 = __expf(s[ni].y - mn0);
            const float p2 = __expf(s[ni].z - mn1);
            const float p3 = __expf(s[ni].w - mn1);
            rs0 += p0 + p1; rs1 += p2 + p3;
            pa[ni >> 1][(ni & 1) * 2 + 0] = bf2(p0, p1);
            pa[ni >> 1][(ni & 1) * 2 + 1] = bf2(p2, p3);
        }
        rs0 = warp_sum2(rs0); rs1 = warp_sum2(rs1);
        l0 = l0 * c0 + rs0; l1 = l1 * c1 + rs1;
#pragma unroll
        for (int ni = 0; ni < 16; ni++) {
            acc[ni].x *= c0; acc[ni].y *= c0;
            acc[ni].z *= c1; acc[ni].w *= c1;
        }

#pragma unroll
        for (int kf = 0; kf < 4; kf++) {
            const uint32_t* vr0 = Vr + (kf * 8 + lc) * 136;
            const uint32_t* vr1 = Vr + (kf * 8 + lc + 4) * 136;
#pragma unroll
            for (int ni = 0; ni < 16; ni++)
                mma_bf16(acc[ni], pa[kf], vr0[ni * 8 + lr], vr1[ni * 8 + lr]);
        }
    }

    const float inv0 = 1.f / l0, inv1 = 1.f / l1;
    float* o0 = g_outG + (size_t)n0g * HD + h * DD;
    float* o1 = g_outG + (size_t)n1g * HD + h * DD;
#pragma unroll
    for (int ni = 0; ni < 16; ni++) {
        const int col = ni * 8 + 2 * lc;
        *(float2*)&o0[col] = make_float2(acc[ni].x * inv0, acc[ni].y * inv0);
        *(float2*)&o1[col] = make_float2(acc[ni].z * inv1, acc[ni].w * inv1);
    }
}

// ---------------------------------------------------------------------------
// Kernel 4: combine
// ---------------------------------------------------------------------------
__global__ __launch_bounds__(256) void combine(const float* __restrict__ alpha_logit,
                                               const float* __restrict__ beta_p,
                                               float* __restrict__ out)
{
    const int idx = blockIdx.x * blockDim.x + threadIdx.x;
    const int n  = idx / (DD / 4);
    const int d4 = (idx % (DD / 4)) * 4;

    const float alpha = 1.f / (1.f + __expf(-alpha_logit[0]));
    const float beta  = beta_p[0];
    const float ca = alpha * 0.25f;
    const float cg = (1.f - alpha) * 0.25f;
    const float cb = beta * 0.25f;

    float sl0 = 0, sl1 = 0, sl2 = 0, sl3 = 0;
    float sg0 = 0, sg1 = 0, sg2 = 0, sg3 = 0;
    float sv0 = 0, sv1 = 0, sv2 = 0, sv3 = 0;
#pragma unroll
    for (int h = 0; h < HH; h++) {
        const size_t base = (size_t)n * HD + h * DD + d4;
        float4 a = *(const float4*)&g_outL[base];
        float4 b = *(const float4*)&g_outG[base];
        float4 c = *(const float4*)&g_V[base];
        sl0 += a.x; sl1 += a.y; sl2 += a.z; sl3 += a.w;
        sg0 += b.x; sg1 += b.y; sg2 += b.z; sg3 += b.w;
        sv0 += c.x; sv1 += c.y; sv2 += c.z; sv3 += c.w;
    }
    float4 o;
    o.x = ca * sl0 + cg * sg0 + cb * sv0;
    o.y = ca * sl1 + cg * sg1 + cb * sv1;
    o.z = ca * sl2 + cg * sg2 + cb * sv2;
    o.w = ca * sl3 + cg * sg3 + cb * sv3;
    *(float4*)&out[(size_t)n * DD + d4] = o;
}

// ---------------------------------------------------------------------------
// Launcher
// ---------------------------------------------------------------------------
extern "C" void kernel_launch(void* const* d_in, const int* in_sizes, int n_in,
                              void* d_out, int out_size)
{
    (void)in_sizes; (void)n_in; (void)out_size;
    const float* x     = (const float*)d_in[0];
    const int*   pidx  = (const int*)  d_in[1];
    const float* Wq    = (const float*)d_in[2];
    const float* bq    = (const float*)d_in[3];
    const float* Wk    = (const float*)d_in[4];
    const float* bk    = (const float*)d_in[5];
    const float* Wv    = (const float*)d_in[6];
    const float* bv    = (const float*)d_in[7];
    const float* seeds = (const float*)d_in[8];
    const float* alog  = (const float*)d_in[9];
    const float* beta  = (const float*)d_in[10];
    float* out = (float*)d_out;

    const int g1b = 2 * 2 * GSTG * 4;       // 1-term: Ah,Bh double-buffered
    const int g3b = 2 * 4 * GSTG * 4;       // 3-term: Ah,Al,Bh,Bl

    // idempotent host-state calls; capture-legal
    cudaFuncSetAttribute((const void*)qkv_gemm_tc<1>,
                         cudaFuncAttributeMaxDynamicSharedMemorySize, g1b);
    cudaFuncSetAttribute((const void*)qkv_gemm_tc<3>,
                         cudaFuncAttributeMaxDynamicSharedMemorySize, g3b);
    cudaFuncSetAttribute((const void*)fine_attn_pool,
                         cudaFuncAttributeMaxDynamicSharedMemorySize, FINE_SMEM_BYTES);
    cudaFuncSetAttribute((const void*)global_attn,
                         cudaFuncAttributeMaxDynamicSharedMemorySize, GA_SMEM_BYTES);

    split_xt<<<NN / 128, 256>>>(x);
    dim3 gw(128 * HD / 256, 3);
    split_w<<<gw, 256>>>(Wq, Wk, Wv);

    dim3 gqk(HD / 128, NN / 128, 2);           // Q, K: single-term
    qkv_gemm_tc<1><<<gqk, 256, g1b>>>(bq, bk, bv, 0);
    dim3 gv(HD / 128, NN / 128, 1);            // V: 3-term split
    qkv_gemm_tc<3><<<gv, 256, g3b>>>(bq, bk, bv, 2);

    dim3 g2(KPP, HH);                          // fine + pooling: 128 x 4
    fine_attn_pool<<<g2, 256, FINE_SMEM_BYTES>>>(pidx, seeds);

    dim3 g4(NN / 128, HH);                     // global: 256 x 4
    global_attn<<<g4, 256, GA_SMEM_BYTES>>>();

    combine<<<(NN * DD / 4) / 256, 256>>>(alog, beta, out);
}

// round 10
// speedup vs baseline: 13.8249x; 1.0146x over previous
#include <cuda_runtime.h>
#include <cuda_bf16.h>
#include <math.h>
#include <stdint.h>

// ---------------------------------------------------------------------------
// Problem constants
// ---------------------------------------------------------------------------
#define NN   32768
#define IN_C 256
#define DD   128
#define HH   4
#define HD   512
#define MM   4
#define KPP  128
#define SSZ  256
#define RR   (KPP*MM)
#define INV_SCALE 0.088388347648318447f   // 1/sqrt(128)

// ---------------------------------------------------------------------------
// Scratch (static device globals; no allocation allowed)
// ---------------------------------------------------------------------------
__device__ float    g_outL[(size_t)NN*HD];
__device__ float    g_outG[(size_t)NN*HD];
__device__ float    g_xself[(size_t)NN*DD];      // exact fp32 x_self
__device__ uint32_t g_Qb[(size_t)NN*256];        // packed bf16x2, pre-scaled
__device__ uint32_t g_Kb[(size_t)NN*256];
__device__ uint32_t g_Vb[(size_t)NN*256];
__device__ uint32_t g_repKb[(size_t)RR*256];     // [rep][h*64+dp]
__device__ uint32_t g_repVb2[(size_t)(RR/2)*512];// [rpair][h*128+d] cross-packed
// GEMM operands
__device__ uint32_t g_xh_t[(size_t)128*NN];      // [kp][m] hi (transposed)
__device__ uint32_t g_xl_t[(size_t)128*NN];      // [kp][m] lo
__device__ uint32_t g_Wh[3][(IN_C/2)*HD];        // [kp][n] hi
__device__ uint32_t g_Wah[128*128];              // Wv head-avg hi  [kp][d]
__device__ uint32_t g_Wal[128*128];              // Wv head-avg lo

// ---------------------------------------------------------------------------
// helpers
// ---------------------------------------------------------------------------
__device__ __forceinline__ float bfr(float v) {
    return __bfloat162float(__float2bfloat16(v));
}
__device__ __forceinline__ uint32_t bf2(float lo, float hi) {
    uint32_t r;
    asm("cvt.rn.bf16x2.f32 %0, %1, %2;" : "=r"(r) : "f"(hi), "f"(lo));
    return r;
}
__device__ __forceinline__ float bflo(uint32_t u) { return __uint_as_float(u << 16); }
__device__ __forceinline__ float bfhi(uint32_t u) { return __uint_as_float(u & 0xffff0000u); }
__device__ __forceinline__ uint32_t prmt(uint32_t a, uint32_t b, uint32_t sel) {
    uint32_t r;
    asm("prmt.b32 %0, %1, %2, %3;" : "=r"(r) : "r"(a), "r"(b), "r"(sel));
    return r;
}
__device__ __forceinline__ void mma_bf16(float4& d, const uint32_t a[4],
                                         uint32_t b0, uint32_t b1) {
    asm volatile(
        "mma.sync.aligned.m16n8k16.row.col.f32.bf16.bf16.f32 "
        "{%0,%1,%2,%3}, {%4,%5,%6,%7}, {%8,%9}, {%0,%1,%2,%3};"
        : "+f"(d.x), "+f"(d.y), "+f"(d.z), "+f"(d.w)
        : "r"(a[0]), "r"(a[1]), "r"(a[2]), "r"(a[3]), "r"(b0), "r"(b1));
}
#define CP_ASYNC16(dst, src) \
    asm volatile("cp.async.cg.shared.global [%0], [%1], 16;" :: "r"(dst), "l"(src))
#define CP_COMMIT() asm volatile("cp.async.commit_group;")
#define CP_WAIT(n)  asm volatile("cp.async.wait_group %0;" :: "n"(n))

__device__ __forceinline__ uint32_t smem_u32addr(const void* p) {
    uint32_t a;
    asm("{ .reg .u64 t; cvta.to.shared.u64 t, %1; cvt.u32.u64 %0, t; }"
        : "=r"(a) : "l"(p));
    return a;
}

__device__ __forceinline__ float warp_max2(float s) {
    s = fmaxf(s, __shfl_xor_sync(0xffffffffu, s, 1));
    s = fmaxf(s, __shfl_xor_sync(0xffffffffu, s, 2));
    return s;
}
__device__ __forceinline__ float warp_sum2(float s) {
    s += __shfl_xor_sync(0xffffffffu, s, 1);
    s += __shfl_xor_sync(0xffffffffu, s, 2);
    return s;
}
__device__ __forceinline__ float warp_max32(float s) {
#pragma unroll
    for (int o = 16; o > 0; o >>= 1) s = fmaxf(s, __shfl_xor_sync(0xffffffffu, s, o));
    return s;
}
__device__ __forceinline__ float warp_sum32(float s) {
#pragma unroll
    for (int o = 16; o > 0; o >>= 1) s += __shfl_xor_sync(0xffffffffu, s, o);
    return s;
}

// ---------------------------------------------------------------------------
// split_xt: x -> transposed hi/lo bf16x2 splits  g_x{h,l}_t [kp][m]
// ---------------------------------------------------------------------------
__global__ __launch_bounds__(256) void split_xt(const float* __restrict__ x)
{
    __shared__ uint32_t Th[32][132];
    __shared__ uint32_t Tl[32][132];
    const int m0 = blockIdx.x * 128;
    const int tid = threadIdx.x;
#pragma unroll
    for (int c = 0; c < 4; c++) {
        const int kpb = c * 32;
        {
            const int m = tid >> 1, half = tid & 1;
            const float* src = x + (size_t)(m0 + m) * IN_C + (kpb + half * 16) * 2;
#pragma unroll
            for (int j = 0; j < 16; j++) {
                float2 v = *(const float2*)(src + 2 * j);
                const float h0 = bfr(v.x), h1 = bfr(v.y);
                Th[half * 16 + j][m] = bf2(v.x, v.y);
                Tl[half * 16 + j][m] = bf2(v.x - h0, v.y - h1);
            }
        }
        __syncthreads();
        {
            const int kpr = tid >> 3, mo = (tid & 7) * 16;
            uint32_t* dh = g_xh_t + (size_t)(kpb + kpr) * NN + m0 + mo;
            uint32_t* dl = g_xl_t + (size_t)(kpb + kpr) * NN + m0 + mo;
#pragma unroll
            for (int j = 0; j < 4; j++) {
                *(uint4*)(dh + 4 * j) = *(uint4*)&Th[kpr][mo + 4 * j];
                *(uint4*)(dl + 4 * j) = *(uint4*)&Tl[kpr][mo + 4 * j];
            }
        }
        __syncthreads();
    }
}

// ---------------------------------------------------------------------------
// split_w: W -> hi bf16x2  g_Wh [kp][n]   (single-term QKV)
// ---------------------------------------------------------------------------
__global__ __launch_bounds__(256) void split_w(
    const float* __restrict__ Wq, const float* __restrict__ Wk,
    const float* __restrict__ Wv)
{
    const float* W = (blockIdx.y == 0) ? Wq : (blockIdx.y == 1) ? Wk : Wv;
    const int idx = blockIdx.x * 256 + threadIdx.x;
    const int kp = idx >> 9, n = idx & 511;
    const float v0 = W[(size_t)(2 * kp) * HD + n];
    const float v1 = W[(size_t)(2 * kp + 1) * HD + n];
    g_Wh[blockIdx.y][idx] = bf2(v0, v1);
}

// ---------------------------------------------------------------------------
// wavg_split: Wavg[k][d] = mean_h Wv[k][h*128+d], hi/lo split along k-pairs
// ---------------------------------------------------------------------------
__global__ __launch_bounds__(256) void wavg_split(const float* __restrict__ Wv)
{
    const int idx = blockIdx.x * 256 + threadIdx.x;   // 128 kp x 128 d
    const int kp = idx >> 7, d = idx & 127;
    const float* r0 = Wv + (size_t)(2 * kp) * HD;
    const float* r1 = Wv + (size_t)(2 * kp + 1) * HD;
    const float v0 = 0.25f * (r0[d] + r0[128 + d] + r0[256 + d] + r0[384 + d]);
    const float v1 = 0.25f * (r1[d] + r1[128 + d] + r1[256 + d] + r1[384 + d]);
    const float h0 = bfr(v0), h1 = bfr(v1);
    g_Wah[idx] = bf2(v0, v1);
    g_Wal[idx] = bf2(v0 - h0, v1 - h1);
}

// ---------------------------------------------------------------------------
// Kernel 1: QKV GEMM, single-term bf16, cp.async double-buffered.
// ---------------------------------------------------------------------------
#define GSTG 2176                       // 16*136 u32 per array

__global__ __launch_bounds__(256) void qkv_gemm_tc(
    const float* __restrict__ bq, const float* __restrict__ bk,
    const float* __restrict__ bv)
{
    const int z = blockIdx.z;
    const uint32_t* WH = g_Wh[z];
    const float* bias = (z == 0) ? bq : (z == 1) ? bk : bv;
    uint32_t* Cb = (z == 0) ? g_Qb : (z == 1) ? g_Kb : g_Vb;

    extern __shared__ uint32_t smg[];

    const int tid  = threadIdx.x;
    const int warp = tid >> 5, lane = tid & 31;
    const int lr = lane >> 2, lc = lane & 3;
    const int wm = warp & 3, wn = warp >> 2;
    const int row0 = blockIdx.y * 128;
    const int col0 = blockIdx.x * 128;

    auto issue = [&](int it, int b) {
        const int kp0 = it * 16;
        const uint32_t base = smem_u32addr(smg + b * 2 * GSTG);
#pragma unroll
        for (int j = 0; j < 2; j++) {
            const int slot = tid * 2 + j;
            const int kpr = slot >> 5, f = (slot & 31) * 4;
            const uint32_t doff = (kpr * 136 + f) * 4;
            CP_ASYNC16(base + doff, g_xh_t + (size_t)(kp0 + kpr) * NN + row0 + f);
            CP_ASYNC16(base + GSTG * 4 + doff, WH + (size_t)(kp0 + kpr) * HD + col0 + f);
        }
    };

    float4 acc[2][8];
#pragma unroll
    for (int mi = 0; mi < 2; mi++)
#pragma unroll
        for (int ni = 0; ni < 8; ni++)
            acc[mi][ni] = make_float4(0.f, 0.f, 0.f, 0.f);

    issue(0, 0); CP_COMMIT();

    for (int it = 0; it < 8; it++) {
        if (it < 7) { issue(it + 1, (it + 1) & 1); CP_COMMIT(); CP_WAIT(1); }
        else        { CP_WAIT(0); }
        __syncthreads();

        const uint32_t* Ah = smg + (it & 1) * 2 * GSTG;
        const uint32_t* Bh = Ah + GSTG;

#pragma unroll
        for (int kf = 0; kf < 2; kf++) {
            const int r0 = (kf * 8 + lc) * 136;
            const int r1 = (kf * 8 + lc + 4) * 136;
            uint32_t ah[2][4];
#pragma unroll
            for (int mi = 0; mi < 2; mi++) {
                const int m0 = wm * 32 + mi * 16 + lr;
                ah[mi][0] = Ah[r0 + m0]; ah[mi][1] = Ah[r0 + m0 + 8];
                ah[mi][2] = Ah[r1 + m0]; ah[mi][3] = Ah[r1 + m0 + 8];
            }
#pragma unroll
            for (int ni = 0; ni < 8; ni++) {
                const int n0 = wn * 64 + ni * 8 + lr;
                const uint32_t bh0 = Bh[r0 + n0], bh1 = Bh[r1 + n0];
#pragma unroll
                for (int mi = 0; mi < 2; mi++)
                    mma_bf16(acc[mi][ni], ah[mi], bh0, bh1);
            }
        }
        __syncthreads();
    }

#pragma unroll
    for (int mi = 0; mi < 2; mi++) {
        const int r = row0 + wm * 32 + mi * 16 + lr;
#pragma unroll
        for (int ni = 0; ni < 8; ni++) {
            const int c = col0 + wn * 64 + ni * 8 + 2 * lc;
            const float2 b2 = *(const float2*)&bias[c];
            float x0 = acc[mi][ni].x + b2.x, y0 = acc[mi][ni].y + b2.y;
            float x1 = acc[mi][ni].z + b2.x, y1 = acc[mi][ni].w + b2.y;
            if (z == 0) { x0 *= INV_SCALE; y0 *= INV_SCALE;
                          x1 *= INV_SCALE; y1 *= INV_SCALE; }
            const int cp = c >> 1;
            Cb[(size_t)r * 256 + cp]       = bf2(x0, y0);
            Cb[(size_t)(r + 8) * 256 + cp] = bf2(x1, y1);
        }
    }
}

// ---------------------------------------------------------------------------
// Kernel 1b: exact x_self GEMM (M=NN, K=256, N=128), 3-term bf16 split.
// ---------------------------------------------------------------------------
__global__ __launch_bounds__(256) void xself_gemm(const float* __restrict__ bv)
{
    extern __shared__ uint32_t smx[];

    const int tid  = threadIdx.x;
    const int warp = tid >> 5, lane = tid & 31;
    const int lr = lane >> 2, lc = lane & 3;
    const int wm = warp & 3, wn = warp >> 2;
    const int row0 = blockIdx.x * 128;

    auto issue = [&](int it, int b) {
        const int kp0 = it * 16;
        const uint32_t base = smem_u32addr(smx + b * 4 * GSTG);
#pragma unroll
        for (int j = 0; j < 2; j++) {
            const int slot = tid * 2 + j;
            const int kpr = slot >> 5, f = (slot & 31) * 4;
            const uint32_t doff = (kpr * 136 + f) * 4;
            const size_t asrc = (size_t)(kp0 + kpr) * NN + row0 + f;
            const size_t bsrc = (size_t)(kp0 + kpr) * 128 + f;
            CP_ASYNC16(base + 0 * GSTG * 4 + doff, g_xh_t + asrc);
            CP_ASYNC16(base + 1 * GSTG * 4 + doff, g_xl_t + asrc);
            CP_ASYNC16(base + 2 * GSTG * 4 + doff, g_Wah + bsrc);
            CP_ASYNC16(base + 3 * GSTG * 4 + doff, g_Wal + bsrc);
        }
    };

    float4 acc[2][8];
#pragma unroll
    for (int mi = 0; mi < 2; mi++)
#pragma unroll
        for (int ni = 0; ni < 8; ni++)
            acc[mi][ni] = make_float4(0.f, 0.f, 0.f, 0.f);

    issue(0, 0); CP_COMMIT();

    for (int it = 0; it < 8; it++) {
        if (it < 7) { issue(it + 1, (it + 1) & 1); CP_COMMIT(); CP_WAIT(1); }
        else        { CP_WAIT(0); }
        __syncthreads();

        const uint32_t* buf = smx + (it & 1) * 4 * GSTG;
        const uint32_t* Ah = buf;
        const uint32_t* Al = buf + GSTG;
        const uint32_t* Bh = buf + 2 * GSTG;
        const uint32_t* Bl = buf + 3 * GSTG;

#pragma unroll
        for (int kf = 0; kf < 2; kf++) {
            const int r0 = (kf * 8 + lc) * 136;
            const int r1 = (kf * 8 + lc + 4) * 136;
            uint32_t ah[2][4], al[2][4];
#pragma unroll
            for (int mi = 0; mi < 2; mi++) {
                const int m0 = wm * 32 + mi * 16 + lr;
                ah[mi][0] = Ah[r0 + m0]; ah[mi][1] = Ah[r0 + m0 + 8];
                ah[mi][2] = Ah[r1 + m0]; ah[mi][3] = Ah[r1 + m0 + 8];
                al[mi][0] = Al[r0 + m0]; al[mi][1] = Al[r0 + m0 + 8];
                al[mi][2] = Al[r1 + m0]; al[mi][3] = Al[r1 + m0 + 8];
            }
#pragma unroll
            for (int ni = 0; ni < 8; ni++) {
                const int n0 = wn * 64 + ni * 8 + lr;
                const uint32_t bh0 = Bh[r0 + n0], bh1 = Bh[r1 + n0];
                const uint32_t bl0 = Bl[r0 + n0], bl1 = Bl[r1 + n0];
#pragma unroll
                for (int mi = 0; mi < 2; mi++) {
                    mma_bf16(acc[mi][ni], ah[mi], bh0, bh1);
                    mma_bf16(acc[mi][ni], ah[mi], bl0, bl1);
                    mma_bf16(acc[mi][ni], al[mi], bh0, bh1);
                }
            }
        }
        __syncthreads();
    }

#pragma unroll
    for (int mi = 0; mi < 2; mi++) {
        const int r = row0 + wm * 32 + mi * 16 + lr;
#pragma unroll
        for (int ni = 0; ni < 8; ni++) {
            const int c = wn * 64 + ni * 8 + 2 * lc;
            const float bx = 0.25f * (bv[c] + bv[128 + c] + bv[256 + c] + bv[384 + c]);
            const float by = 0.25f * (bv[c+1] + bv[129 + c] + bv[257 + c] + bv[385 + c]);
            *(float2*)&g_xself[(size_t)r * DD + c] =
                make_float2(acc[mi][ni].x + bx, acc[mi][ni].y + by);
            *(float2*)&g_xself[(size_t)(r + 8) * DD + c] =
                make_float2(acc[mi][ni].z + bx, acc[mi][ni].w + by);
        }
    }
}

// ---------------------------------------------------------------------------
// Kernel 2: fine attention (one 128-q set per block, z-split) + coarse pooling
// (2 seeds per block). K/V resident; register-P PV.
// ---------------------------------------------------------------------------
#define FINE_SMEM_BYTES ((256*68 + 128*136 + 1040) * 4)

__global__ __launch_bounds__(256) void fine_attn_pool(
    const int* __restrict__ pidx, const float* __restrict__ seeds)
{
    extern __shared__ uint32_t sf[];
    uint32_t* Kr = sf;                        // [256][68]
    uint32_t* Vr = sf + 256 * 68;             // [128][136]
    float*    ps = (float*)(sf + 256 * 68 + 128 * 136);  // [2][260]
    float*    qsm = ps + 2 * 260;             // [2][128]
    float*    vsm = qsm + 2 * 128;            // [2][128]
    float*    lsm = vsm + 2 * 128;            // [2]

    const int tid = threadIdx.x, warp = tid >> 5, lane = tid & 31;
    const int lr = lane >> 2, lc = lane & 3;
    const int kpart = blockIdx.x, h = blockIdx.y, zs = blockIdx.z;
    const int* pi = pidx + kpart * SSZ;

    // ---- stage K ----
    {
        const int node = pi[tid];
        const uint32_t* src = g_Kb + (size_t)node * 256 + h * 64;
        uint32_t* dst = Kr + tid * 68;
#pragma unroll
        for (int j = 0; j < 16; j++)
            *(uint4*)(dst + 4 * j) = *(const uint4*)(src + 4 * j);
    }
    // ---- stage V (PRMT cross-pack) ----
    {
        const int kpi = tid >> 1, dh = (tid & 1) * 32;
        const int ka = pi[2 * kpi], kb = pi[2 * kpi + 1];
        const uint32_t* sa = g_Vb + (size_t)ka * 256 + h * 64 + dh;
        const uint32_t* sb = g_Vb + (size_t)kb * 256 + h * 64 + dh;
        uint32_t* dst = Vr + kpi * 136 + dh * 2;
#pragma unroll
        for (int j = 0; j < 8; j++) {
            uint4 a = *(const uint4*)(sa + 4 * j);
            uint4 b = *(const uint4*)(sb + 4 * j);
            uint4 o0, o1;
            o0.x = prmt(a.x, b.x, 0x5410); o0.y = prmt(a.x, b.x, 0x7632);
            o0.z = prmt(a.y, b.y, 0x5410); o0.w = prmt(a.y, b.y, 0x7632);
            o1.x = prmt(a.z, b.z, 0x5410); o1.y = prmt(a.z, b.z, 0x7632);
            o1.z = prmt(a.w, b.w, 0x5410); o1.w = prmt(a.w, b.w, 0x7632);
            *(uint4*)(dst + 8 * j)     = o0;
            *(uint4*)(dst + 8 * j + 4) = o1;
        }
    }
    // seeds -> smem (2 seeds for this z)
    {
        const int ml = tid >> 7, d = tid & 127;
        qsm[ml * 128 + d] = seeds[(size_t)(zs * 2 + ml) * HD + h * DD + d] * INV_SCALE;
    }
    __syncthreads();

    const int wq = warp * 16;
    const int qb = zs * 128;
    const int n0g = pi[qb + wq + lr];
    const int n1g = pi[qb + wq + lr + 8];

    uint32_t qa[8][4];
    {
        const uint32_t* q0p = g_Qb + (size_t)n0g * 256 + h * 64;
        const uint32_t* q1p = g_Qb + (size_t)n1g * 256 + h * 64;
#pragma unroll
        for (int kf = 0; kf < 8; kf++) {
            qa[kf][0] = q0p[kf * 8 + lc];
            qa[kf][1] = q1p[kf * 8 + lc];
            qa[kf][2] = q0p[kf * 8 + lc + 4];
            qa[kf][3] = q1p[kf * 8 + lc + 4];
        }
    }

    float4 acc[16];
#pragma unroll
    for (int ni = 0; ni < 16; ni++) acc[ni] = make_float4(0.f, 0.f, 0.f, 0.f);
    float m0 = -INFINITY, m1 = -INFINITY, l0 = 0.f, l1 = 0.f;

#pragma unroll 1
    for (int kt = 0; kt < 4; kt++) {
        float4 s[8];
#pragma unroll
        for (int ni = 0; ni < 8; ni++) s[ni] = make_float4(0.f, 0.f, 0.f, 0.f);
#pragma unroll
        for (int kf = 0; kf < 8; kf++) {
#pragma unroll
            for (int ni = 0; ni < 8; ni++) {
                const uint32_t* kr = Kr + (kt * 64 + ni * 8 + lr) * 68 + kf * 8;
                mma_bf16(s[ni], qa[kf], kr[lc], kr[lc + 4]);
            }
        }

        float tm0 = -INFINITY, tm1 = -INFINITY;
#pragma unroll
        for (int ni = 0; ni < 8; ni++) {
            tm0 = fmaxf(tm0, fmaxf(s[ni].x, s[ni].y));
            tm1 = fmaxf(tm1, fmaxf(s[ni].z, s[ni].w));
        }
        tm0 = warp_max2(tm0); tm1 = warp_max2(tm1);
        const float mn0 = fmaxf(m0, tm0), mn1 = fmaxf(m1, tm1);
        const float c0 = __expf(m0 - mn0), c1 = __expf(m1 - mn1);
        m0 = mn0; m1 = mn1;

        float rs0 = 0.f, rs1 = 0.f;
        uint32_t pa[4][4];
#pragma unroll
        for (int ni = 0; ni < 8; ni++) {
            const float p0 = __expf(s[ni].x - mn0);
            const float p1 = __expf(s[ni].y - mn0);
            const float p2 = __expf(s[ni].z - mn1);
            const float p3 = __expf(s[ni].w - mn1);
            rs0 += p0 + p1; rs1 += p2 + p3;
            pa[ni >> 1][(ni & 1) * 2 + 0] = bf2(p0, p1);
            pa[ni >> 1][(ni & 1) * 2 + 1] = bf2(p2, p3);
        }
        rs0 = warp_sum2(rs0); rs1 = warp_sum2(rs1);
        l0 = l0 * c0 + rs0; l1 = l1 * c1 + rs1;
#pragma unroll
        for (int ni = 0; ni < 16; ni++) {
            acc[ni].x *= c0; acc[ni].y *= c0;
            acc[ni].z *= c1; acc[ni].w *= c1;
        }

#pragma unroll
        for (int kf = 0; kf < 4; kf++) {
            const uint32_t* vr0 = Vr + (kt * 32 + kf * 8 + lc) * 136;
            const uint32_t* vr1 = Vr + (kt * 32 + kf * 8 + lc + 4) * 136;
#pragma unroll
            for (int ni = 0; ni < 16; ni++)
                mma_bf16(acc[ni], pa[kf], vr0[ni * 8 + lr], vr1[ni * 8 + lr]);
        }
    }

    {
        const float inv0 = 1.f / l0, inv1 = 1.f / l1;
        float* o0 = g_outL + (size_t)n0g * HD + h * DD;
        float* o1 = g_outL + (size_t)n1g * HD + h * DD;
#pragma unroll
        for (int ni = 0; ni < 16; ni++) {
            const int col = ni * 8 + 2 * lc;
            *(float2*)&o0[col] = make_float2(acc[ni].x * inv0, acc[ni].y * inv0);
            *(float2*)&o1[col] = make_float2(acc[ni].z * inv1, acc[ni].w * inv1);
        }
    }

    // ---- fused coarse pooling: seeds zs*2, zs*2+1 over resident K/V ----
    __syncthreads();
    if (warp < 2) {
        const int m = warp;
        float sc[8];
        float tmax = -INFINITY;
#pragma unroll
        for (int j = 0; j < 8; j++) {
            const int key = j * 32 + lane;
            float s = 0.f;
            const uint32_t* kr = Kr + key * 68;
            const float* qm = qsm + m * 128;
#pragma unroll
            for (int dp = 0; dp < 64; dp++) {
                const uint32_t u = kr[dp];
                s += qm[2 * dp] * bflo(u) + qm[2 * dp + 1] * bfhi(u);
            }
            sc[j] = s;
            tmax = fmaxf(tmax, s);
        }
        tmax = warp_max32(tmax);
        float lsum = 0.f;
#pragma unroll
        for (int j = 0; j < 8; j++) {
            const float p = __expf(sc[j] - tmax);
            ps[m * 260 + j * 32 + lane] = p;
            lsum += p;
        }
        lsum = warp_sum32(lsum);
        if (lane == 0) lsm[m] = lsum;
    }
    __syncthreads();

    if (tid < 128) {
        const int ml = tid >> 6, dp = tid & 63;
        float rk0 = 0.f, rk1 = 0.f, rv0 = 0.f, rv1 = 0.f;
        const float* pm = ps + ml * 260;
#pragma unroll 4
        for (int kp = 0; kp < 128; kp++) {
            const float p0 = pm[2 * kp], p1 = pm[2 * kp + 1];
            const uint32_t ka = Kr[(2 * kp) * 68 + dp];
            const uint32_t kb = Kr[(2 * kp + 1) * 68 + dp];
            rk0 += p0 * bflo(ka) + p1 * bflo(kb);
            rk1 += p0 * bfhi(ka) + p1 * bfhi(kb);
            const uint2 vv = *(const uint2*)&Vr[kp * 136 + 2 * dp];
            rv0 += p0 * bflo(vv.x) + p1 * bfhi(vv.x);
            rv1 += p0 * bflo(vv.y) + p1 * bfhi(vv.y);
        }
        const float inv = 1.f / lsm[ml];
        const int r = kpart * MM + zs * 2 + ml;
        g_repKb[(size_t)r * 256 + h * 64 + dp] = bf2(rk0 * inv, rk1 * inv);
        vsm[ml * 128 + 2 * dp]     = rv0 * inv;
        vsm[ml * 128 + 2 * dp + 1] = rv1 * inv;
    }
    __syncthreads();
    if (tid < 128) {
        const int rpair = kpart * 2 + zs;
        g_repVb2[(size_t)rpair * 512 + h * 128 + tid] =
            bf2(vsm[tid], vsm[128 + tid]);
    }
}

// ---------------------------------------------------------------------------
// Kernel 3: global cross-attention; cp.async double-buffered K/V tiles.
//   per buffer: Kr [64][68] (4352 u32) | Vr [32][136] (4352 u32)
// ---------------------------------------------------------------------------
#define GA_BUF 8704
#define GA_SMEM_BYTES (2 * GA_BUF * 4)

__global__ __launch_bounds__(256) void global_attn()
{
    extern __shared__ uint32_t sg[];

    const int tid = threadIdx.x, warp = tid >> 5, lane = tid & 31;
    const int lr = lane >> 2, lc = lane & 3;
    const int h = blockIdx.y;
    const int q0 = blockIdx.x * 128;
    const int wq = warp * 16;
    const int n0g = q0 + wq + lr, n1g = q0 + wq + lr + 8;
    const uint32_t sbase = smem_u32addr(sg);

    auto issueG = [&](int t, int b) {
        const uint32_t base = sbase + b * GA_BUF * 4;
#pragma unroll
        for (int j = 0; j < 8; j++) {
            const int cid = tid * 8 + j;
            if (cid < 1024) {             // K: 64 rows x 16 chunks
                const int row = cid >> 4, c4 = (cid & 15) * 4;
                CP_ASYNC16(base + (row * 68 + c4) * 4,
                           g_repKb + (size_t)(t + row) * 256 + h * 64 + c4);
            } else {                      // V: 32 rows x 32 chunks
                const int cid2 = cid - 1024;
                const int kpi = cid2 >> 5, c4 = (cid2 & 31) * 4;
                CP_ASYNC16(base + (64 * 68 + kpi * 136 + c4) * 4,
                           g_repVb2 + (size_t)((t >> 1) + kpi) * 512 + h * 128 + c4);
            }
        }
    };

    uint32_t qa[8][4];
    {
        const uint32_t* q0p = g_Qb + (size_t)n0g * 256 + h * 64;
        const uint32_t* q1p = g_Qb + (size_t)n1g * 256 + h * 64;
#pragma unroll
        for (int kf = 0; kf < 8; kf++) {
            qa[kf][0] = q0p[kf * 8 + lc];
            qa[kf][1] = q1p[kf * 8 + lc];
            qa[kf][2] = q0p[kf * 8 + lc + 4];
            qa[kf][3] = q1p[kf * 8 + lc + 4];
        }
    }

    float4 acc[16];
#pragma unroll
    for (int ni = 0; ni < 16; ni++) acc[ni] = make_float4(0.f, 0.f, 0.f, 0.f);
    float m0 = -INFINITY, m1 = -INFINITY, l0 = 0.f, l1 = 0.f;

    issueG(0, 0);  CP_COMMIT();
    issueG(64, 1); CP_COMMIT();

    for (int ti = 0; ti < 8; ti++) {
        if (ti < 7) CP_WAIT(1); else CP_WAIT(0);
        __syncthreads();

        const uint32_t* Kr = sg + (ti & 1) * GA_BUF;
        const uint32_t* Vr = Kr + 64 * 68;

        float4 s[8];
#pragma unroll
        for (int ni = 0; ni < 8; ni++) s[ni] = make_float4(0.f, 0.f, 0.f, 0.f);
#pragma unroll
        for (int kf = 0; kf < 8; kf++) {
#pragma unroll
            for (int ni = 0; ni < 8; ni++) {
                const uint32_t* kr = Kr + (ni * 8 + lr) * 68 + kf * 8;
                mma_bf16(s[ni], qa[kf], kr[lc], kr[lc + 4]);
            }
        }

        float tm0 = -INFINITY, tm1 = -INFINITY;
#pragma unroll
        for (int ni = 0; ni < 8; ni++) {
            tm0 = fmaxf(tm0, fmaxf(s[ni].x, s[ni].y));
            tm1 = fmaxf(tm1, fmaxf(s[ni].z, s[ni].w));
        }
        tm0 = warp_max2(tm0); tm1 = warp_max2(tm1);
        const float mn0 = fmaxf(m0, tm0), mn1 = fmaxf(m1, tm1);
        const float c0 = __expf(m0 - mn0), c1 = __expf(m1 - mn1);
        m0 = mn0; m1 = mn1;

        float rs0 = 0.f, rs1 = 0.f;
        uint32_t pa[4][4];
#pragma unroll
        for (int ni = 0; ni < 8; ni++) {
            const float p0 = __expf(s[ni].x - mn0);
            const float p1 = __expf(s[ni].y - mn0);
            const float p2 = __expf(s[ni].z - mn1);
            const float p3 = __expf(s[ni].w - mn1);
            rs0 += p0 + p1; rs1 += p2 + p3;
            pa[ni >> 1][(ni & 1) * 2 + 0] = bf2(p0, p1);
            pa[ni >> 1][(ni & 1) * 2 + 1] = bf2(p2, p3);
        }
        rs0 = warp_sum2(rs0); rs1 = warp_sum2(rs1);
        l0 = l0 * c0 + rs0; l1 = l1 * c1 + rs1;
#pragma unroll
        for (int ni = 0; ni < 16; ni++) {
            acc[ni].x *= c0; acc[ni].y *= c0;
            acc[ni].z *= c1; acc[ni].w *= c1;
        }

#pragma unroll
        for (int kf = 0; kf < 4; kf++) {
            const uint32_t* vr0 = Vr + (kf * 8 + lc) * 136;
            const uint32_t* vr1 = Vr + (kf * 8 + lc + 4) * 136;
#pragma unroll
            for (int ni = 0; ni < 16; ni++)
                mma_bf16(acc[ni], pa[kf], vr0[ni * 8 + lr], vr1[ni * 8 + lr]);
        }

        __syncthreads();
        if (ti + 2 < 8) { issueG((ti + 2) * 64, ti & 1); CP_COMMIT(); }
    }

    const float inv0 = 1.f / l0, inv1 = 1.f / l1;
    float* o0 = g_outG + (size_t)n0g * HD + h * DD;
    float* o1 = g_outG + (size_t)n1g * HD + h * DD;
#pragma unroll
    for (int ni = 0; ni < 16; ni++) {
        const int col = ni * 8 + 2 * lc;
        *(float2*)&o0[col] = make_float2(acc[ni].x * inv0, acc[ni].y * inv0);
        *(float2*)&o1[col] = make_float2(acc[ni].z * inv1, acc[ni].w * inv1);
    }
}

// ---------------------------------------------------------------------------
// Kernel 4: combine — out = a*mean_h(outL) + (1-a)*mean_h(outG) + beta*xself
// ---------------------------------------------------------------------------
__global__ __launch_bounds__(256) void combine(const float* __restrict__ alpha_logit,
                                               const float* __restrict__ beta_p,
                                               float* __restrict__ out)
{
    const int idx = blockIdx.x * blockDim.x + threadIdx.x;
    const int n  = idx / (DD / 4);
    const int d4 = (idx % (DD / 4)) * 4;

    const float alpha = 1.f / (1.f + __expf(-alpha_logit[0]));
    const float beta  = beta_p[0];
    const float ca = alpha * 0.25f;
    const float cg = (1.f - alpha) * 0.25f;

    float sl0 = 0, sl1 = 0, sl2 = 0, sl3 = 0;
    float sg0 = 0, sg1 = 0, sg2 = 0, sg3 = 0;
#pragma unroll
    for (int h = 0; h < HH; h++) {
        const size_t base = (size_t)n * HD + h * DD + d4;
        float4 a = *(const float4*)&g_outL[base];
        float4 b = *(const float4*)&g_outG[base];
        sl0 += a.x; sl1 += a.y; sl2 += a.z; sl3 += a.w;
        sg0 += b.x; sg1 += b.y; sg2 += b.z; sg3 += b.w;
    }
    const float4 xs = *(const float4*)&g_xself[(size_t)n * DD + d4];
    float4 o;
    o.x = ca * sl0 + cg * sg0 + beta * xs.x;
    o.y = ca * sl1 + cg * sg1 + beta * xs.y;
    o.z = ca * sl2 + cg * sg2 + beta * xs.z;
    o.w = ca * sl3 + cg * sg3 + beta * xs.w;
    *(float4*)&out[(size_t)n * DD + d4] = o;
}

// ---------------------------------------------------------------------------
// Launcher
// ---------------------------------------------------------------------------
extern "C" void kernel_launch(void* const* d_in, const int* in_sizes, int n_in,
                              void* d_out, int out_size)
{
    (void)in_sizes; (void)n_in; (void)out_size;
    const float* x     = (const float*)d_in[0];
    const int*   pidx  = (const int*)  d_in[1];
    const float* Wq    = (const float*)d_in[2];
    const float* bq    = (const float*)d_in[3];
    const float* Wk    = (const float*)d_in[4];
    const float* bk    = (const float*)d_in[5];
    const float* Wv    = (const float*)d_in[6];
    const float* bv    = (const float*)d_in[7];
    const float* seeds = (const float*)d_in[8];
    const float* alog  = (const float*)d_in[9];
    const float* beta  = (const float*)d_in[10];
    float* out = (float*)d_out;

    const int gqkb = 2 * 2 * GSTG * 4;     // single-term: Ah,Bh x2 buffers
    const int gxsb = 2 * 4 * GSTG * 4;     // 3-term: Ah,Al,Bh,Bl x2 buffers

    // idempotent host-state calls; capture-legal
    cudaFuncSetAttribute((const void*)qkv_gemm_tc,
                         cudaFuncAttributeMaxDynamicSharedMemorySize, gqkb);
    cudaFuncSetAttribute((const void*)xself_gemm,
                         cudaFuncAttributeMaxDynamicSharedMemorySize, gxsb);
    cudaFuncSetAttribute((const void*)fine_attn_pool,
                         cudaFuncAttributeMaxDynamicSharedMemorySize, FINE_SMEM_BYTES);
    cudaFuncSetAttribute((const void*)global_attn,
                         cudaFuncAttributeMaxDynamicSharedMemorySize, GA_SMEM_BYTES);

    split_xt<<<NN / 128, 256>>>(x);
    dim3 gw(128 * HD / 256, 3);
    split_w<<<gw, 256>>>(Wq, Wk, Wv);
    wavg_split<<<64, 256>>>(Wv);

    dim3 g1(HD / 128, NN / 128, 3);            // Q,K,V single-term
    qkv_gemm_tc<<<g1, 256, gqkb>>>(bq, bk, bv);

    xself_gemm<<<NN / 128, 256, gxsb>>>(bv);   // exact x_self

    dim3 g2(KPP, HH, 2);                       // fine + pooling: 128 x 4 x 2
    fine_attn_pool<<<g2, 256, FINE_SMEM_BYTES>>>(pidx, seeds);

    dim3 g4(NN / 128, HH);                     // global: 256 x 4
    global_attn<<<g4, 256, GA_SMEM_BYTES>>>();

    combine<<<(NN * DD / 4) / 256, 256>>>(alog, beta, out);
}

// round 11
// speedup vs baseline: 14.4338x; 1.0440x over previous
#include <cuda_runtime.h>
#include <cuda_bf16.h>
#include <math.h>
#include <stdint.h>

// ---------------------------------------------------------------------------
// Problem constants
// ---------------------------------------------------------------------------
#define NN   32768
#define IN_C 256
#define DD   128
#define HH   4
#define HD   512
#define MM   4
#define KPP  128
#define SSZ  256
#define RR   (KPP*MM)
#define INV_SCALE 0.088388347648318447f   // 1/sqrt(128)

// ---------------------------------------------------------------------------
// Scratch (static device globals; no allocation allowed)
// ---------------------------------------------------------------------------
__device__ float    g_xself[(size_t)NN*DD];      // exact fp32 x_self
__device__ uint32_t g_outLb[(size_t)NN*256];     // packed bf16x2 attention outs
__device__ uint32_t g_outGb[(size_t)NN*256];
__device__ uint32_t g_Qb[(size_t)NN*256];        // packed bf16x2, pre-scaled
__device__ uint32_t g_Kb[(size_t)NN*256];
__device__ uint32_t g_Vb[(size_t)NN*256];
__device__ uint32_t g_repKb[(size_t)RR*256];     // [rep][h*64+dp]
__device__ uint32_t g_repVb2[(size_t)(RR/2)*512];// [rpair][h*128+d] cross-packed
// GEMM operands
__device__ uint32_t g_xh_t[(size_t)128*NN];      // [kp][m] hi (transposed)
__device__ uint32_t g_xl_t[(size_t)128*NN];      // [kp][m] lo
__device__ uint32_t g_Wh[3][(IN_C/2)*HD];        // [kp][n] hi
__device__ uint32_t g_Wah[128*128];              // Wv head-avg hi  [kp][d]
__device__ uint32_t g_Wal[128*128];              // Wv head-avg lo

// ---------------------------------------------------------------------------
// helpers
// ---------------------------------------------------------------------------
__device__ __forceinline__ float bfr(float v) {
    return __bfloat162float(__float2bfloat16(v));
}
__device__ __forceinline__ uint32_t bf2(float lo, float hi) {
    uint32_t r;
    asm("cvt.rn.bf16x2.f32 %0, %1, %2;" : "=r"(r) : "f"(hi), "f"(lo));
    return r;
}
__device__ __forceinline__ float bflo(uint32_t u) { return __uint_as_float(u << 16); }
__device__ __forceinline__ float bfhi(uint32_t u) { return __uint_as_float(u & 0xffff0000u); }
__device__ __forceinline__ uint32_t prmt(uint32_t a, uint32_t b, uint32_t sel) {
    uint32_t r;
    asm("prmt.b32 %0, %1, %2, %3;" : "=r"(r) : "r"(a), "r"(b), "r"(sel));
    return r;
}
__device__ __forceinline__ void mma_bf16(float4& d, const uint32_t a[4],
                                         uint32_t b0, uint32_t b1) {
    asm volatile(
        "mma.sync.aligned.m16n8k16.row.col.f32.bf16.bf16.f32 "
        "{%0,%1,%2,%3}, {%4,%5,%6,%7}, {%8,%9}, {%0,%1,%2,%3};"
        : "+f"(d.x), "+f"(d.y), "+f"(d.z), "+f"(d.w)
        : "r"(a[0]), "r"(a[1]), "r"(a[2]), "r"(a[3]), "r"(b0), "r"(b1));
}
#define CP_ASYNC16(dst, src) \
    asm volatile("cp.async.cg.shared.global [%0], [%1], 16;" :: "r"(dst), "l"(src))
#define CP_COMMIT() asm volatile("cp.async.commit_group;")
#define CP_WAIT(n)  asm volatile("cp.async.wait_group %0;" :: "n"(n))

__device__ __forceinline__ uint32_t smem_u32addr(const void* p) {
    uint32_t a;
    asm("{ .reg .u64 t; cvta.to.shared.u64 t, %1; cvt.u32.u64 %0, t; }"
        : "=r"(a) : "l"(p));
    return a;
}

__device__ __forceinline__ float warp_max2(float s) {
    s = fmaxf(s, __shfl_xor_sync(0xffffffffu, s, 1));
    s = fmaxf(s, __shfl_xor_sync(0xffffffffu, s, 2));
    return s;
}
__device__ __forceinline__ float warp_sum2(float s) {
    s += __shfl_xor_sync(0xffffffffu, s, 1);
    s += __shfl_xor_sync(0xffffffffu, s, 2);
    return s;
}
__device__ __forceinline__ float warp_max32(float s) {
#pragma unroll
    for (int o = 16; o > 0; o >>= 1) s = fmaxf(s, __shfl_xor_sync(0xffffffffu, s, o));
    return s;
}
__device__ __forceinline__ float warp_sum32(float s) {
#pragma unroll
    for (int o = 16; o > 0; o >>= 1) s += __shfl_xor_sync(0xffffffffu, s, o);
    return s;
}

// ---------------------------------------------------------------------------
// split_xt: x -> transposed hi/lo bf16x2 splits  g_x{h,l}_t [kp][m]
// ---------------------------------------------------------------------------
__global__ __launch_bounds__(256) void split_xt(const float* __restrict__ x)
{
    __shared__ uint32_t Th[32][132];
    __shared__ uint32_t Tl[32][132];
    const int m0 = blockIdx.x * 128;
    const int tid = threadIdx.x;
#pragma unroll
    for (int c = 0; c < 4; c++) {
        const int kpb = c * 32;
        {
            const int m = tid >> 1, half = tid & 1;
            const float* src = x + (size_t)(m0 + m) * IN_C + (kpb + half * 16) * 2;
#pragma unroll
            for (int j = 0; j < 16; j++) {
                float2 v = *(const float2*)(src + 2 * j);
                const float h0 = bfr(v.x), h1 = bfr(v.y);
                Th[half * 16 + j][m] = bf2(v.x, v.y);
                Tl[half * 16 + j][m] = bf2(v.x - h0, v.y - h1);
            }
        }
        __syncthreads();
        {
            const int kpr = tid >> 3, mo = (tid & 7) * 16;
            uint32_t* dh = g_xh_t + (size_t)(kpb + kpr) * NN + m0 + mo;
            uint32_t* dl = g_xl_t + (size_t)(kpb + kpr) * NN + m0 + mo;
#pragma unroll
            for (int j = 0; j < 4; j++) {
                *(uint4*)(dh + 4 * j) = *(uint4*)&Th[kpr][mo + 4 * j];
                *(uint4*)(dl + 4 * j) = *(uint4*)&Tl[kpr][mo + 4 * j];
            }
        }
        __syncthreads();
    }
}

// ---------------------------------------------------------------------------
// split_w: W -> hi bf16x2  g_Wh [kp][n]
// ---------------------------------------------------------------------------
__global__ __launch_bounds__(256) void split_w(
    const float* __restrict__ Wq, const float* __restrict__ Wk,
    const float* __restrict__ Wv)
{
    const float* W = (blockIdx.y == 0) ? Wq : (blockIdx.y == 1) ? Wk : Wv;
    const int idx = blockIdx.x * 256 + threadIdx.x;
    const int kp = idx >> 9, n = idx & 511;
    const float v0 = W[(size_t)(2 * kp) * HD + n];
    const float v1 = W[(size_t)(2 * kp + 1) * HD + n];
    g_Wh[blockIdx.y][idx] = bf2(v0, v1);
}

// ---------------------------------------------------------------------------
// wavg_split: Wavg[k][d] = mean_h Wv[k][h*128+d], hi/lo split along k-pairs
// ---------------------------------------------------------------------------
__global__ __launch_bounds__(256) void wavg_split(const float* __restrict__ Wv)
{
    const int idx = blockIdx.x * 256 + threadIdx.x;   // 128 kp x 128 d
    const int kp = idx >> 7, d = idx & 127;
    const float* r0 = Wv + (size_t)(2 * kp) * HD;
    const float* r1 = Wv + (size_t)(2 * kp + 1) * HD;
    const float v0 = 0.25f * (r0[d] + r0[128 + d] + r0[256 + d] + r0[384 + d]);
    const float v1 = 0.25f * (r1[d] + r1[128 + d] + r1[256 + d] + r1[384 + d]);
    const float h0 = bfr(v0), h1 = bfr(v1);
    g_Wah[idx] = bf2(v0, v1);
    g_Wal[idx] = bf2(v0 - h0, v1 - h1);
}

// ---------------------------------------------------------------------------
// Kernel 1: unified A-resident QKV GEMM.
// Block = one 128-row slab x one 128-col slab; full-K A tile resident in smem;
// z in {Q,K,V} looped inside, B streamed via 4-deep cp.async ring.
// ---------------------------------------------------------------------------
#define GSTG 2176                        // 16*136 u32 per B stage
#define ASMEM (128 * 136)                // full-K A tile
#define GEMM_SMEM_BYTES ((ASMEM + 4 * GSTG) * 4)

__global__ __launch_bounds__(256) void qkv_gemm_tc(
    const float* __restrict__ bq, const float* __restrict__ bk,
    const float* __restrict__ bv)
{
    extern __shared__ uint32_t smg[];
    uint32_t* Asm = smg;                 // [128 kp][136 m]
    uint32_t* Bbuf = smg + ASMEM;        // 4 x [16 kp][136 n]

    const int tid  = threadIdx.x;
    const int warp = tid >> 5, lane = tid & 31;
    const int lr = lane >> 2, lc = lane & 3;
    const int wm = warp & 3, wn = warp >> 2;
    const int row0 = blockIdx.y * 128;
    const int col0 = blockIdx.x * 128;

    // ---- load full-K A tile (one cp.async group) ----
    {
        const uint32_t abase = smem_u32addr(Asm);
#pragma unroll
        for (int j = 0; j < 16; j++) {
            const int cid = j * 256 + tid;          // 4096 16B chunks
            const int kpr = cid >> 5, f = (cid & 31) * 4;
            CP_ASYNC16(abase + (kpr * 136 + f) * 4,
                       g_xh_t + (size_t)kpr * NN + row0 + f);
        }
        CP_COMMIT();
    }

    // ---- B stage issue: st in 0..23, z = st>>3, k-stage = st&7 ----
    auto issueB = [&](int st) {
        const int z = st >> 3, kp0 = (st & 7) * 16;
        const uint32_t base = smem_u32addr(Bbuf + (st & 3) * GSTG);
        const uint32_t* WH = g_Wh[z];
#pragma unroll
        for (int j = 0; j < 2; j++) {
            const int slot = tid * 2 + j;
            const int kpr = slot >> 5, f = (slot & 31) * 4;
            CP_ASYNC16(base + (kpr * 136 + f) * 4,
                       WH + (size_t)(kp0 + kpr) * HD + col0 + f);
        }
        CP_COMMIT();
    };

    issueB(0); issueB(1); issueB(2); issueB(3);

    float4 acc[2][8];
#pragma unroll
    for (int mi = 0; mi < 2; mi++)
#pragma unroll
        for (int ni = 0; ni < 8; ni++)
            acc[mi][ni] = make_float4(0.f, 0.f, 0.f, 0.f);

#pragma unroll 1
    for (int st = 0; st < 24; st++) {
        if (st < 21)      CP_WAIT(3);
        else if (st == 21) CP_WAIT(2);
        else if (st == 22) CP_WAIT(1);
        else               CP_WAIT(0);
        __syncthreads();

        const uint32_t* Bh = Bbuf + (st & 3) * GSTG;
        const int ks = (st & 7) * 16;

#pragma unroll
        for (int kf = 0; kf < 2; kf++) {
            const int ra0 = (ks + kf * 8 + lc) * 136;       // A rows (global kp)
            const int ra1 = (ks + kf * 8 + lc + 4) * 136;
            const int rb0 = (kf * 8 + lc) * 136;            // B rows (stage-local)
            const int rb1 = (kf * 8 + lc + 4) * 136;
            uint32_t ah[2][4];
#pragma unroll
            for (int mi = 0; mi < 2; mi++) {
                const int m0 = wm * 32 + mi * 16 + lr;
                ah[mi][0] = Asm[ra0 + m0]; ah[mi][1] = Asm[ra0 + m0 + 8];
                ah[mi][2] = Asm[ra1 + m0]; ah[mi][3] = Asm[ra1 + m0 + 8];
            }
#pragma unroll
            for (int ni = 0; ni < 8; ni++) {
                const int n0 = wn * 64 + ni * 8 + lr;
                const uint32_t bh0 = Bh[rb0 + n0], bh1 = Bh[rb1 + n0];
#pragma unroll
                for (int mi = 0; mi < 2; mi++)
                    mma_bf16(acc[mi][ni], ah[mi], bh0, bh1);
            }
        }

        // ---- epilogue at end of each matrix ----
        if ((st & 7) == 7) {
            const int z = st >> 3;
            const float* bias = (z == 0) ? bq : (z == 1) ? bk : bv;
            uint32_t* Cb = (z == 0) ? g_Qb : (z == 1) ? g_Kb : g_Vb;
#pragma unroll
            for (int mi = 0; mi < 2; mi++) {
                const int r = row0 + wm * 32 + mi * 16 + lr;
#pragma unroll
                for (int ni = 0; ni < 8; ni++) {
                    const int c = col0 + wn * 64 + ni * 8 + 2 * lc;
                    const float2 b2 = *(const float2*)&bias[c];
                    float x0 = acc[mi][ni].x + b2.x, y0 = acc[mi][ni].y + b2.y;
                    float x1 = acc[mi][ni].z + b2.x, y1 = acc[mi][ni].w + b2.y;
                    if (z == 0) { x0 *= INV_SCALE; y0 *= INV_SCALE;
                                  x1 *= INV_SCALE; y1 *= INV_SCALE; }
                    const int cp = c >> 1;
                    Cb[(size_t)r * 256 + cp]       = bf2(x0, y0);
                    Cb[(size_t)(r + 8) * 256 + cp] = bf2(x1, y1);
                    acc[mi][ni] = make_float4(0.f, 0.f, 0.f, 0.f);
                }
            }
        }

        __syncthreads();
        if (st + 4 < 24) issueB(st + 4);
    }
}

// ---------------------------------------------------------------------------
// Kernel 1b: exact x_self GEMM (M=NN, K=256, N=128), 3-term bf16 split.
// ---------------------------------------------------------------------------
__global__ __launch_bounds__(256) void xself_gemm(const float* __restrict__ bv)
{
    extern __shared__ uint32_t smx[];

    const int tid  = threadIdx.x;
    const int warp = tid >> 5, lane = tid & 31;
    const int lr = lane >> 2, lc = lane & 3;
    const int wm = warp & 3, wn = warp >> 2;
    const int row0 = blockIdx.x * 128;

    auto issue = [&](int it, int b) {
        const int kp0 = it * 16;
        const uint32_t base = smem_u32addr(smx + b * 4 * GSTG);
#pragma unroll
        for (int j = 0; j < 2; j++) {
            const int slot = tid * 2 + j;
            const int kpr = slot >> 5, f = (slot & 31) * 4;
            const uint32_t doff = (kpr * 136 + f) * 4;
            const size_t asrc = (size_t)(kp0 + kpr) * NN + row0 + f;
            const size_t bsrc = (size_t)(kp0 + kpr) * 128 + f;
            CP_ASYNC16(base + 0 * GSTG * 4 + doff, g_xh_t + asrc);
            CP_ASYNC16(base + 1 * GSTG * 4 + doff, g_xl_t + asrc);
            CP_ASYNC16(base + 2 * GSTG * 4 + doff, g_Wah + bsrc);
            CP_ASYNC16(base + 3 * GSTG * 4 + doff, g_Wal + bsrc);
        }
    };

    float4 acc[2][8];
#pragma unroll
    for (int mi = 0; mi < 2; mi++)
#pragma unroll
        for (int ni = 0; ni < 8; ni++)
            acc[mi][ni] = make_float4(0.f, 0.f, 0.f, 0.f);

    issue(0, 0); CP_COMMIT();

    for (int it = 0; it < 8; it++) {
        if (it < 7) { issue(it + 1, (it + 1) & 1); CP_COMMIT(); CP_WAIT(1); }
        else        { CP_WAIT(0); }
        __syncthreads();

        const uint32_t* buf = smx + (it & 1) * 4 * GSTG;
        const uint32_t* Ah = buf;
        const uint32_t* Al = buf + GSTG;
        const uint32_t* Bh = buf + 2 * GSTG;
        const uint32_t* Bl = buf + 3 * GSTG;

#pragma unroll
        for (int kf = 0; kf < 2; kf++) {
            const int r0 = (kf * 8 + lc) * 136;
            const int r1 = (kf * 8 + lc + 4) * 136;
            uint32_t ah[2][4], al[2][4];
#pragma unroll
            for (int mi = 0; mi < 2; mi++) {
                const int m0 = wm * 32 + mi * 16 + lr;
                ah[mi][0] = Ah[r0 + m0]; ah[mi][1] = Ah[r0 + m0 + 8];
                ah[mi][2] = Ah[r1 + m0]; ah[mi][3] = Ah[r1 + m0 + 8];
                al[mi][0] = Al[r0 + m0]; al[mi][1] = Al[r0 + m0 + 8];
                al[mi][2] = Al[r1 + m0]; al[mi][3] = Al[r1 + m0 + 8];
            }
#pragma unroll
            for (int ni = 0; ni < 8; ni++) {
                const int n0 = wn * 64 + ni * 8 + lr;
                const uint32_t bh0 = Bh[r0 + n0], bh1 = Bh[r1 + n0];
                const uint32_t bl0 = Bl[r0 + n0], bl1 = Bl[r1 + n0];
#pragma unroll
                for (int mi = 0; mi < 2; mi++) {
                    mma_bf16(acc[mi][ni], ah[mi], bh0, bh1);
                    mma_bf16(acc[mi][ni], ah[mi], bl0, bl1);
                    mma_bf16(acc[mi][ni], al[mi], bh0, bh1);
                }
            }
        }
        __syncthreads();
    }

#pragma unroll
    for (int mi = 0; mi < 2; mi++) {
        const int r = row0 + wm * 32 + mi * 16 + lr;
#pragma unroll
        for (int ni = 0; ni < 8; ni++) {
            const int c = wn * 64 + ni * 8 + 2 * lc;
            const float bx = 0.25f * (bv[c] + bv[128 + c] + bv[256 + c] + bv[384 + c]);
            const float by = 0.25f * (bv[c+1] + bv[129 + c] + bv[257 + c] + bv[385 + c]);
            *(float2*)&g_xself[(size_t)r * DD + c] =
                make_float2(acc[mi][ni].x + bx, acc[mi][ni].y + by);
            *(float2*)&g_xself[(size_t)(r + 8) * DD + c] =
                make_float2(acc[mi][ni].z + bx, acc[mi][ni].w + by);
        }
    }
}

// ---------------------------------------------------------------------------
// Kernel 2: fine attention (z-split) + coarse pooling. Packed bf16 outputs.
// ---------------------------------------------------------------------------
#define FINE_SMEM_BYTES ((256*68 + 128*136 + 1040) * 4)

__global__ __launch_bounds__(256) void fine_attn_pool(
    const int* __restrict__ pidx, const float* __restrict__ seeds)
{
    extern __shared__ uint32_t sf[];
    uint32_t* Kr = sf;                        // [256][68]
    uint32_t* Vr = sf + 256 * 68;             // [128][136]
    float*    ps = (float*)(sf + 256 * 68 + 128 * 136);  // [2][260]
    float*    qsm = ps + 2 * 260;             // [2][128]
    float*    vsm = qsm + 2 * 128;            // [2][128]
    float*    lsm = vsm + 2 * 128;            // [2]

    const int tid = threadIdx.x, warp = tid >> 5, lane = tid & 31;
    const int lr = lane >> 2, lc = lane & 3;
    const int kpart = blockIdx.x, h = blockIdx.y, zs = blockIdx.z;
    const int* pi = pidx + kpart * SSZ;

    // ---- stage K ----
    {
        const int node = pi[tid];
        const uint32_t* src = g_Kb + (size_t)node * 256 + h * 64;
        uint32_t* dst = Kr + tid * 68;
#pragma unroll
        for (int j = 0; j < 16; j++)
            *(uint4*)(dst + 4 * j) = *(const uint4*)(src + 4 * j);
    }
    // ---- stage V (PRMT cross-pack) ----
    {
        const int kpi = tid >> 1, dh = (tid & 1) * 32;
        const int ka = pi[2 * kpi], kb = pi[2 * kpi + 1];
        const uint32_t* sa = g_Vb + (size_t)ka * 256 + h * 64 + dh;
        const uint32_t* sb = g_Vb + (size_t)kb * 256 + h * 64 + dh;
        uint32_t* dst = Vr + kpi * 136 + dh * 2;
#pragma unroll
        for (int j = 0; j < 8; j++) {
            uint4 a = *(const uint4*)(sa + 4 * j);
            uint4 b = *(const uint4*)(sb + 4 * j);
            uint4 o0, o1;
            o0.x = prmt(a.x, b.x, 0x5410); o0.y = prmt(a.x, b.x, 0x7632);
            o0.z = prmt(a.y, b.y, 0x5410); o0.w = prmt(a.y, b.y, 0x7632);
            o1.x = prmt(a.z, b.z, 0x5410); o1.y = prmt(a.z, b.z, 0x7632);
            o1.z = prmt(a.w, b.w, 0x5410); o1.w = prmt(a.w, b.w, 0x7632);
            *(uint4*)(dst + 8 * j)     = o0;
            *(uint4*)(dst + 8 * j + 4) = o1;
        }
    }
    // seeds -> smem (2 seeds for this z)
    {
        const int ml = tid >> 7, d = tid & 127;
        qsm[ml * 128 + d] = seeds[(size_t)(zs * 2 + ml) * HD + h * DD + d] * INV_SCALE;
    }
    __syncthreads();

    const int wq = warp * 16;
    const int qb = zs * 128;
    const int n0g = pi[qb + wq + lr];
    const int n1g = pi[qb + wq + lr + 8];

    uint32_t qa[8][4];
    {
        const uint32_t* q0p = g_Qb + (size_t)n0g * 256 + h * 64;
        const uint32_t* q1p = g_Qb + (size_t)n1g * 256 + h * 64;
#pragma unroll
        for (int kf = 0; kf < 8; kf++) {
            qa[kf][0] = q0p[kf * 8 + lc];
            qa[kf][1] = q1p[kf * 8 + lc];
            qa[kf][2] = q0p[kf * 8 + lc + 4];
            qa[kf][3] = q1p[kf * 8 + lc + 4];
        }
    }

    float4 acc[16];
#pragma unroll
    for (int ni = 0; ni < 16; ni++) acc[ni] = make_float4(0.f, 0.f, 0.f, 0.f);
    float m0 = -INFINITY, m1 = -INFINITY, l0 = 0.f, l1 = 0.f;

#pragma unroll 1
    for (int kt = 0; kt < 4; kt++) {
        float4 s[8];
#pragma unroll
        for (int ni = 0; ni < 8; ni++) s[ni] = make_float4(0.f, 0.f, 0.f, 0.f);
#pragma unroll
        for (int kf = 0; kf < 8; kf++) {
#pragma unroll
            for (int ni = 0; ni < 8; ni++) {
                const uint32_t* kr = Kr + (kt * 64 + ni * 8 + lr) * 68 + kf * 8;
                mma_bf16(s[ni], qa[kf], kr[lc], kr[lc + 4]);
            }
        }

        float tm0 = -INFINITY, tm1 = -INFINITY;
#pragma unroll
        for (int ni = 0; ni < 8; ni++) {
            tm0 = fmaxf(tm0, fmaxf(s[ni].x, s[ni].y));
            tm1 = fmaxf(tm1, fmaxf(s[ni].z, s[ni].w));
        }
        tm0 = warp_max2(tm0); tm1 = warp_max2(tm1);
        const float mn0 = fmaxf(m0, tm0), mn1 = fmaxf(m1, tm1);
        const float c0 = __expf(m0 - mn0), c1 = __expf(m1 - mn1);
        m0 = mn0; m1 = mn1;

        float rs0 = 0.f, rs1 = 0.f;
        uint32_t pa[4][4];
#pragma unroll
        for (int ni = 0; ni < 8; ni++) {
            const float p0 = __expf(s[ni].x - mn0);
            const float p1 = __expf(s[ni].y - mn0);
            const float p2 = __expf(s[ni].z - mn1);
            const float p3 = __expf(s[ni].w - mn1);
            rs0 += p0 + p1; rs1 += p2 + p3;
            pa[ni >> 1][(ni & 1) * 2 + 0] = bf2(p0, p1);
            pa[ni >> 1][(ni & 1) * 2 + 1] = bf2(p2, p3);
        }
        rs0 = warp_sum2(rs0); rs1 = warp_sum2(rs1);
        l0 = l0 * c0 + rs0; l1 = l1 * c1 + rs1;
#pragma unroll
        for (int ni = 0; ni < 16; ni++) {
            acc[ni].x *= c0; acc[ni].y *= c0;
            acc[ni].z *= c1; acc[ni].w *= c1;
        }

#pragma unroll
        for (int kf = 0; kf < 4; kf++) {
            const uint32_t* vr0 = Vr + (kt * 32 + kf * 8 + lc) * 136;
            const uint32_t* vr1 = Vr + (kt * 32 + kf * 8 + lc + 4) * 136;
#pragma unroll
            for (int ni = 0; ni < 16; ni++)
                mma_bf16(acc[ni], pa[kf], vr0[ni * 8 + lr], vr1[ni * 8 + lr]);
        }
    }

    {
        const float inv0 = 1.f / l0, inv1 = 1.f / l1;
        uint32_t* o0 = g_outLb + (size_t)n0g * 256 + h * 64;
        uint32_t* o1 = g_outLb + (size_t)n1g * 256 + h * 64;
#pragma unroll
        for (int ni = 0; ni < 16; ni++) {
            o0[ni * 4 + lc] = bf2(acc[ni].x * inv0, acc[ni].y * inv0);
            o1[ni * 4 + lc] = bf2(acc[ni].z * inv1, acc[ni].w * inv1);
        }
    }

    // ---- fused coarse pooling: seeds zs*2, zs*2+1 over resident K/V ----
    __syncthreads();
    if (warp < 2) {
        const int m = warp;
        float sc[8];
        float tmax = -INFINITY;
#pragma unroll
        for (int j = 0; j < 8; j++) {
            const int key = j * 32 + lane;
            float s = 0.f;
            const uint32_t* kr = Kr + key * 68;
            const float* qm = qsm + m * 128;
#pragma unroll
            for (int dp = 0; dp < 64; dp++) {
                const uint32_t u = kr[dp];
                s += qm[2 * dp] * bflo(u) + qm[2 * dp + 1] * bfhi(u);
            }
            sc[j] = s;
            tmax = fmaxf(tmax, s);
        }
        tmax = warp_max32(tmax);
        float lsum = 0.f;
#pragma unroll
        for (int j = 0; j < 8; j++) {
            const float p = __expf(sc[j] - tmax);
            ps[m * 260 + j * 32 + lane] = p;
            lsum += p;
        }
        lsum = warp_sum32(lsum);
        if (lane == 0) lsm[m] = lsum;
    }
    __syncthreads();

    if (tid < 128) {
        const int ml = tid >> 6, dp = tid & 63;
        float rk0 = 0.f, rk1 = 0.f, rv0 = 0.f, rv1 = 0.f;
        const float* pm = ps + ml * 260;
#pragma unroll 4
        for (int kp = 0; kp < 128; kp++) {
            const float p0 = pm[2 * kp], p1 = pm[2 * kp + 1];
            const uint32_t ka = Kr[(2 * kp) * 68 + dp];
            const uint32_t kb = Kr[(2 * kp + 1) * 68 + dp];
            rk0 += p0 * bflo(ka) + p1 * bflo(kb);
            rk1 += p0 * bfhi(ka) + p1 * bfhi(kb);
            const uint2 vv = *(const uint2*)&Vr[kp * 136 + 2 * dp];
            rv0 += p0 * bflo(vv.x) + p1 * bfhi(vv.x);
            rv1 += p0 * bflo(vv.y) + p1 * bfhi(vv.y);
        }
        const float inv = 1.f / lsm[ml];
        const int r = kpart * MM + zs * 2 + ml;
        g_repKb[(size_t)r * 256 + h * 64 + dp] = bf2(rk0 * inv, rk1 * inv);
        vsm[ml * 128 + 2 * dp]     = rv0 * inv;
        vsm[ml * 128 + 2 * dp + 1] = rv1 * inv;
    }
    __syncthreads();
    if (tid < 128) {
        const int rpair = kpart * 2 + zs;
        g_repVb2[(size_t)rpair * 512 + h * 128 + tid] =
            bf2(vsm[tid], vsm[128 + tid]);
    }
}

// ---------------------------------------------------------------------------
// Kernel 3: global cross-attention; cp.async double-buffered K/V tiles.
// ---------------------------------------------------------------------------
#define GA_BUF 8704
#define GA_SMEM_BYTES (2 * GA_BUF * 4)

__global__ __launch_bounds__(256) void global_attn()
{
    extern __shared__ uint32_t sg[];

    const int tid = threadIdx.x, warp = tid >> 5, lane = tid & 31;
    const int lr = lane >> 2, lc = lane & 3;
    const int h = blockIdx.y;
    const int q0 = blockIdx.x * 128;
    const int wq = warp * 16;
    const int n0g = q0 + wq + lr, n1g = q0 + wq + lr + 8;
    const uint32_t sbase = smem_u32addr(sg);

    auto issueG = [&](int t, int b) {
        const uint32_t base = sbase + b * GA_BUF * 4;
#pragma unroll
        for (int j = 0; j < 8; j++) {
            const int cid = tid * 8 + j;
            if (cid < 1024) {             // K: 64 rows x 16 chunks
                const int row = cid >> 4, c4 = (cid & 15) * 4;
                CP_ASYNC16(base + (row * 68 + c4) * 4,
                           g_repKb + (size_t)(t + row) * 256 + h * 64 + c4);
            } else {                      // V: 32 rows x 32 chunks
                const int cid2 = cid - 1024;
                const int kpi = cid2 >> 5, c4 = (cid2 & 31) * 4;
                CP_ASYNC16(base + (64 * 68 + kpi * 136 + c4) * 4,
                           g_repVb2 + (size_t)((t >> 1) + kpi) * 512 + h * 128 + c4);
            }
        }
    };

    uint32_t qa[8][4];
    {
        const uint32_t* q0p = g_Qb + (size_t)n0g * 256 + h * 64;
        const uint32_t* q1p = g_Qb + (size_t)n1g * 256 + h * 64;
#pragma unroll
        for (int kf = 0; kf < 8; kf++) {
            qa[kf][0] = q0p[kf * 8 + lc];
            qa[kf][1] = q1p[kf * 8 + lc];
            qa[kf][2] = q0p[kf * 8 + lc + 4];
            qa[kf][3] = q1p[kf * 8 + lc + 4];
        }
    }

    float4 acc[16];
#pragma unroll
    for (int ni = 0; ni < 16; ni++) acc[ni] = make_float4(0.f, 0.f, 0.f, 0.f);
    float m0 = -INFINITY, m1 = -INFINITY, l0 = 0.f, l1 = 0.f;

    issueG(0, 0);  CP_COMMIT();
    issueG(64, 1); CP_COMMIT();

    for (int ti = 0; ti < 8; ti++) {
        if (ti < 7) CP_WAIT(1); else CP_WAIT(0);
        __syncthreads();

        const uint32_t* Kr = sg + (ti & 1) * GA_BUF;
        const uint32_t* Vr = Kr + 64 * 68;

        float4 s[8];
#pragma unroll
        for (int ni = 0; ni < 8; ni++) s[ni] = make_float4(0.f, 0.f, 0.f, 0.f);
#pragma unroll
        for (int kf = 0; kf < 8; kf++) {
#pragma unroll
            for (int ni = 0; ni < 8; ni++) {
                const uint32_t* kr = Kr + (ni * 8 + lr) * 68 + kf * 8;
                mma_bf16(s[ni], qa[kf], kr[lc], kr[lc + 4]);
            }
        }

        float tm0 = -INFINITY, tm1 = -INFINITY;
#pragma unroll
        for (int ni = 0; ni < 8; ni++) {
            tm0 = fmaxf(tm0, fmaxf(s[ni].x, s[ni].y));
            tm1 = fmaxf(tm1, fmaxf(s[ni].z, s[ni].w));
        }
        tm0 = warp_max2(tm0); tm1 = warp_max2(tm1);
        const float mn0 = fmaxf(m0, tm0), mn1 = fmaxf(m1, tm1);
        const float c0 = __expf(m0 - mn0), c1 = __expf(m1 - mn1);
        m0 = mn0; m1 = mn1;

        float rs0 = 0.f, rs1 = 0.f;
        uint32_t pa[4][4];
#pragma unroll
        for (int ni = 0; ni < 8; ni++) {
            const float p0 = __expf(s[ni].x - mn0);
            const float p1 = __expf(s[ni].y - mn0);
            const float p2 = __expf(s[ni].z - mn1);
            const float p3 = __expf(s[ni].w - mn1);
            rs0 += p0 + p1; rs1 += p2 + p3;
            pa[ni >> 1][(ni & 1) * 2 + 0] = bf2(p0, p1);
            pa[ni >> 1][(ni & 1) * 2 + 1] = bf2(p2, p3);
        }
        rs0 = warp_sum2(rs0); rs1 = warp_sum2(rs1);
        l0 = l0 * c0 + rs0; l1 = l1 * c1 + rs1;
#pragma unroll
        for (int ni = 0; ni < 16; ni++) {
            acc[ni].x *= c0; acc[ni].y *= c0;
            acc[ni].z *= c1; acc[ni].w *= c1;
        }

#pragma unroll
        for (int kf = 0; kf < 4; kf++) {
            const uint32_t* vr0 = Vr + (kf * 8 + lc) * 136;
            const uint32_t* vr1 = Vr + (kf * 8 + lc + 4) * 136;
#pragma unroll
            for (int ni = 0; ni < 16; ni++)
                mma_bf16(acc[ni], pa[kf], vr0[ni * 8 + lr], vr1[ni * 8 + lr]);
        }

        __syncthreads();
        if (ti + 2 < 8) { issueG((ti + 2) * 64, ti & 1); CP_COMMIT(); }
    }

    const float inv0 = 1.f / l0, inv1 = 1.f / l1;
    uint32_t* o0 = g_outGb + (size_t)n0g * 256 + h * 64;
    uint32_t* o1 = g_outGb + (size_t)n1g * 256 + h * 64;
#pragma unroll
    for (int ni = 0; ni < 16; ni++) {
        o0[ni * 4 + lc] = bf2(acc[ni].x * inv0, acc[ni].y * inv0);
        o1[ni * 4 + lc] = bf2(acc[ni].z * inv1, acc[ni].w * inv1);
    }
}

// ---------------------------------------------------------------------------
// Kernel 4: combine — unpack bf16 outL/outG, add exact x_self
// ---------------------------------------------------------------------------
__global__ __launch_bounds__(256) void combine(const float* __restrict__ alpha_logit,
                                               const float* __restrict__ beta_p,
                                               float* __restrict__ out)
{
    const int idx = blockIdx.x * 256 + threadIdx.x;   // NN * 16
    const int n = idx >> 4, g = idx & 15;

    const float alpha = 1.f / (1.f + __expf(-alpha_logit[0]));
    const float beta  = beta_p[0];
    const float ca = alpha * 0.25f;
    const float cg = (1.f - alpha) * 0.25f;

    float s[8];
#pragma unroll
    for (int j = 0; j < 8; j++) s[j] = 0.f;

#pragma unroll
    for (int h = 0; h < HH; h++) {
        const size_t base = (size_t)n * 256 + h * 64 + g * 4;
        const uint4 a = *(const uint4*)&g_outLb[base];
        const uint4 b = *(const uint4*)&g_outGb[base];
        s[0] += ca * bflo(a.x) + cg * bflo(b.x);
        s[1] += ca * bfhi(a.x) + cg * bfhi(b.x);
        s[2] += ca * bflo(a.y) + cg * bflo(b.y);
        s[3] += ca * bfhi(a.y) + cg * bfhi(b.y);
        s[4] += ca * bflo(a.z) + cg * bflo(b.z);
        s[5] += ca * bfhi(a.z) + cg * bfhi(b.z);
        s[6] += ca * bflo(a.w) + cg * bflo(b.w);
        s[7] += ca * bfhi(a.w) + cg * bfhi(b.w);
    }

    const size_t ob = (size_t)n * DD + g * 8;
    const float4 xs0 = *(const float4*)&g_xself[ob];
    const float4 xs1 = *(const float4*)&g_xself[ob + 4];
    float4 o0, o1;
    o0.x = s[0] + beta * xs0.x; o0.y = s[1] + beta * xs0.y;
    o0.z = s[2] + beta * xs0.z; o0.w = s[3] + beta * xs0.w;
    o1.x = s[4] + beta * xs1.x; o1.y = s[5] + beta * xs1.y;
    o1.z = s[6] + beta * xs1.z; o1.w = s[7] + beta * xs1.w;
    *(float4*)&out[ob]     = o0;
    *(float4*)&out[ob + 4] = o1;
}

// ---------------------------------------------------------------------------
// Launcher
// ---------------------------------------------------------------------------
extern "C" void kernel_launch(void* const* d_in, const int* in_sizes, int n_in,
                              void* d_out, int out_size)
{
    (void)in_sizes; (void)n_in; (void)out_size;
    const float* x     = (const float*)d_in[0];
    const int*   pidx  = (const int*)  d_in[1];
    const float* Wq    = (const float*)d_in[2];
    const float* bq    = (const float*)d_in[3];
    const float* Wk    = (const float*)d_in[4];
    const float* bk    = (const float*)d_in[5];
    const float* Wv    = (const float*)d_in[6];
    const float* bv    = (const float*)d_in[7];
    const float* seeds = (const float*)d_in[8];
    const float* alog  = (const float*)d_in[9];
    const float* beta  = (const float*)d_in[10];
    float* out = (float*)d_out;

    const int gxsb = 2 * 4 * GSTG * 4;     // xself: 3-term double-buffered

    // idempotent host-state calls; capture-legal
    cudaFuncSetAttribute((const void*)qkv_gemm_tc,
                         cudaFuncAttributeMaxDynamicSharedMemorySize, GEMM_SMEM_BYTES);
    cudaFuncSetAttribute((const void*)xself_gemm,
                         cudaFuncAttributeMaxDynamicSharedMemorySize, gxsb);
    cudaFuncSetAttribute((const void*)fine_attn_pool,
                         cudaFuncAttributeMaxDynamicSharedMemorySize, FINE_SMEM_BYTES);
    cudaFuncSetAttribute((const void*)global_attn,
                         cudaFuncAttributeMaxDynamicSharedMemorySize, GA_SMEM_BYTES);

    split_xt<<<NN / 128, 256>>>(x);
    dim3 gw(128 * HD / 256, 3);
    split_w<<<gw, 256>>>(Wq, Wk, Wv);
    wavg_split<<<64, 256>>>(Wv);

    dim3 g1(HD / 128, NN / 128);               // unified A-resident QKV
    qkv_gemm_tc<<<g1, 256, GEMM_SMEM_BYTES>>>(bq, bk, bv);

    xself_gemm<<<NN / 128, 256, gxsb>>>(bv);   // exact x_self

    dim3 g2(KPP, HH, 2);                       // fine + pooling
    fine_attn_pool<<<g2, 256, FINE_SMEM_BYTES>>>(pidx, seeds);

    dim3 g4(NN / 128, HH);                     // global
    global_attn<<<g4, 256, GA_SMEM_BYTES>>>();

    combine<<<(NN * 16) / 256, 256>>>(alog, beta, out);
}